// round 2
// baseline (speedup 1.0000x reference)
#include <cuda_runtime.h>
#include <math.h>

#define NB 2
#define SL 2048
#define DM 1024
#define NH 16
#define DHD 64
#define NLAYER 8
#define DFF 4096
#define NTOK (NB*SL)

// ---------------- scratch (static device globals; no allocs) ----------------
__device__ float g_h[(size_t)NTOK*DM];
__device__ float g_q[(size_t)NTOK*DM];
__device__ float g_k[(size_t)NTOK*DM];
__device__ float g_v[(size_t)NTOK*DM];
__device__ float g_o[(size_t)NTOK*DM];
__device__ float g_ff[(size_t)NTOK*DFF];

// ---------------- h = x + pe ----------------
__global__ void add_pe_kernel(const float* __restrict__ x, const float* __restrict__ pe) {
    int i = blockIdx.x * 256 + threadIdx.x;
    g_h[i] = x[i] + pe[i & (SL*DM - 1)];   // SL*DM = 2^21, pe repeats per batch
}

// ---------------- SGEMM: C = act(A[M,K] @ W[K,N] + bias) ----------------
// BM=BN=128, BK=8, 256 threads, 8x8 per thread.
template<int ACT, bool HASB>
__global__ __launch_bounds__(256, 2) void sgemm_kernel(
    const float* __restrict__ A, const float* __restrict__ W,
    const float* __restrict__ bias, float* __restrict__ C,
    int M, int N, int K)
{
    __shared__ float As[8][128];
    __shared__ float Bs[8][128];
    const int t  = threadIdx.x;
    const int tx = t & 15, ty = t >> 4;
    const int bx = blockIdx.x, by = blockIdx.y;

    const float* Ab = A + (size_t)(by * 128) * K;
    const float* Bb = W + bx * 128;

    const int arow = t >> 1, acol = (t & 1) * 4;
    const int brow = t >> 5, bcol = (t & 31) * 4;

    float acc[8][8];
#pragma unroll
    for (int i = 0; i < 8; i++)
#pragma unroll
        for (int j = 0; j < 8; j++) acc[i][j] = 0.f;

    for (int kt = 0; kt < K; kt += 8) {
        float4 a4 = *(const float4*)(Ab + (size_t)arow * K + kt + acol);
        float4 b4 = *(const float4*)(Bb + (size_t)(kt + brow) * N + bcol);
        As[acol + 0][arow] = a4.x;
        As[acol + 1][arow] = a4.y;
        As[acol + 2][arow] = a4.z;
        As[acol + 3][arow] = a4.w;
        *(float4*)(&Bs[brow][bcol]) = b4;
        __syncthreads();
#pragma unroll
        for (int k = 0; k < 8; k++) {
            float a[8], b[8];
            *(float4*)(a)     = *(const float4*)(&As[k][ty * 8]);
            *(float4*)(a + 4) = *(const float4*)(&As[k][ty * 8 + 4]);
            *(float4*)(b)     = *(const float4*)(&Bs[k][tx * 8]);
            *(float4*)(b + 4) = *(const float4*)(&Bs[k][tx * 8 + 4]);
#pragma unroll
            for (int i = 0; i < 8; i++)
#pragma unroll
                for (int j = 0; j < 8; j++)
                    acc[i][j] = fmaf(a[i], b[j], acc[i][j]);
        }
        __syncthreads();
    }

#pragma unroll
    for (int i = 0; i < 8; i++) {
        int row = by * 128 + ty * 8 + i;
        float* crow = C + (size_t)row * N + bx * 128 + tx * 8;
#pragma unroll
        for (int j = 0; j < 8; j++) {
            float vv = acc[i][j];
            if (HASB) vv += bias[bx * 128 + tx * 8 + j];
            if (ACT == 1) {
                // SELU (jax.nn.selu constants)
                vv = 1.0507009873554805f *
                     (vv > 0.f ? vv : 1.6732632423543772f * expm1f(vv));
            }
            acc[i][j] = vv;
        }
        *(float4*)(crow)     = *(float4*)(&acc[i][0]);
        *(float4*)(crow + 4) = *(float4*)(&acc[i][4]);
    }
}

// ---------------- flash attention (fp32, causal, online softmax) ----------------
// grid: (SL/64, NB*NH); block 256. One 64-query tile per block.
// Column mapping c = tx + 16*j keeps smem LDS conflict-free with pitch 68.
__global__ __launch_bounds__(256, 2) void flash_kernel(
    const float* __restrict__ q, const float* __restrict__ k,
    const float* __restrict__ v, float* __restrict__ o)
{
    extern __shared__ float sm[];
    float* Qs    = sm;                 // 64*68
    float* Ks    = Qs + 64 * 68;
    float* Vs    = Ks + 64 * 68;
    float* Ss    = Vs + 64 * 68;
    float* rowm  = Ss + 64 * 68;       // 64
    float* rowl  = rowm + 64;
    float* rowsc = rowl + 64;

    const int qt = gridDim.x - 1 - blockIdx.x;   // heavy tiles first
    const int bh = blockIdx.y;
    const int b  = bh >> 4, hd = bh & 15;
    const float* qb = q + (size_t)b * SL * DM + hd * DHD;
    const float* kb = k + (size_t)b * SL * DM + hd * DHD;
    const float* vb = v + (size_t)b * SL * DM + hd * DHD;
    float*       ob = o + (size_t)b * SL * DM + hd * DHD;

    const int t  = threadIdx.x;
    const int tx = t & 15, ty = t >> 4;

    // load Q tile, pre-scaled by 1/sqrt(DH) = 0.125
    for (int i = t; i < 64 * 16; i += 256) {
        int r = i >> 4, c = (i & 15) * 4;
        float4 v4 = *(const float4*)(qb + (size_t)(qt * 64 + r) * DM + c);
        v4.x *= 0.125f; v4.y *= 0.125f; v4.z *= 0.125f; v4.w *= 0.125f;
        *(float4*)(&Qs[r * 68 + c]) = v4;
    }
    if (t < 64) { rowm[t] = -1e30f; rowl[t] = 0.f; }

    float oacc[4][4];
#pragma unroll
    for (int i = 0; i < 4; i++)
#pragma unroll
        for (int j = 0; j < 4; j++) oacc[i][j] = 0.f;

    for (int kt = 0; kt <= qt; kt++) {
        __syncthreads();   // protect Ks/Vs/Ss reuse (also orders Q load / rowm init)
        for (int i = t; i < 64 * 16; i += 256) {
            int r = i >> 4, c = (i & 15) * 4;
            *(float4*)(&Ks[r * 68 + c]) = *(const float4*)(kb + (size_t)(kt * 64 + r) * DM + c);
            *(float4*)(&Vs[r * 68 + c]) = *(const float4*)(vb + (size_t)(kt * 64 + r) * DM + c);
        }
        __syncthreads();

        // S = Q @ K^T : thread rows ty*4+i, cols tx+16*j
        float s[4][4];
#pragma unroll
        for (int i = 0; i < 4; i++)
#pragma unroll
            for (int j = 0; j < 4; j++) s[i][j] = 0.f;

        for (int d = 0; d < 64; d += 4) {
            float4 qv[4], kv[4];
#pragma unroll
            for (int i = 0; i < 4; i++) qv[i] = *(const float4*)(&Qs[(ty * 4 + i) * 68 + d]);
#pragma unroll
            for (int j = 0; j < 4; j++) kv[j] = *(const float4*)(&Ks[(tx + 16 * j) * 68 + d]);
#pragma unroll
            for (int i = 0; i < 4; i++)
#pragma unroll
                for (int j = 0; j < 4; j++) {
                    s[i][j] = fmaf(qv[i].x, kv[j].x, s[i][j]);
                    s[i][j] = fmaf(qv[i].y, kv[j].y, s[i][j]);
                    s[i][j] = fmaf(qv[i].z, kv[j].z, s[i][j]);
                    s[i][j] = fmaf(qv[i].w, kv[j].w, s[i][j]);
                }
        }

        if (kt == qt) {
#pragma unroll
            for (int i = 0; i < 4; i++)
#pragma unroll
                for (int j = 0; j < 4; j++)
                    if (tx + 16 * j > ty * 4 + i) s[i][j] = -1e30f;
        }
#pragma unroll
        for (int i = 0; i < 4; i++)
#pragma unroll
            for (int j = 0; j < 4; j++)
                Ss[(ty * 4 + i) * 68 + tx + 16 * j] = s[i][j];
        __syncthreads();

        // online softmax: warp w owns rows w*8..w*8+7; 4 lanes per row
        {
            int w = t >> 5, lane = t & 31;
            int row = w * 8 + (lane >> 2);
            int part = lane & 3;
            float* srow = &Ss[row * 68 + part * 16];
            float lm = -1e30f;
#pragma unroll
            for (int c = 0; c < 16; c++) lm = fmaxf(lm, srow[c]);
            lm = fmaxf(lm, __shfl_xor_sync(0xffffffffu, lm, 1));
            lm = fmaxf(lm, __shfl_xor_sync(0xffffffffu, lm, 2));
            float mold = rowm[row];
            float mnew = fmaxf(mold, lm);
            float sc   = __expf(mold - mnew);
            float ls   = 0.f;
#pragma unroll
            for (int c = 0; c < 16; c++) {
                float e = __expf(srow[c] - mnew);
                srow[c] = e;
                ls += e;
            }
            ls += __shfl_xor_sync(0xffffffffu, ls, 1);
            ls += __shfl_xor_sync(0xffffffffu, ls, 2);
            if (part == 0) {
                rowm[row]  = mnew;
                rowl[row]  = rowl[row] * sc + ls;
                rowsc[row] = sc;
            }
        }
        __syncthreads();

        // O = O*scale + P @ V
#pragma unroll
        for (int i = 0; i < 4; i++) {
            float sc = rowsc[ty * 4 + i];
#pragma unroll
            for (int j = 0; j < 4; j++) oacc[i][j] *= sc;
        }
        for (int kk = 0; kk < 64; kk += 4) {
            float p[4][4];
#pragma unroll
            for (int i = 0; i < 4; i++)
                *(float4*)(p[i]) = *(const float4*)(&Ss[(ty * 4 + i) * 68 + kk]);
#pragma unroll
            for (int m = 0; m < 4; m++) {
                float vr[4];
#pragma unroll
                for (int j = 0; j < 4; j++) vr[j] = Vs[(kk + m) * 68 + tx + 16 * j];
#pragma unroll
                for (int i = 0; i < 4; i++)
#pragma unroll
                    for (int j = 0; j < 4; j++)
                        oacc[i][j] = fmaf(p[i][m], vr[j], oacc[i][j]);
            }
        }
    }

    // epilogue: divide by row sum, store
#pragma unroll
    for (int i = 0; i < 4; i++) {
        float inv = 1.f / rowl[ty * 4 + i];
        int row = qt * 64 + ty * 4 + i;
#pragma unroll
        for (int j = 0; j < 4; j++)
            ob[(size_t)row * DM + tx + 16 * j] = oacc[i][j] * inv;
    }
}

// ---------------- out = LayerNorm(a + r) * g + b  (one block per token) ----------------
__global__ void resid_ln_kernel(const float* __restrict__ a, const float* __restrict__ r,
                                const float* __restrict__ g, const float* __restrict__ bb,
                                float* __restrict__ out)
{
    int row = blockIdx.x;
    int t = threadIdx.x;
    const float* pa = a + (size_t)row * DM;
    const float* pr = r + (size_t)row * DM;
    float v[4];
    float s = 0.f, s2 = 0.f;
#pragma unroll
    for (int i = 0; i < 4; i++) {
        float x = pa[t + i * 256] + pr[t + i * 256];
        v[i] = x; s += x; s2 += x * x;
    }
#pragma unroll
    for (int off = 16; off > 0; off >>= 1) {
        s  += __shfl_down_sync(0xffffffffu, s,  off);
        s2 += __shfl_down_sync(0xffffffffu, s2, off);
    }
    __shared__ float ws[8], ws2[8];
    __shared__ float sm_mean, sm_rstd;
    int w = t >> 5, lane = t & 31;
    if (lane == 0) { ws[w] = s; ws2[w] = s2; }
    __syncthreads();
    if (t == 0) {
        float S = 0.f, S2 = 0.f;
#pragma unroll
        for (int i = 0; i < 8; i++) { S += ws[i]; S2 += ws2[i]; }
        float mean = S * (1.f / DM);
        float var  = S2 * (1.f / DM) - mean * mean;
        sm_mean = mean;
        sm_rstd = rsqrtf(var + 1e-5f);
    }
    __syncthreads();
    float mean = sm_mean, rstd = sm_rstd;
#pragma unroll
    for (int i = 0; i < 4; i++) {
        int col = t + i * 256;
        out[(size_t)row * DM + col] = (v[i] - mean) * rstd * g[col] + bb[col];
    }
}

__global__ void copy_out_kernel(float* __restrict__ out) {
    int i = blockIdx.x * 256 + threadIdx.x;
    out[i] = g_h[i];
}

// ---------------- launch ----------------
extern "C" void kernel_launch(void* const* d_in, const int* in_sizes, int n_in,
                              void* d_out, int out_size)
{
    const float* x    = (const float*)d_in[0];
    const float* pe   = (const float*)d_in[1];
    const float* wq   = (const float*)d_in[2];
    const float* wk   = (const float*)d_in[3];
    const float* wv   = (const float*)d_in[4];
    const float* ln1g = (const float*)d_in[5];
    const float* ln1b = (const float*)d_in[6];
    const float* w1   = (const float*)d_in[7];
    const float* b1   = (const float*)d_in[8];
    const float* w2   = (const float*)d_in[9];
    const float* b2   = (const float*)d_in[10];
    const float* ln2g = (const float*)d_in[11];
    const float* ln2b = (const float*)d_in[12];

    float *ph, *pq, *pk, *pv, *po, *pff;
    cudaGetSymbolAddress((void**)&ph,  g_h);
    cudaGetSymbolAddress((void**)&pq,  g_q);
    cudaGetSymbolAddress((void**)&pk,  g_k);
    cudaGetSymbolAddress((void**)&pv,  g_v);
    cudaGetSymbolAddress((void**)&po,  g_o);
    cudaGetSymbolAddress((void**)&pff, g_ff);

    const int FLASH_SMEM = (4 * 64 * 68 + 3 * 64) * 4;   // 70400 B
    cudaFuncSetAttribute(flash_kernel, cudaFuncAttributeMaxDynamicSharedMemorySize, FLASH_SMEM);

    add_pe_kernel<<<NTOK * DM / 256, 256>>>(x, pe);

    for (int l = 0; l < NLAYER; l++) {
        const float* wql = wq + (size_t)l * DM * DM;
        const float* wkl = wk + (size_t)l * DM * DM;
        const float* wvl = wv + (size_t)l * DM * DM;

        dim3 gqkv(DM / 128, NTOK / 128);       // (8, 32)
        sgemm_kernel<0, false><<<gqkv, 256>>>(ph, wql, nullptr, pq, NTOK, DM, DM);
        sgemm_kernel<0, false><<<gqkv, 256>>>(ph, wkl, nullptr, pk, NTOK, DM, DM);
        sgemm_kernel<0, false><<<gqkv, 256>>>(ph, wvl, nullptr, pv, NTOK, DM, DM);

        flash_kernel<<<dim3(SL / 64, NB * NH), 256, FLASH_SMEM>>>(pq, pk, pv, po);

        resid_ln_kernel<<<NTOK, 256>>>(ph, po, ln1g + (size_t)l * DM, ln1b + (size_t)l * DM, ph);

        sgemm_kernel<1, true><<<dim3(DFF / 128, NTOK / 128), 256>>>(
            ph, w1 + (size_t)l * DM * DFF, b1 + (size_t)l * DFF, pff, NTOK, DFF, DM);
        sgemm_kernel<0, true><<<dim3(DM / 128, NTOK / 128), 256>>>(
            pff, w2 + (size_t)l * DFF * DM, b2 + (size_t)l * DM, po, NTOK, DM, DFF);

        resid_ln_kernel<<<NTOK, 256>>>(ph, po, ln2g + (size_t)l * DM, ln2b + (size_t)l * DM, ph);
    }

    copy_out_kernel<<<NTOK * DM / 256, 256>>>((float*)d_out);
}

// round 4
// speedup vs baseline: 1.8752x; 1.8752x over previous
#include <cuda_runtime.h>
#include <cuda_fp16.h>
#include <cstdint>
#include <math.h>

#define NB 2
#define SL 2048
#define DM 1024
#define NH 16
#define DHD 64
#define NLAYER 8
#define DFF 4096
#define NTOK (NB*SL)

// ---------------- scratch (static device globals; no allocs) ----------------
__device__ __align__(256) float g_h [(size_t)NTOK*DM];
__device__ __align__(256) float g_q [(size_t)NTOK*DM];
__device__ __align__(256) float g_k [(size_t)NTOK*DM];
__device__ __align__(256) float g_v [(size_t)NTOK*DM];
__device__ __align__(256) float g_o [(size_t)NTOK*DM];

// split-fp16 activations
__device__ __align__(256) __half g_h_hi[(size_t)NTOK*DM];
__device__ __align__(256) __half g_h_lo[(size_t)NTOK*DM];
__device__ __align__(256) __half g_ff_hi[(size_t)NTOK*DFF];
__device__ __align__(256) __half g_ff_lo[(size_t)NTOK*DFF];

// transposed + split weights: [N, K] fp16 hi/lo per layer
__device__ __align__(256) __half g_wq_hi[(size_t)NLAYER*DM*DM],  g_wq_lo[(size_t)NLAYER*DM*DM];
__device__ __align__(256) __half g_wk_hi[(size_t)NLAYER*DM*DM],  g_wk_lo[(size_t)NLAYER*DM*DM];
__device__ __align__(256) __half g_wv_hi[(size_t)NLAYER*DM*DM],  g_wv_lo[(size_t)NLAYER*DM*DM];
__device__ __align__(256) __half g_w1_hi[(size_t)NLAYER*DM*DFF], g_w1_lo[(size_t)NLAYER*DM*DFF];
__device__ __align__(256) __half g_w2_hi[(size_t)NLAYER*DM*DFF], g_w2_lo[(size_t)NLAYER*DM*DFF];

// ---------------- helpers ----------------
__device__ __forceinline__ uint32_t smem_u32(const void* p) {
    uint32_t a;
    asm("{ .reg .u64 t; cvta.to.shared.u64 t, %1; cvt.u32.u64 %0, t; }" : "=r"(a) : "l"(p));
    return a;
}
#define CP_ASYNC16(dst, src) asm volatile("cp.async.cg.shared.global [%0], [%1], 16;" :: "r"(dst), "l"(src))
#define CP_COMMIT()          asm volatile("cp.async.commit_group;" ::: "memory")
#define CP_WAIT(n)           asm volatile("cp.async.wait_group %0;" :: "n"(n) : "memory")

__device__ __forceinline__ void ldsm4(uint32_t* r, uint32_t a) {
    asm volatile("ldmatrix.sync.aligned.m8n8.x4.shared.b16 {%0,%1,%2,%3}, [%4];"
        : "=r"(r[0]), "=r"(r[1]), "=r"(r[2]), "=r"(r[3]) : "r"(a));
}
__device__ __forceinline__ void mma16816(float* c, const uint32_t* a, const uint32_t* b) {
    asm volatile("mma.sync.aligned.m16n8k16.row.col.f32.f16.f16.f32 "
        "{%0,%1,%2,%3}, {%4,%5,%6,%7}, {%8,%9}, {%0,%1,%2,%3};"
        : "+f"(c[0]), "+f"(c[1]), "+f"(c[2]), "+f"(c[3])
        : "r"(a[0]), "r"(a[1]), "r"(a[2]), "r"(a[3]), "r"(b[0]), "r"(b[1]));
}
__device__ __forceinline__ void split_h(float v, __half& hi, __half& lo) {
    hi = __float2half_rn(v);
    lo = __float2half_rn(v - __half2float(hi));
}
__device__ __forceinline__ float selu_f(float v) {
    return 1.0507009873554805f * (v > 0.f ? v : 1.6732632423543772f * expm1f(v));
}

// smem tile: 128 rows x 32 fp16 = 64B/row, 4 x 16B chunks; chunk ^= (row>>1)&3
__device__ __forceinline__ uint32_t tile_off(int row, int colElem) {
    return (uint32_t)(row * 64 + ((((colElem >> 3) & 3) ^ ((row >> 1) & 3)) << 4));
}

// ---------------- h = x + pe (+ split) ----------------
__global__ void add_pe_kernel(const float* __restrict__ x, const float* __restrict__ pe) {
    int i = blockIdx.x * 256 + threadIdx.x;
    float v = x[i] + pe[i & (SL*DM - 1)];
    g_h[i] = v;
    split_h(v, g_h_hi[i], g_h_lo[i]);
}

// ---------------- split-fp16 GEMM via mma.sync (HMMA) ----------------
// C[M,N] = act( (Ah+Al)[M,K] @ (Bh+Bl)[N,K]^T + bias )
// EPI: 0 = fp32 out; 1 = bias+SELU -> fp16 hi/lo out; 2 = bias -> fp32 out
// grid (N/128, M/128), 256 threads (8 warps, warp tile 32x64). BK=32, 2-stage cp.async.
#define MM_STAGE 32768           // Ah 8K | Al 8K | Bh 8K | Bl 8K
#define MM_SMEM  (2*MM_STAGE)

template<int EPI>
__global__ __launch_bounds__(256, 1) void mm_kernel(
    const __half* __restrict__ Ah, const __half* __restrict__ Al,
    const __half* __restrict__ Bh, const __half* __restrict__ Bl,
    const float* __restrict__ bias,
    float* __restrict__ Cf, __half* __restrict__ Ch, __half* __restrict__ Cl,
    int M, int N, int K)
{
    extern __shared__ char smem[];
    const uint32_t sb = smem_u32(smem);
    const int t = threadIdx.x, lane = t & 31, wid = t >> 5;
    const int n0 = blockIdx.x * 128, m0 = blockIdx.y * 128;
    const int wm = (wid >> 1) * 32, wn = (wid & 1) * 64;

    const int row0 = t >> 2, ch0 = t & 3;
    const uint32_t so0 = tile_off(row0, ch0 * 8);   // row0+64 has same swizzle -> +4096

    float acc[2][8][4];
#pragma unroll
    for (int mt = 0; mt < 2; mt++)
#pragma unroll
        for (int nt = 0; nt < 8; nt++)
#pragma unroll
            for (int e = 0; e < 4; e++) acc[mt][nt][e] = 0.f;

    const int nst = K >> 5;

    auto LOAD_STAGE = [&](int stage, int kt) {
        const uint32_t sa = sb + stage * MM_STAGE;
        const size_t kof = (size_t)kt * 32 + ch0 * 8;
#pragma unroll
        for (int i = 0; i < 2; i++) {
            const int row = row0 + i * 64;
            const uint32_t so = sa + so0 + i * 4096;
            const size_t ga = (size_t)(m0 + row) * K + kof;
            const size_t gb = (size_t)(n0 + row) * K + kof;
            CP_ASYNC16(so,         Ah + ga);
            CP_ASYNC16(so +  8192, Al + ga);
            CP_ASYNC16(so + 16384, Bh + gb);
            CP_ASYNC16(so + 24576, Bl + gb);
        }
    };

    auto COMPUTE = [&](int stage) {
        const uint32_t sa = sb + stage * MM_STAGE;
#pragma unroll
        for (int ks = 0; ks < 2; ks++) {
            const int k0 = ks * 16;
            uint32_t ahf[2][4], alf[2][4], bhf[8][2], blf[8][2];
#pragma unroll
            for (int mt = 0; mt < 2; mt++) {
                const int r = wm + mt * 16 + (lane & 7) + ((lane >> 3) & 1) * 8;
                const int c = k0 + (lane >> 4) * 8;
                const uint32_t off = tile_off(r, c);
                ldsm4(ahf[mt], sa + off);
                ldsm4(alf[mt], sa + 8192 + off);
            }
#pragma unroll
            for (int g = 0; g < 4; g++) {
                const int r = wn + g * 16 + (lane & 7) + (lane >> 4) * 8;
                const int c = k0 + ((lane >> 3) & 1) * 8;
                const uint32_t off = tile_off(r, c);
                uint32_t tmp[4];
                ldsm4(tmp, sa + 16384 + off);
                bhf[g*2][0] = tmp[0]; bhf[g*2][1] = tmp[1];
                bhf[g*2+1][0] = tmp[2]; bhf[g*2+1][1] = tmp[3];
                ldsm4(tmp, sa + 24576 + off);
                blf[g*2][0] = tmp[0]; blf[g*2][1] = tmp[1];
                blf[g*2+1][0] = tmp[2]; blf[g*2+1][1] = tmp[3];
            }
            // three passes keeps same-accumulator MMAs 16 apart (ILP)
#pragma unroll
            for (int mt = 0; mt < 2; mt++)
#pragma unroll
                for (int nt = 0; nt < 8; nt++) mma16816(acc[mt][nt], ahf[mt], bhf[nt]);
#pragma unroll
            for (int mt = 0; mt < 2; mt++)
#pragma unroll
                for (int nt = 0; nt < 8; nt++) mma16816(acc[mt][nt], ahf[mt], blf[nt]);
#pragma unroll
            for (int mt = 0; mt < 2; mt++)
#pragma unroll
                for (int nt = 0; nt < 8; nt++) mma16816(acc[mt][nt], alf[mt], bhf[nt]);
        }
    };

    LOAD_STAGE(0, 0); CP_COMMIT();
    LOAD_STAGE(1, 1); CP_COMMIT();
    CP_WAIT(1);
    __syncthreads();

#pragma unroll 1
    for (int kt = 0; kt < nst; kt++) {
        const int cur = kt & 1;
        COMPUTE(cur);
        __syncthreads();
        if (kt + 2 < nst) { LOAD_STAGE(cur, kt + 2); CP_COMMIT(); CP_WAIT(1); }
        else              { CP_WAIT(0); }
        __syncthreads();
    }

    // epilogue: acc frag (mt,nt): rows m0+wm+mt*16+(lane>>2)(+8), cols n0+wn+nt*8+(lane&3)*2
#pragma unroll
    for (int mt = 0; mt < 2; mt++) {
        const int r0 = m0 + wm + mt * 16 + (lane >> 2);
#pragma unroll
        for (int nt = 0; nt < 8; nt++) {
            const int col = n0 + wn + nt * 8 + (lane & 3) * 2;
            float v0 = acc[mt][nt][0], v1 = acc[mt][nt][1];
            float v2 = acc[mt][nt][2], v3 = acc[mt][nt][3];
            if (EPI == 0) {
                *(float2*)(Cf + (size_t)r0 * N + col)       = make_float2(v0, v1);
                *(float2*)(Cf + (size_t)(r0 + 8) * N + col) = make_float2(v2, v3);
            } else if (EPI == 2) {
                const float b0 = bias[col], b1 = bias[col + 1];
                *(float2*)(Cf + (size_t)r0 * N + col)       = make_float2(v0 + b0, v1 + b1);
                *(float2*)(Cf + (size_t)(r0 + 8) * N + col) = make_float2(v2 + b0, v3 + b1);
            } else {
                const float b0 = bias[col], b1 = bias[col + 1];
                float s0 = selu_f(v0 + b0), s1 = selu_f(v1 + b1);
                float s2 = selu_f(v2 + b0), s3 = selu_f(v3 + b1);
                __half h0, l0, h1, l1;
                split_h(s0, h0, l0); split_h(s1, h1, l1);
                *(__half2*)(Ch + (size_t)r0 * N + col) = __halves2half2(h0, h1);
                *(__half2*)(Cl + (size_t)r0 * N + col) = __halves2half2(l0, l1);
                split_h(s2, h0, l0); split_h(s3, h1, l1);
                *(__half2*)(Ch + (size_t)(r0 + 8) * N + col) = __halves2half2(h0, h1);
                *(__half2*)(Cl + (size_t)(r0 + 8) * N + col) = __halves2half2(l0, l1);
            }
        }
    }
}

// ---------------- weight transpose + split: W[K,N] -> Wt_hi/lo[N,K] ----------------
__global__ void transpose_split_kernel(const float* __restrict__ W,
                                       __half* __restrict__ Th,
                                       __half* __restrict__ Tl,
                                       int K, int N)
{
    __shared__ float tile[32][33];
    const int l = blockIdx.z;
    const float* Wl = W + (size_t)l * K * N;
    const size_t ob = (size_t)l * K * N;
    const int n0 = blockIdx.x * 32, k0 = blockIdx.y * 32;
    for (int i = threadIdx.y; i < 32; i += 8)
        tile[i][threadIdx.x] = Wl[(size_t)(k0 + i) * N + n0 + threadIdx.x];
    __syncthreads();
    for (int i = threadIdx.y; i < 32; i += 8) {
        float v = tile[threadIdx.x][i];          // W[k0+tx][n0+i]
        __half h, lo;
        split_h(v, h, lo);
        Th[ob + (size_t)(n0 + i) * K + k0 + threadIdx.x] = h;
        Tl[ob + (size_t)(n0 + i) * K + k0 + threadIdx.x] = lo;
    }
}

// ---------------- flash attention (fp32, causal, online softmax) ----------------
__global__ __launch_bounds__(256, 2) void flash_kernel(
    const float* __restrict__ q, const float* __restrict__ k,
    const float* __restrict__ v, float* __restrict__ o)
{
    extern __shared__ float sm[];
    float* Qs    = sm;
    float* Ks    = Qs + 64 * 68;
    float* Vs    = Ks + 64 * 68;
    float* Ss    = Vs + 64 * 68;
    float* rowm  = Ss + 64 * 68;
    float* rowl  = rowm + 64;
    float* rowsc = rowl + 64;

    const int qt = gridDim.x - 1 - blockIdx.x;
    const int bh = blockIdx.y;
    const int b  = bh >> 4, hd = bh & 15;
    const float* qb = q + (size_t)b * SL * DM + hd * DHD;
    const float* kb = k + (size_t)b * SL * DM + hd * DHD;
    const float* vb = v + (size_t)b * SL * DM + hd * DHD;
    float*       ob = o + (size_t)b * SL * DM + hd * DHD;

    const int t  = threadIdx.x;
    const int tx = t & 15, ty = t >> 4;

    for (int i = t; i < 64 * 16; i += 256) {
        int r = i >> 4, c = (i & 15) * 4;
        float4 v4 = *(const float4*)(qb + (size_t)(qt * 64 + r) * DM + c);
        v4.x *= 0.125f; v4.y *= 0.125f; v4.z *= 0.125f; v4.w *= 0.125f;
        *(float4*)(&Qs[r * 68 + c]) = v4;
    }
    if (t < 64) { rowm[t] = -1e30f; rowl[t] = 0.f; }

    float oacc[4][4];
#pragma unroll
    for (int i = 0; i < 4; i++)
#pragma unroll
        for (int j = 0; j < 4; j++) oacc[i][j] = 0.f;

    for (int kt = 0; kt <= qt; kt++) {
        __syncthreads();
        for (int i = t; i < 64 * 16; i += 256) {
            int r = i >> 4, c = (i & 15) * 4;
            *(float4*)(&Ks[r * 68 + c]) = *(const float4*)(kb + (size_t)(kt * 64 + r) * DM + c);
            *(float4*)(&Vs[r * 68 + c]) = *(const float4*)(vb + (size_t)(kt * 64 + r) * DM + c);
        }
        __syncthreads();

        float s[4][4];
#pragma unroll
        for (int i = 0; i < 4; i++)
#pragma unroll
            for (int j = 0; j < 4; j++) s[i][j] = 0.f;

        for (int d = 0; d < 64; d += 4) {
            float4 qv[4], kv[4];
#pragma unroll
            for (int i = 0; i < 4; i++) qv[i] = *(const float4*)(&Qs[(ty * 4 + i) * 68 + d]);
#pragma unroll
            for (int j = 0; j < 4; j++) kv[j] = *(const float4*)(&Ks[(tx + 16 * j) * 68 + d]);
#pragma unroll
            for (int i = 0; i < 4; i++)
#pragma unroll
                for (int j = 0; j < 4; j++) {
                    s[i][j] = fmaf(qv[i].x, kv[j].x, s[i][j]);
                    s[i][j] = fmaf(qv[i].y, kv[j].y, s[i][j]);
                    s[i][j] = fmaf(qv[i].z, kv[j].z, s[i][j]);
                    s[i][j] = fmaf(qv[i].w, kv[j].w, s[i][j]);
                }
        }

        if (kt == qt) {
#pragma unroll
            for (int i = 0; i < 4; i++)
#pragma unroll
                for (int j = 0; j < 4; j++)
                    if (tx + 16 * j > ty * 4 + i) s[i][j] = -1e30f;
        }
#pragma unroll
        for (int i = 0; i < 4; i++)
#pragma unroll
            for (int j = 0; j < 4; j++)
                Ss[(ty * 4 + i) * 68 + tx + 16 * j] = s[i][j];
        __syncthreads();

        {
            int w = t >> 5, lane = t & 31;
            int row = w * 8 + (lane >> 2);
            int part = lane & 3;
            float* srow = &Ss[row * 68 + part * 16];
            float lm = -1e30f;
#pragma unroll
            for (int c = 0; c < 16; c++) lm = fmaxf(lm, srow[c]);
            lm = fmaxf(lm, __shfl_xor_sync(0xffffffffu, lm, 1));
            lm = fmaxf(lm, __shfl_xor_sync(0xffffffffu, lm, 2));
            float mold = rowm[row];
            float mnew = fmaxf(mold, lm);
            float sc   = __expf(mold - mnew);
            float ls   = 0.f;
#pragma unroll
            for (int c = 0; c < 16; c++) {
                float e = __expf(srow[c] - mnew);
                srow[c] = e;
                ls += e;
            }
            ls += __shfl_xor_sync(0xffffffffu, ls, 1);
            ls += __shfl_xor_sync(0xffffffffu, ls, 2);
            if (part == 0) {
                rowm[row]  = mnew;
                rowl[row]  = rowl[row] * sc + ls;
                rowsc[row] = sc;
            }
        }
        __syncthreads();

#pragma unroll
        for (int i = 0; i < 4; i++) {
            float sc = rowsc[ty * 4 + i];
#pragma unroll
            for (int j = 0; j < 4; j++) oacc[i][j] *= sc;
        }
        for (int kk = 0; kk < 64; kk += 4) {
            float p[4][4];
#pragma unroll
            for (int i = 0; i < 4; i++)
                *(float4*)(p[i]) = *(const float4*)(&Ss[(ty * 4 + i) * 68 + kk]);
#pragma unroll
            for (int m = 0; m < 4; m++) {
                float vr[4];
#pragma unroll
                for (int j = 0; j < 4; j++) vr[j] = Vs[(kk + m) * 68 + tx + 16 * j];
#pragma unroll
                for (int i = 0; i < 4; i++)
#pragma unroll
                    for (int j = 0; j < 4; j++)
                        oacc[i][j] = fmaf(p[i][m], vr[j], oacc[i][j]);
            }
        }
    }

#pragma unroll
    for (int i = 0; i < 4; i++) {
        float inv = 1.f / rowl[ty * 4 + i];
        int row = qt * 64 + ty * 4 + i;
#pragma unroll
        for (int j = 0; j < 4; j++)
            ob[(size_t)row * DM + tx + 16 * j] = oacc[i][j] * inv;
    }
}

// ---------------- out = LayerNorm(a + r) * g + b  (+ split) ----------------
__global__ void resid_ln_kernel(const float* __restrict__ a, const float* __restrict__ r,
                                const float* __restrict__ g, const float* __restrict__ bb,
                                float* __restrict__ out)
{
    int row = blockIdx.x;
    int t = threadIdx.x;
    const float* pa = a + (size_t)row * DM;
    const float* pr = r + (size_t)row * DM;
    float v[4];
    float s = 0.f, s2 = 0.f;
#pragma unroll
    for (int i = 0; i < 4; i++) {
        float x = pa[t + i * 256] + pr[t + i * 256];
        v[i] = x; s += x; s2 += x * x;
    }
#pragma unroll
    for (int off = 16; off > 0; off >>= 1) {
        s  += __shfl_down_sync(0xffffffffu, s,  off);
        s2 += __shfl_down_sync(0xffffffffu, s2, off);
    }
    __shared__ float ws[8], ws2[8];
    __shared__ float sm_mean, sm_rstd;
    int w = t >> 5, lane = t & 31;
    if (lane == 0) { ws[w] = s; ws2[w] = s2; }
    __syncthreads();
    if (t == 0) {
        float S = 0.f, S2 = 0.f;
#pragma unroll
        for (int i = 0; i < 8; i++) { S += ws[i]; S2 += ws2[i]; }
        float mean = S * (1.f / DM);
        float var  = S2 * (1.f / DM) - mean * mean;
        sm_mean = mean;
        sm_rstd = rsqrtf(var + 1e-5f);
    }
    __syncthreads();
    float mean = sm_mean, rstd = sm_rstd;
#pragma unroll
    for (int i = 0; i < 4; i++) {
        int col = t + i * 256;
        float y = (v[i] - mean) * rstd * g[col] + bb[col];
        size_t idx = (size_t)row * DM + col;
        out[idx] = y;
        split_h(y, g_h_hi[idx], g_h_lo[idx]);
    }
}

__global__ void copy_out_kernel(float* __restrict__ out) {
    int i = blockIdx.x * 256 + threadIdx.x;
    out[i] = g_h[i];
}

// ---------------- launch ----------------
extern "C" void kernel_launch(void* const* d_in, const int* in_sizes, int n_in,
                              void* d_out, int out_size)
{
    const float* x    = (const float*)d_in[0];
    const float* pe   = (const float*)d_in[1];
    const float* wq   = (const float*)d_in[2];
    const float* wk   = (const float*)d_in[3];
    const float* wv   = (const float*)d_in[4];
    const float* ln1g = (const float*)d_in[5];
    const float* ln1b = (const float*)d_in[6];
    const float* w1   = (const float*)d_in[7];
    const float* b1   = (const float*)d_in[8];
    const float* w2   = (const float*)d_in[9];
    const float* b2   = (const float*)d_in[10];
    const float* ln2g = (const float*)d_in[11];
    const float* ln2b = (const float*)d_in[12];

    float *ph, *pq, *pk, *pv, *po;
    cudaGetSymbolAddress((void**)&ph, g_h);
    cudaGetSymbolAddress((void**)&pq, g_q);
    cudaGetSymbolAddress((void**)&pk, g_k);
    cudaGetSymbolAddress((void**)&pv, g_v);
    cudaGetSymbolAddress((void**)&po, g_o);
    __half *phh, *phl, *pfh, *pfl;
    cudaGetSymbolAddress((void**)&phh, g_h_hi);
    cudaGetSymbolAddress((void**)&phl, g_h_lo);
    cudaGetSymbolAddress((void**)&pfh, g_ff_hi);
    cudaGetSymbolAddress((void**)&pfl, g_ff_lo);
    __half *wqh, *wql_, *wkh, *wkl, *wvh, *wvl, *w1h, *w1l, *w2h, *w2l;
    cudaGetSymbolAddress((void**)&wqh, g_wq_hi);  cudaGetSymbolAddress((void**)&wql_, g_wq_lo);
    cudaGetSymbolAddress((void**)&wkh, g_wk_hi);  cudaGetSymbolAddress((void**)&wkl,  g_wk_lo);
    cudaGetSymbolAddress((void**)&wvh, g_wv_hi);  cudaGetSymbolAddress((void**)&wvl,  g_wv_lo);
    cudaGetSymbolAddress((void**)&w1h, g_w1_hi);  cudaGetSymbolAddress((void**)&w1l,  g_w1_lo);
    cudaGetSymbolAddress((void**)&w2h, g_w2_hi);  cudaGetSymbolAddress((void**)&w2l,  g_w2_lo);

    const int FLASH_SMEM = (4 * 64 * 68 + 3 * 64) * 4;
    cudaFuncSetAttribute(flash_kernel, cudaFuncAttributeMaxDynamicSharedMemorySize, FLASH_SMEM);
    cudaFuncSetAttribute(mm_kernel<0>, cudaFuncAttributeMaxDynamicSharedMemorySize, MM_SMEM);
    cudaFuncSetAttribute(mm_kernel<1>, cudaFuncAttributeMaxDynamicSharedMemorySize, MM_SMEM);
    cudaFuncSetAttribute(mm_kernel<2>, cudaFuncAttributeMaxDynamicSharedMemorySize, MM_SMEM);

    // pre-transpose + split all weights
    dim3 tb(32, 8);
    transpose_split_kernel<<<dim3(DM/32,  DM/32,  NLAYER), tb>>>(wq, wqh, wql_, DM, DM);
    transpose_split_kernel<<<dim3(DM/32,  DM/32,  NLAYER), tb>>>(wk, wkh, wkl,  DM, DM);
    transpose_split_kernel<<<dim3(DM/32,  DM/32,  NLAYER), tb>>>(wv, wvh, wvl,  DM, DM);
    transpose_split_kernel<<<dim3(DFF/32, DM/32,  NLAYER), tb>>>(w1, w1h, w1l,  DM, DFF);
    transpose_split_kernel<<<dim3(DM/32,  DFF/32, NLAYER), tb>>>(w2, w2h, w2l,  DFF, DM);

    add_pe_kernel<<<NTOK * DM / 256, 256>>>(x, pe);

    for (int l = 0; l < NLAYER; l++) {
        const size_t wo  = (size_t)l * DM * DM;
        const size_t wo1 = (size_t)l * DM * DFF;

        dim3 gqkv(DM / 128, NTOK / 128);
        mm_kernel<0><<<gqkv, 256, MM_SMEM>>>(phh, phl, wqh + wo, wql_ + wo, nullptr,
                                             pq, nullptr, nullptr, NTOK, DM, DM);
        mm_kernel<0><<<gqkv, 256, MM_SMEM>>>(phh, phl, wkh + wo, wkl + wo, nullptr,
                                             pk, nullptr, nullptr, NTOK, DM, DM);
        mm_kernel<0><<<gqkv, 256, MM_SMEM>>>(phh, phl, wvh + wo, wvl + wo, nullptr,
                                             pv, nullptr, nullptr, NTOK, DM, DM);

        flash_kernel<<<dim3(SL / 64, NB * NH), 256, FLASH_SMEM>>>(pq, pk, pv, po);

        resid_ln_kernel<<<NTOK, 256>>>(ph, po, ln1g + (size_t)l * DM, ln1b + (size_t)l * DM, ph);

        mm_kernel<1><<<dim3(DFF / 128, NTOK / 128), 256, MM_SMEM>>>(
            phh, phl, w1h + wo1, w1l + wo1, b1 + (size_t)l * DFF,
            nullptr, pfh, pfl, NTOK, DFF, DM);
        mm_kernel<2><<<dim3(DM / 128, NTOK / 128), 256, MM_SMEM>>>(
            pfh, pfl, w2h + wo1, w2l + wo1, b2 + (size_t)l * DM,
            po, nullptr, nullptr, NTOK, DM, DFF);

        resid_ln_kernel<<<NTOK, 256>>>(ph, po, ln2g + (size_t)l * DM, ln2b + (size_t)l * DM, ph);
    }

    copy_out_kernel<<<NTOK * DM / 256, 256>>>((float*)d_out);
}

// round 5
// speedup vs baseline: 1.8759x; 1.0004x over previous
#include <cuda_runtime.h>
#include <cuda_fp16.h>
#include <cstdint>
#include <math.h>

#define NB 2
#define SL 2048
#define DM 1024
#define NH 16
#define DHD 64
#define NLAYER 8
#define DFF 4096
#define NTOK (NB*SL)
#define QS (3*DM)          // fused qkv row stride

// ---------------- scratch (static device globals; no allocs) ----------------
__device__ __align__(256) float g_h  [(size_t)NTOK*DM];
__device__ __align__(256) float g_qkv[(size_t)NTOK*QS];
__device__ __align__(256) float g_o  [(size_t)NTOK*DM];

// split-fp16 activations
__device__ __align__(256) __half g_h_hi[(size_t)NTOK*DM];
__device__ __align__(256) __half g_h_lo[(size_t)NTOK*DM];
__device__ __align__(256) __half g_ff_hi[(size_t)NTOK*DFF];
__device__ __align__(256) __half g_ff_lo[(size_t)NTOK*DFF];

// transposed + split weights: [N, K] fp16 hi/lo per layer (qkv fused: [3072,1024])
__device__ __align__(256) __half g_wqkv_hi[(size_t)NLAYER*QS*DM], g_wqkv_lo[(size_t)NLAYER*QS*DM];
__device__ __align__(256) __half g_w1_hi[(size_t)NLAYER*DM*DFF],  g_w1_lo[(size_t)NLAYER*DM*DFF];
__device__ __align__(256) __half g_w2_hi[(size_t)NLAYER*DM*DFF],  g_w2_lo[(size_t)NLAYER*DM*DFF];

// ---------------- helpers ----------------
__device__ __forceinline__ uint32_t smem_u32(const void* p) {
    uint32_t a;
    asm("{ .reg .u64 t; cvta.to.shared.u64 t, %1; cvt.u32.u64 %0, t; }" : "=r"(a) : "l"(p));
    return a;
}
#define CP_ASYNC16(dst, src) asm volatile("cp.async.cg.shared.global [%0], [%1], 16;" :: "r"(dst), "l"(src))
#define CP_COMMIT()          asm volatile("cp.async.commit_group;" ::: "memory")
#define CP_WAIT(n)           asm volatile("cp.async.wait_group %0;" :: "n"(n) : "memory")

__device__ __forceinline__ void ldsm4(uint32_t* r, uint32_t a) {
    asm volatile("ldmatrix.sync.aligned.m8n8.x4.shared.b16 {%0,%1,%2,%3}, [%4];"
        : "=r"(r[0]), "=r"(r[1]), "=r"(r[2]), "=r"(r[3]) : "r"(a));
}
__device__ __forceinline__ void mma16816(float* c, const uint32_t* a, const uint32_t* b) {
    asm volatile("mma.sync.aligned.m16n8k16.row.col.f32.f16.f16.f32 "
        "{%0,%1,%2,%3}, {%4,%5,%6,%7}, {%8,%9}, {%0,%1,%2,%3};"
        : "+f"(c[0]), "+f"(c[1]), "+f"(c[2]), "+f"(c[3])
        : "r"(a[0]), "r"(a[1]), "r"(a[2]), "r"(a[3]), "r"(b[0]), "r"(b[1]));
}
__device__ __forceinline__ void split_h(float v, __half& hi, __half& lo) {
    hi = __float2half_rn(v);
    lo = __float2half_rn(v - __half2float(hi));
}
__device__ __forceinline__ float selu_f(float v) {
    return 1.0507009873554805f * (v > 0.f ? v : 1.6732632423543772f * expm1f(v));
}

// smem tile: 128 rows x 32 fp16 = 64B/row, 4 x 16B chunks; chunk ^= (row>>1)&3
__device__ __forceinline__ uint32_t tile_off(int row, int colElem) {
    return (uint32_t)(row * 64 + ((((colElem >> 3) & 3) ^ ((row >> 1) & 3)) << 4));
}

// ---------------- h = x + pe (+ split) ----------------
__global__ void add_pe_kernel(const float* __restrict__ x, const float* __restrict__ pe) {
    int i = blockIdx.x * 256 + threadIdx.x;
    float v = x[i] + pe[i & (SL*DM - 1)];
    g_h[i] = v;
    split_h(v, g_h_hi[i], g_h_lo[i]);
}

// ---------------- split-fp16 GEMM via mma.sync (HMMA) ----------------
// C[M,N] = act( (Ah+Al)[M,K] @ (Bh+Bl)[N,K]^T + bias )
// EPI: 0 = fp32 out; 1 = bias+SELU -> fp16 hi/lo out; 2 = bias -> fp32 out
// grid (N/128, M/128), 256 threads (8 warps, warp tile 32x64). BK=32, 4-stage cp.async,
// single __syncthreads per k-step, loads issued before compute.
#define MM_STAGE 32768           // Ah 8K | Al 8K | Bh 8K | Bl 8K
#define MM_NSTG  4
#define MM_SMEM  (MM_NSTG*MM_STAGE)

template<int EPI>
__global__ __launch_bounds__(256, 1) void mm_kernel(
    const __half* __restrict__ Ah, const __half* __restrict__ Al,
    const __half* __restrict__ Bh, const __half* __restrict__ Bl,
    const float* __restrict__ bias,
    float* __restrict__ Cf, __half* __restrict__ Ch, __half* __restrict__ Cl,
    int M, int N, int K)
{
    extern __shared__ char smem[];
    const uint32_t sb = smem_u32(smem);
    const int t = threadIdx.x, lane = t & 31, wid = t >> 5;
    const int n0 = blockIdx.x * 128, m0 = blockIdx.y * 128;
    const int wm = (wid >> 1) * 32, wn = (wid & 1) * 64;

    const int row0 = t >> 2, ch0 = t & 3;
    const uint32_t so0 = tile_off(row0, ch0 * 8);   // row0+64 has same swizzle -> +4096

    float acc[2][8][4];
#pragma unroll
    for (int mt = 0; mt < 2; mt++)
#pragma unroll
        for (int nt = 0; nt < 8; nt++)
#pragma unroll
            for (int e = 0; e < 4; e++) acc[mt][nt][e] = 0.f;

    const int nst = K >> 5;

    auto LOAD_STAGE = [&](int stage, int kt) {
        const uint32_t sa = sb + stage * MM_STAGE;
        const size_t kof = (size_t)kt * 32 + ch0 * 8;
#pragma unroll
        for (int i = 0; i < 2; i++) {
            const int row = row0 + i * 64;
            const uint32_t so = sa + so0 + i * 4096;
            const size_t ga = (size_t)(m0 + row) * K + kof;
            const size_t gb = (size_t)(n0 + row) * K + kof;
            CP_ASYNC16(so,         Ah + ga);
            CP_ASYNC16(so +  8192, Al + ga);
            CP_ASYNC16(so + 16384, Bh + gb);
            CP_ASYNC16(so + 24576, Bl + gb);
        }
    };

    auto COMPUTE = [&](int stage) {
        const uint32_t sa = sb + stage * MM_STAGE;
#pragma unroll
        for (int ks = 0; ks < 2; ks++) {
            const int k0 = ks * 16;
            uint32_t ahf[2][4], alf[2][4], bhf[8][2], blf[8][2];
#pragma unroll
            for (int mt = 0; mt < 2; mt++) {
                const int r = wm + mt * 16 + (lane & 7) + ((lane >> 3) & 1) * 8;
                const int c = k0 + (lane >> 4) * 8;
                const uint32_t off = tile_off(r, c);
                ldsm4(ahf[mt], sa + off);
                ldsm4(alf[mt], sa + 8192 + off);
            }
#pragma unroll
            for (int g = 0; g < 4; g++) {
                const int r = wn + g * 16 + (lane & 7) + (lane >> 4) * 8;
                const int c = k0 + ((lane >> 3) & 1) * 8;
                const uint32_t off = tile_off(r, c);
                uint32_t tmp[4];
                ldsm4(tmp, sa + 16384 + off);
                bhf[g*2][0] = tmp[0]; bhf[g*2][1] = tmp[1];
                bhf[g*2+1][0] = tmp[2]; bhf[g*2+1][1] = tmp[3];
                ldsm4(tmp, sa + 24576 + off);
                blf[g*2][0] = tmp[0]; blf[g*2][1] = tmp[1];
                blf[g*2+1][0] = tmp[2]; blf[g*2+1][1] = tmp[3];
            }
#pragma unroll
            for (int mt = 0; mt < 2; mt++)
#pragma unroll
                for (int nt = 0; nt < 8; nt++) mma16816(acc[mt][nt], ahf[mt], bhf[nt]);
#pragma unroll
            for (int mt = 0; mt < 2; mt++)
#pragma unroll
                for (int nt = 0; nt < 8; nt++) mma16816(acc[mt][nt], ahf[mt], blf[nt]);
#pragma unroll
            for (int mt = 0; mt < 2; mt++)
#pragma unroll
                for (int nt = 0; nt < 8; nt++) mma16816(acc[mt][nt], alf[mt], bhf[nt]);
        }
    };

    // prologue: stages 0,1,2 in flight
    LOAD_STAGE(0, 0); CP_COMMIT();
    LOAD_STAGE(1, 1); CP_COMMIT();
    LOAD_STAGE(2, 2); CP_COMMIT();

#pragma unroll 1
    for (int kt = 0; kt < nst; kt++) {
        if (kt + 3 < nst) { CP_WAIT(2); } else { CP_WAIT(0); }
        __syncthreads();
        if (kt + 3 < nst) { LOAD_STAGE((kt + 3) & 3, kt + 3); CP_COMMIT(); }
        COMPUTE(kt & 3);
    }

    // epilogue: acc frag (mt,nt): rows m0+wm+mt*16+(lane>>2)(+8), cols n0+wn+nt*8+(lane&3)*2
#pragma unroll
    for (int mt = 0; mt < 2; mt++) {
        const int r0 = m0 + wm + mt * 16 + (lane >> 2);
#pragma unroll
        for (int nt = 0; nt < 8; nt++) {
            const int col = n0 + wn + nt * 8 + (lane & 3) * 2;
            float v0 = acc[mt][nt][0], v1 = acc[mt][nt][1];
            float v2 = acc[mt][nt][2], v3 = acc[mt][nt][3];
            if (EPI == 0) {
                *(float2*)(Cf + (size_t)r0 * N + col)       = make_float2(v0, v1);
                *(float2*)(Cf + (size_t)(r0 + 8) * N + col) = make_float2(v2, v3);
            } else if (EPI == 2) {
                const float b0 = bias[col], b1 = bias[col + 1];
                *(float2*)(Cf + (size_t)r0 * N + col)       = make_float2(v0 + b0, v1 + b1);
                *(float2*)(Cf + (size_t)(r0 + 8) * N + col) = make_float2(v2 + b0, v3 + b1);
            } else {
                const float b0 = bias[col], b1 = bias[col + 1];
                float s0 = selu_f(v0 + b0), s1 = selu_f(v1 + b1);
                float s2 = selu_f(v2 + b0), s3 = selu_f(v3 + b1);
                __half h0, l0, h1, l1;
                split_h(s0, h0, l0); split_h(s1, h1, l1);
                *(__half2*)(Ch + (size_t)r0 * N + col) = __halves2half2(h0, h1);
                *(__half2*)(Cl + (size_t)r0 * N + col) = __halves2half2(l0, l1);
                split_h(s2, h0, l0); split_h(s3, h1, l1);
                *(__half2*)(Ch + (size_t)(r0 + 8) * N + col) = __halves2half2(h0, h1);
                *(__half2*)(Cl + (size_t)(r0 + 8) * N + col) = __halves2half2(l0, l1);
            }
        }
    }
}

// ---------------- weight transpose + split: W[K,N] -> Wt_hi/lo[N,K] ----------------
__global__ void transpose_split_kernel(const float* __restrict__ W,
                                       __half* __restrict__ Th,
                                       __half* __restrict__ Tl,
                                       int K, int N, size_t in_lstride, size_t out_lstride)
{
    __shared__ float tile[32][33];
    const int l = blockIdx.z;
    const float* Wl = W + (size_t)l * in_lstride;
    const size_t ob = (size_t)l * out_lstride;
    const int n0 = blockIdx.x * 32, k0 = blockIdx.y * 32;
    for (int i = threadIdx.y; i < 32; i += 8)
        tile[i][threadIdx.x] = Wl[(size_t)(k0 + i) * N + n0 + threadIdx.x];
    __syncthreads();
    for (int i = threadIdx.y; i < 32; i += 8) {
        float v = tile[threadIdx.x][i];          // W[k0+tx][n0+i]
        __half h, lo;
        split_h(v, h, lo);
        Th[ob + (size_t)(n0 + i) * K + k0 + threadIdx.x] = h;
        Tl[ob + (size_t)(n0 + i) * K + k0 + threadIdx.x] = lo;
    }
}

// ---------------- flash attention (fp32, causal, online softmax) ----------------
// q/k/v come from the fused qkv buffer [NTOK, 3072]; o -> [NTOK, DM]
__global__ __launch_bounds__(256, 2) void flash_kernel(
    const float* __restrict__ qkv, float* __restrict__ o)
{
    extern __shared__ float sm[];
    float* Qs    = sm;
    float* Ks    = Qs + 64 * 68;
    float* Vs    = Ks + 64 * 68;
    float* Ss    = Vs + 64 * 68;
    float* rowm  = Ss + 64 * 68;
    float* rowl  = rowm + 64;
    float* rowsc = rowl + 64;

    const int qt = gridDim.x - 1 - blockIdx.x;
    const int bh = blockIdx.y;
    const int b  = bh >> 4, hd = bh & 15;
    const float* qb = qkv + (size_t)b * SL * QS + hd * DHD;
    const float* kb = qb + DM;
    const float* vb = qb + 2 * DM;
    float*       ob = o + (size_t)b * SL * DM + hd * DHD;

    const int t  = threadIdx.x;
    const int tx = t & 15, ty = t >> 4;

    for (int i = t; i < 64 * 16; i += 256) {
        int r = i >> 4, c = (i & 15) * 4;
        float4 v4 = *(const float4*)(qb + (size_t)(qt * 64 + r) * QS + c);
        v4.x *= 0.125f; v4.y *= 0.125f; v4.z *= 0.125f; v4.w *= 0.125f;
        *(float4*)(&Qs[r * 68 + c]) = v4;
    }
    if (t < 64) { rowm[t] = -1e30f; rowl[t] = 0.f; }

    float oacc[4][4];
#pragma unroll
    for (int i = 0; i < 4; i++)
#pragma unroll
        for (int j = 0; j < 4; j++) oacc[i][j] = 0.f;

    for (int kt = 0; kt <= qt; kt++) {
        __syncthreads();
        for (int i = t; i < 64 * 16; i += 256) {
            int r = i >> 4, c = (i & 15) * 4;
            *(float4*)(&Ks[r * 68 + c]) = *(const float4*)(kb + (size_t)(kt * 64 + r) * QS + c);
            *(float4*)(&Vs[r * 68 + c]) = *(const float4*)(vb + (size_t)(kt * 64 + r) * QS + c);
        }
        __syncthreads();

        float s[4][4];
#pragma unroll
        for (int i = 0; i < 4; i++)
#pragma unroll
            for (int j = 0; j < 4; j++) s[i][j] = 0.f;

        for (int d = 0; d < 64; d += 4) {
            float4 qv[4], kv[4];
#pragma unroll
            for (int i = 0; i < 4; i++) qv[i] = *(const float4*)(&Qs[(ty * 4 + i) * 68 + d]);
#pragma unroll
            for (int j = 0; j < 4; j++) kv[j] = *(const float4*)(&Ks[(tx + 16 * j) * 68 + d]);
#pragma unroll
            for (int i = 0; i < 4; i++)
#pragma unroll
                for (int j = 0; j < 4; j++) {
                    s[i][j] = fmaf(qv[i].x, kv[j].x, s[i][j]);
                    s[i][j] = fmaf(qv[i].y, kv[j].y, s[i][j]);
                    s[i][j] = fmaf(qv[i].z, kv[j].z, s[i][j]);
                    s[i][j] = fmaf(qv[i].w, kv[j].w, s[i][j]);
                }
        }

        if (kt == qt) {
#pragma unroll
            for (int i = 0; i < 4; i++)
#pragma unroll
                for (int j = 0; j < 4; j++)
                    if (tx + 16 * j > ty * 4 + i) s[i][j] = -1e30f;
        }
#pragma unroll
        for (int i = 0; i < 4; i++)
#pragma unroll
            for (int j = 0; j < 4; j++)
                Ss[(ty * 4 + i) * 68 + tx + 16 * j] = s[i][j];
        __syncthreads();

        {
            int w = t >> 5, lane = t & 31;
            int row = w * 8 + (lane >> 2);
            int part = lane & 3;
            float* srow = &Ss[row * 68 + part * 16];
            float lm = -1e30f;
#pragma unroll
            for (int c = 0; c < 16; c++) lm = fmaxf(lm, srow[c]);
            lm = fmaxf(lm, __shfl_xor_sync(0xffffffffu, lm, 1));
            lm = fmaxf(lm, __shfl_xor_sync(0xffffffffu, lm, 2));
            float mold = rowm[row];
            float mnew = fmaxf(mold, lm);
            float sc   = __expf(mold - mnew);
            float ls   = 0.f;
#pragma unroll
            for (int c = 0; c < 16; c++) {
                float e = __expf(srow[c] - mnew);
                srow[c] = e;
                ls += e;
            }
            ls += __shfl_xor_sync(0xffffffffu, ls, 1);
            ls += __shfl_xor_sync(0xffffffffu, ls, 2);
            if (part == 0) {
                rowm[row]  = mnew;
                rowl[row]  = rowl[row] * sc + ls;
                rowsc[row] = sc;
            }
        }
        __syncthreads();

#pragma unroll
        for (int i = 0; i < 4; i++) {
            float sc = rowsc[ty * 4 + i];
#pragma unroll
            for (int j = 0; j < 4; j++) oacc[i][j] *= sc;
        }
        for (int kk = 0; kk < 64; kk += 4) {
            float p[4][4];
#pragma unroll
            for (int i = 0; i < 4; i++)
                *(float4*)(p[i]) = *(const float4*)(&Ss[(ty * 4 + i) * 68 + kk]);
#pragma unroll
            for (int m = 0; m < 4; m++) {
                float vr[4];
#pragma unroll
                for (int j = 0; j < 4; j++) vr[j] = Vs[(kk + m) * 68 + tx + 16 * j];
#pragma unroll
                for (int i = 0; i < 4; i++)
#pragma unroll
                    for (int j = 0; j < 4; j++)
                        oacc[i][j] = fmaf(p[i][m], vr[j], oacc[i][j]);
            }
        }
    }

#pragma unroll
    for (int i = 0; i < 4; i++) {
        float inv = 1.f / rowl[ty * 4 + i];
        int row = qt * 64 + ty * 4 + i;
#pragma unroll
        for (int j = 0; j < 4; j++)
            ob[(size_t)row * DM + tx + 16 * j] = oacc[i][j] * inv;
    }
}

// ---------------- out = LayerNorm(a + r) * g + b  (+ split) ----------------
__global__ void resid_ln_kernel(const float* __restrict__ a, const float* __restrict__ r,
                                const float* __restrict__ g, const float* __restrict__ bb,
                                float* __restrict__ out)
{
    int row = blockIdx.x;
    int t = threadIdx.x;
    const float* pa = a + (size_t)row * DM;
    const float* pr = r + (size_t)row * DM;
    float v[4];
    float s = 0.f, s2 = 0.f;
#pragma unroll
    for (int i = 0; i < 4; i++) {
        float x = pa[t + i * 256] + pr[t + i * 256];
        v[i] = x; s += x; s2 += x * x;
    }
#pragma unroll
    for (int off = 16; off > 0; off >>= 1) {
        s  += __shfl_down_sync(0xffffffffu, s,  off);
        s2 += __shfl_down_sync(0xffffffffu, s2, off);
    }
    __shared__ float ws[8], ws2[8];
    __shared__ float sm_mean, sm_rstd;
    int w = t >> 5, lane = t & 31;
    if (lane == 0) { ws[w] = s; ws2[w] = s2; }
    __syncthreads();
    if (t == 0) {
        float S = 0.f, S2 = 0.f;
#pragma unroll
        for (int i = 0; i < 8; i++) { S += ws[i]; S2 += ws2[i]; }
        float mean = S * (1.f / DM);
        float var  = S2 * (1.f / DM) - mean * mean;
        sm_mean = mean;
        sm_rstd = rsqrtf(var + 1e-5f);
    }
    __syncthreads();
    float mean = sm_mean, rstd = sm_rstd;
#pragma unroll
    for (int i = 0; i < 4; i++) {
        int col = t + i * 256;
        float y = (v[i] - mean) * rstd * g[col] + bb[col];
        size_t idx = (size_t)row * DM + col;
        out[idx] = y;
        split_h(y, g_h_hi[idx], g_h_lo[idx]);
    }
}

__global__ void copy_out_kernel(float* __restrict__ out) {
    int i = blockIdx.x * 256 + threadIdx.x;
    out[i] = g_h[i];
}

// ---------------- launch ----------------
extern "C" void kernel_launch(void* const* d_in, const int* in_sizes, int n_in,
                              void* d_out, int out_size)
{
    const float* x    = (const float*)d_in[0];
    const float* pe   = (const float*)d_in[1];
    const float* wq   = (const float*)d_in[2];
    const float* wk   = (const float*)d_in[3];
    const float* wv   = (const float*)d_in[4];
    const float* ln1g = (const float*)d_in[5];
    const float* ln1b = (const float*)d_in[6];
    const float* w1   = (const float*)d_in[7];
    const float* b1   = (const float*)d_in[8];
    const float* w2   = (const float*)d_in[9];
    const float* b2   = (const float*)d_in[10];
    const float* ln2g = (const float*)d_in[11];
    const float* ln2b = (const float*)d_in[12];

    float *ph, *pqkv, *po;
    cudaGetSymbolAddress((void**)&ph,   g_h);
    cudaGetSymbolAddress((void**)&pqkv, g_qkv);
    cudaGetSymbolAddress((void**)&po,   g_o);
    __half *phh, *phl, *pfh, *pfl;
    cudaGetSymbolAddress((void**)&phh, g_h_hi);
    cudaGetSymbolAddress((void**)&phl, g_h_lo);
    cudaGetSymbolAddress((void**)&pfh, g_ff_hi);
    cudaGetSymbolAddress((void**)&pfl, g_ff_lo);
    __half *wqkvh, *wqkvl, *w1h, *w1l, *w2h, *w2l;
    cudaGetSymbolAddress((void**)&wqkvh, g_wqkv_hi); cudaGetSymbolAddress((void**)&wqkvl, g_wqkv_lo);
    cudaGetSymbolAddress((void**)&w1h, g_w1_hi);     cudaGetSymbolAddress((void**)&w1l, g_w1_lo);
    cudaGetSymbolAddress((void**)&w2h, g_w2_hi);     cudaGetSymbolAddress((void**)&w2l, g_w2_lo);

    const int FLASH_SMEM = (4 * 64 * 68 + 3 * 64) * 4;
    cudaFuncSetAttribute(flash_kernel, cudaFuncAttributeMaxDynamicSharedMemorySize, FLASH_SMEM);
    cudaFuncSetAttribute(mm_kernel<0>, cudaFuncAttributeMaxDynamicSharedMemorySize, MM_SMEM);
    cudaFuncSetAttribute(mm_kernel<1>, cudaFuncAttributeMaxDynamicSharedMemorySize, MM_SMEM);
    cudaFuncSetAttribute(mm_kernel<2>, cudaFuncAttributeMaxDynamicSharedMemorySize, MM_SMEM);

    // pre-transpose + split all weights (qkv into one fused [3072,1024] block per layer)
    dim3 tb(32, 8);
    transpose_split_kernel<<<dim3(DM/32,  DM/32,  NLAYER), tb>>>(
        wq, wqkvh,                    wqkvl,                    DM, DM,
        (size_t)DM*DM, (size_t)QS*DM);
    transpose_split_kernel<<<dim3(DM/32,  DM/32,  NLAYER), tb>>>(
        wk, wqkvh + (size_t)DM*DM,    wqkvl + (size_t)DM*DM,    DM, DM,
        (size_t)DM*DM, (size_t)QS*DM);
    transpose_split_kernel<<<dim3(DM/32,  DM/32,  NLAYER), tb>>>(
        wv, wqkvh + (size_t)2*DM*DM,  wqkvl + (size_t)2*DM*DM,  DM, DM,
        (size_t)DM*DM, (size_t)QS*DM);
    transpose_split_kernel<<<dim3(DFF/32, DM/32,  NLAYER), tb>>>(
        w1, w1h, w1l, DM, DFF, (size_t)DM*DFF, (size_t)DM*DFF);
    transpose_split_kernel<<<dim3(DM/32,  DFF/32, NLAYER), tb>>>(
        w2, w2h, w2l, DFF, DM, (size_t)DM*DFF, (size_t)DM*DFF);

    add_pe_kernel<<<NTOK * DM / 256, 256>>>(x, pe);

    for (int l = 0; l < NLAYER; l++) {
        const size_t woq = (size_t)l * QS * DM;
        const size_t wo1 = (size_t)l * DM * DFF;

        // fused QKV: [NTOK,1024] x [3072,1024]^T -> [NTOK,3072]
        mm_kernel<0><<<dim3(QS / 128, NTOK / 128), 256, MM_SMEM>>>(
            phh, phl, wqkvh + woq, wqkvl + woq, nullptr,
            pqkv, nullptr, nullptr, NTOK, QS, DM);

        flash_kernel<<<dim3(SL / 64, NB * NH), 256, FLASH_SMEM>>>(pqkv, po);

        resid_ln_kernel<<<NTOK, 256>>>(ph, po, ln1g + (size_t)l * DM, ln1b + (size_t)l * DM, ph);

        mm_kernel<1><<<dim3(DFF / 128, NTOK / 128), 256, MM_SMEM>>>(
            phh, phl, w1h + wo1, w1l + wo1, b1 + (size_t)l * DFF,
            nullptr, pfh, pfl, NTOK, DFF, DM);
        mm_kernel<2><<<dim3(DM / 128, NTOK / 128), 256, MM_SMEM>>>(
            pfh, pfl, w2h + wo1, w2l + wo1, b2 + (size_t)l * DM,
            po, nullptr, nullptr, NTOK, DM, DFF);

        resid_ln_kernel<<<NTOK, 256>>>(ph, po, ln2g + (size_t)l * DM, ln2b + (size_t)l * DM, ph);
    }

    copy_out_kernel<<<NTOK * DM / 256, 256>>>((float*)d_out);
}

// round 6
// speedup vs baseline: 2.8130x; 1.4995x over previous
#include <cuda_runtime.h>
#include <cuda_fp16.h>
#include <cstdint>
#include <math.h>

#define NB 2
#define SL 2048
#define DM 1024
#define NH 16
#define DHD 64
#define NLAYER 8
#define DFF 4096
#define NTOK (NB*SL)
#define QS (3*DM)          // fused qkv row stride

// ---------------- scratch (static device globals; no allocs) ----------------
__device__ __align__(256) float g_h  [(size_t)NTOK*DM];
__device__ __align__(256) float g_o  [(size_t)NTOK*DM];

// split-fp16 activations
__device__ __align__(256) __half g_h_hi[(size_t)NTOK*DM];
__device__ __align__(256) __half g_h_lo[(size_t)NTOK*DM];
__device__ __align__(256) __half g_ff_hi[(size_t)NTOK*DFF];
__device__ __align__(256) __half g_ff_lo[(size_t)NTOK*DFF];
__device__ __align__(256) __half g_qkv_hi[(size_t)NTOK*QS];
__device__ __align__(256) __half g_qkv_lo[(size_t)NTOK*QS];

// transposed + split weights: [N, K] fp16 hi/lo per layer (qkv fused: [3072,1024])
__device__ __align__(256) __half g_wqkv_hi[(size_t)NLAYER*QS*DM], g_wqkv_lo[(size_t)NLAYER*QS*DM];
__device__ __align__(256) __half g_w1_hi[(size_t)NLAYER*DM*DFF],  g_w1_lo[(size_t)NLAYER*DM*DFF];
__device__ __align__(256) __half g_w2_hi[(size_t)NLAYER*DM*DFF],  g_w2_lo[(size_t)NLAYER*DM*DFF];

// ---------------- helpers ----------------
__device__ __forceinline__ uint32_t smem_u32(const void* p) {
    uint32_t a;
    asm("{ .reg .u64 t; cvta.to.shared.u64 t, %1; cvt.u32.u64 %0, t; }" : "=r"(a) : "l"(p));
    return a;
}
#define CP_ASYNC16(dst, src) asm volatile("cp.async.cg.shared.global [%0], [%1], 16;" :: "r"(dst), "l"(src))
#define CP_COMMIT()          asm volatile("cp.async.commit_group;" ::: "memory")
#define CP_WAIT(n)           asm volatile("cp.async.wait_group %0;" :: "n"(n) : "memory")

__device__ __forceinline__ void ldsm4(uint32_t* r, uint32_t a) {
    asm volatile("ldmatrix.sync.aligned.m8n8.x4.shared.b16 {%0,%1,%2,%3}, [%4];"
        : "=r"(r[0]), "=r"(r[1]), "=r"(r[2]), "=r"(r[3]) : "r"(a));
}
__device__ __forceinline__ void ldsm4t(uint32_t* r, uint32_t a) {
    asm volatile("ldmatrix.sync.aligned.m8n8.x4.trans.shared.b16 {%0,%1,%2,%3}, [%4];"
        : "=r"(r[0]), "=r"(r[1]), "=r"(r[2]), "=r"(r[3]) : "r"(a));
}
__device__ __forceinline__ void mma16816(float* c, const uint32_t* a, const uint32_t* b) {
    asm volatile("mma.sync.aligned.m16n8k16.row.col.f32.f16.f16.f32 "
        "{%0,%1,%2,%3}, {%4,%5,%6,%7}, {%8,%9}, {%0,%1,%2,%3};"
        : "+f"(c[0]), "+f"(c[1]), "+f"(c[2]), "+f"(c[3])
        : "r"(a[0]), "r"(a[1]), "r"(a[2]), "r"(a[3]), "r"(b[0]), "r"(b[1]));
}
__device__ __forceinline__ void split_h(float v, __half& hi, __half& lo) {
    hi = __float2half_rn(v);
    lo = __float2half_rn(v - __half2float(hi));
}
__device__ __forceinline__ float selu_f(float v) {
    return 1.0507009873554805f * (v > 0.f ? v : 1.6732632423543772f * expm1f(v));
}
__device__ __forceinline__ uint32_t packh(float a, float b) {
    __half2 h = __floats2half2_rn(a, b);
    return *(uint32_t*)&h;
}

// GEMM smem tile: 128 rows x 32 fp16 = 64B/row, 4 x 16B chunks; chunk ^= (row>>1)&3
__device__ __forceinline__ uint32_t tile_off(int row, int colElem) {
    return (uint32_t)(row * 64 + ((((colElem >> 3) & 3) ^ ((row >> 1) & 3)) << 4));
}
// flash smem tile: 64 rows x 64 fp16 = 128B/row, 8 x 16B chunks; chunk ^= row&7
__device__ __forceinline__ uint32_t fa_off(int row, int colElem) {
    return (uint32_t)(row * 128 + ((((colElem >> 3) & 7) ^ (row & 7)) << 4));
}

// ---------------- h = x + pe (+ split) ----------------
__global__ void add_pe_kernel(const float* __restrict__ x, const float* __restrict__ pe) {
    int i = blockIdx.x * 256 + threadIdx.x;
    float v = x[i] + pe[i & (SL*DM - 1)];
    g_h[i] = v;
    split_h(v, g_h_hi[i], g_h_lo[i]);
}

// ---------------- split-fp16 GEMM via mma.sync (HMMA) ----------------
// C[M,N] = act( (Ah+Al)[M,K] @ (Bh+Bl)[N,K]^T + bias )
// EPI: 0 = fp32 out; 1 = bias+SELU -> fp16 hi/lo; 2 = bias -> fp32; 3 = qkv split fp16 (q scaled 0.125)
#define MM_STAGE 32768           // Ah 8K | Al 8K | Bh 8K | Bl 8K
#define MM_NSTG  4
#define MM_SMEM  (MM_NSTG*MM_STAGE)

template<int EPI>
__global__ __launch_bounds__(256, 1) void mm_kernel(
    const __half* __restrict__ Ah, const __half* __restrict__ Al,
    const __half* __restrict__ Bh, const __half* __restrict__ Bl,
    const float* __restrict__ bias,
    float* __restrict__ Cf, __half* __restrict__ Ch, __half* __restrict__ Cl,
    int M, int N, int K)
{
    extern __shared__ char smem[];
    const uint32_t sb = smem_u32(smem);
    const int t = threadIdx.x, lane = t & 31, wid = t >> 5;
    const int n0 = blockIdx.x * 128, m0 = blockIdx.y * 128;
    const int wm = (wid >> 1) * 32, wn = (wid & 1) * 64;

    const int row0 = t >> 2, ch0 = t & 3;
    const uint32_t so0 = tile_off(row0, ch0 * 8);

    float acc[2][8][4];
#pragma unroll
    for (int mt = 0; mt < 2; mt++)
#pragma unroll
        for (int nt = 0; nt < 8; nt++)
#pragma unroll
            for (int e = 0; e < 4; e++) acc[mt][nt][e] = 0.f;

    const int nst = K >> 5;

    auto LOAD_STAGE = [&](int stage, int kt) {
        const uint32_t sa = sb + stage * MM_STAGE;
        const size_t kof = (size_t)kt * 32 + ch0 * 8;
#pragma unroll
        for (int i = 0; i < 2; i++) {
            const int row = row0 + i * 64;
            const uint32_t so = sa + so0 + i * 4096;
            const size_t ga = (size_t)(m0 + row) * K + kof;
            const size_t gb = (size_t)(n0 + row) * K + kof;
            CP_ASYNC16(so,         Ah + ga);
            CP_ASYNC16(so +  8192, Al + ga);
            CP_ASYNC16(so + 16384, Bh + gb);
            CP_ASYNC16(so + 24576, Bl + gb);
        }
    };

    auto COMPUTE = [&](int stage) {
        const uint32_t sa = sb + stage * MM_STAGE;
#pragma unroll
        for (int ks = 0; ks < 2; ks++) {
            const int k0 = ks * 16;
            uint32_t ahf[2][4], alf[2][4], bhf[8][2], blf[8][2];
#pragma unroll
            for (int mt = 0; mt < 2; mt++) {
                const int r = wm + mt * 16 + (lane & 7) + ((lane >> 3) & 1) * 8;
                const int c = k0 + (lane >> 4) * 8;
                const uint32_t off = tile_off(r, c);
                ldsm4(ahf[mt], sa + off);
                ldsm4(alf[mt], sa + 8192 + off);
            }
#pragma unroll
            for (int g = 0; g < 4; g++) {
                const int r = wn + g * 16 + (lane & 7) + (lane >> 4) * 8;
                const int c = k0 + ((lane >> 3) & 1) * 8;
                const uint32_t off = tile_off(r, c);
                uint32_t tmp[4];
                ldsm4(tmp, sa + 16384 + off);
                bhf[g*2][0] = tmp[0]; bhf[g*2][1] = tmp[1];
                bhf[g*2+1][0] = tmp[2]; bhf[g*2+1][1] = tmp[3];
                ldsm4(tmp, sa + 24576 + off);
                blf[g*2][0] = tmp[0]; blf[g*2][1] = tmp[1];
                blf[g*2+1][0] = tmp[2]; blf[g*2+1][1] = tmp[3];
            }
#pragma unroll
            for (int mt = 0; mt < 2; mt++)
#pragma unroll
                for (int nt = 0; nt < 8; nt++) mma16816(acc[mt][nt], ahf[mt], bhf[nt]);
#pragma unroll
            for (int mt = 0; mt < 2; mt++)
#pragma unroll
                for (int nt = 0; nt < 8; nt++) mma16816(acc[mt][nt], ahf[mt], blf[nt]);
#pragma unroll
            for (int mt = 0; mt < 2; mt++)
#pragma unroll
                for (int nt = 0; nt < 8; nt++) mma16816(acc[mt][nt], alf[mt], bhf[nt]);
        }
    };

    LOAD_STAGE(0, 0); CP_COMMIT();
    LOAD_STAGE(1, 1); CP_COMMIT();
    LOAD_STAGE(2, 2); CP_COMMIT();

#pragma unroll 1
    for (int kt = 0; kt < nst; kt++) {
        if (kt + 3 < nst) { CP_WAIT(2); } else { CP_WAIT(0); }
        __syncthreads();
        if (kt + 3 < nst) { LOAD_STAGE((kt + 3) & 3, kt + 3); CP_COMMIT(); }
        COMPUTE(kt & 3);
    }

#pragma unroll
    for (int mt = 0; mt < 2; mt++) {
        const int r0 = m0 + wm + mt * 16 + (lane >> 2);
#pragma unroll
        for (int nt = 0; nt < 8; nt++) {
            const int col = n0 + wn + nt * 8 + (lane & 3) * 2;
            float v0 = acc[mt][nt][0], v1 = acc[mt][nt][1];
            float v2 = acc[mt][nt][2], v3 = acc[mt][nt][3];
            if (EPI == 0) {
                *(float2*)(Cf + (size_t)r0 * N + col)       = make_float2(v0, v1);
                *(float2*)(Cf + (size_t)(r0 + 8) * N + col) = make_float2(v2, v3);
            } else if (EPI == 2) {
                const float b0 = bias[col], b1 = bias[col + 1];
                *(float2*)(Cf + (size_t)r0 * N + col)       = make_float2(v0 + b0, v1 + b1);
                *(float2*)(Cf + (size_t)(r0 + 8) * N + col) = make_float2(v2 + b0, v3 + b1);
            } else if (EPI == 1) {
                const float b0 = bias[col], b1 = bias[col + 1];
                float s0 = selu_f(v0 + b0), s1 = selu_f(v1 + b1);
                float s2 = selu_f(v2 + b0), s3 = selu_f(v3 + b1);
                __half h0, l0, h1, l1;
                split_h(s0, h0, l0); split_h(s1, h1, l1);
                *(__half2*)(Ch + (size_t)r0 * N + col) = __halves2half2(h0, h1);
                *(__half2*)(Cl + (size_t)r0 * N + col) = __halves2half2(l0, l1);
                split_h(s2, h0, l0); split_h(s3, h1, l1);
                *(__half2*)(Ch + (size_t)(r0 + 8) * N + col) = __halves2half2(h0, h1);
                *(__half2*)(Cl + (size_t)(r0 + 8) * N + col) = __halves2half2(l0, l1);
            } else {   // EPI == 3: qkv, q region scaled by 1/8, split fp16
                const float sc = (col < DM) ? 0.125f : 1.0f;
                float s0 = v0 * sc, s1 = v1 * sc, s2 = v2 * sc, s3 = v3 * sc;
                __half h0, l0, h1, l1;
                split_h(s0, h0, l0); split_h(s1, h1, l1);
                *(__half2*)(Ch + (size_t)r0 * N + col) = __halves2half2(h0, h1);
                *(__half2*)(Cl + (size_t)r0 * N + col) = __halves2half2(l0, l1);
                split_h(s2, h0, l0); split_h(s3, h1, l1);
                *(__half2*)(Ch + (size_t)(r0 + 8) * N + col) = __halves2half2(h0, h1);
                *(__half2*)(Cl + (size_t)(r0 + 8) * N + col) = __halves2half2(l0, l1);
            }
        }
    }
}

// ---------------- weight transpose + split ----------------
__global__ void transpose_split_kernel(const float* __restrict__ W,
                                       __half* __restrict__ Th,
                                       __half* __restrict__ Tl,
                                       int K, int N, size_t in_lstride, size_t out_lstride)
{
    __shared__ float tile[32][33];
    const int l = blockIdx.z;
    const float* Wl = W + (size_t)l * in_lstride;
    const size_t ob = (size_t)l * out_lstride;
    const int n0 = blockIdx.x * 32, k0 = blockIdx.y * 32;
    for (int i = threadIdx.y; i < 32; i += 8)
        tile[i][threadIdx.x] = Wl[(size_t)(k0 + i) * N + n0 + threadIdx.x];
    __syncthreads();
    for (int i = threadIdx.y; i < 32; i += 8) {
        float v = tile[threadIdx.x][i];
        __half h, lo;
        split_h(v, h, lo);
        Th[ob + (size_t)(n0 + i) * K + k0 + threadIdx.x] = h;
        Tl[ob + (size_t)(n0 + i) * K + k0 + threadIdx.x] = lo;
    }
}

// ---------------- flash attention: split-fp16 HMMA, causal, online softmax ----------------
// 64x64 tiles, 128 threads / 4 warps; warp w owns q-rows [w*16, w*16+16).
__global__ __launch_bounds__(128, 2) void flash_kernel(
    const __half* __restrict__ qkvh, const __half* __restrict__ qkvl,
    float* __restrict__ o)
{
    __shared__ __half sQh[4096], sQl[4096], sKh[4096], sKl[4096], sVh[4096], sVl[4096];
    const uint32_t bQh = smem_u32(sQh), bQl = smem_u32(sQl);
    const uint32_t bKh = smem_u32(sKh), bKl = smem_u32(sKl);
    const uint32_t bVh = smem_u32(sVh), bVl = smem_u32(sVl);

    const int qt = gridDim.x - 1 - blockIdx.x;   // heavy tiles first
    const int bh = blockIdx.y;
    const int b  = bh >> 4, hd = bh & 15;
    const size_t qoff = (size_t)b * SL * QS + hd * DHD;

    const int t = threadIdx.x, lane = t & 31, w = t >> 5;

    // per-thread load geometry: 4 chunks; seg = t + i*128 -> row = seg>>3, chunk = seg&7
    int lrow[4]; uint32_t lso[4];
#pragma unroll
    for (int i = 0; i < 4; i++) {
        int seg = t + i * 128;
        lrow[i] = seg >> 3;
        int ch = seg & 7;
        lso[i] = (uint32_t)(lrow[i] * 128 + ((ch ^ (lrow[i] & 7)) << 4));
    }
    int lch[4];
#pragma unroll
    for (int i = 0; i < 4; i++) lch[i] = (t + i * 128) & 7;

    // load Q tile (hi/lo)
#pragma unroll
    for (int i = 0; i < 4; i++) {
        const size_t g = qoff + (size_t)(qt * 64 + lrow[i]) * QS + lch[i] * 8;
        CP_ASYNC16(bQh + lso[i], qkvh + g);
        CP_ASYNC16(bQl + lso[i], qkvl + g);
    }
    CP_COMMIT(); CP_WAIT(0);
    __syncthreads();

    // Q fragments (fixed for whole kt loop)
    uint32_t qfh[4][4], qfl[4][4];
#pragma unroll
    for (int ks = 0; ks < 4; ks++) {
        const int r = w * 16 + (lane & 7) + ((lane >> 3) & 1) * 8;
        const int c = ks * 16 + (lane >> 4) * 8;
        const uint32_t off = fa_off(r, c);
        ldsm4(qfh[ks], bQh + off);
        ldsm4(qfl[ks], bQl + off);
    }

    float acc_o[8][4];
#pragma unroll
    for (int n = 0; n < 8; n++)
#pragma unroll
        for (int e = 0; e < 4; e++) acc_o[n][e] = 0.f;
    float m0 = -1e30f, m1 = -1e30f, l0 = 0.f, l1 = 0.f;

    const int gr0 = qt * 64 + w * 16 + (lane >> 2);   // global q row (part 0)
    const int gr1 = gr0 + 8;

    for (int kt = 0; kt <= qt; kt++) {
        __syncthreads();   // previous PV reads done before overwrite
#pragma unroll
        for (int i = 0; i < 4; i++) {
            const size_t gk = qoff + DM     + (size_t)(kt * 64 + lrow[i]) * QS + lch[i] * 8;
            const size_t gv = qoff + 2 * DM + (size_t)(kt * 64 + lrow[i]) * QS + lch[i] * 8;
            CP_ASYNC16(bKh + lso[i], qkvh + gk);
            CP_ASYNC16(bKl + lso[i], qkvl + gk);
            CP_ASYNC16(bVh + lso[i], qkvh + gv);
            CP_ASYNC16(bVl + lso[i], qkvl + gv);
        }
        CP_COMMIT(); CP_WAIT(0);
        __syncthreads();

        // ---- S = Q K^T (split, 3 passes) ----
        float s_[8][4];
#pragma unroll
        for (int n = 0; n < 8; n++)
#pragma unroll
            for (int e = 0; e < 4; e++) s_[n][e] = 0.f;

#pragma unroll
        for (int ks = 0; ks < 4; ks++) {
            const int k0 = ks * 16;
            uint32_t bhf[8][2], blf[8][2];
#pragma unroll
            for (int g = 0; g < 4; g++) {
                const int r = g * 16 + (lane & 7) + (lane >> 4) * 8;
                const int c = k0 + ((lane >> 3) & 1) * 8;
                const uint32_t off = fa_off(r, c);
                uint32_t tmp[4];
                ldsm4(tmp, bKh + off);
                bhf[g*2][0] = tmp[0]; bhf[g*2][1] = tmp[1];
                bhf[g*2+1][0] = tmp[2]; bhf[g*2+1][1] = tmp[3];
                ldsm4(tmp, bKl + off);
                blf[g*2][0] = tmp[0]; blf[g*2][1] = tmp[1];
                blf[g*2+1][0] = tmp[2]; blf[g*2+1][1] = tmp[3];
            }
#pragma unroll
            for (int n = 0; n < 8; n++) mma16816(s_[n], qfh[ks], bhf[n]);
#pragma unroll
            for (int n = 0; n < 8; n++) mma16816(s_[n], qfh[ks], blf[n]);
#pragma unroll
            for (int n = 0; n < 8; n++) mma16816(s_[n], qfl[ks], bhf[n]);
        }

        // ---- causal mask on diagonal tile ----
        if (kt == qt) {
#pragma unroll
            for (int n = 0; n < 8; n++) {
                const int c = kt * 64 + n * 8 + (lane & 3) * 2;
                if (c     > gr0) s_[n][0] = -1e30f;
                if (c + 1 > gr0) s_[n][1] = -1e30f;
                if (c     > gr1) s_[n][2] = -1e30f;
                if (c + 1 > gr1) s_[n][3] = -1e30f;
            }
        }

        // ---- online softmax ----
        float mx0 = -1e30f, mx1 = -1e30f;
#pragma unroll
        for (int n = 0; n < 8; n++) {
            mx0 = fmaxf(mx0, fmaxf(s_[n][0], s_[n][1]));
            mx1 = fmaxf(mx1, fmaxf(s_[n][2], s_[n][3]));
        }
        mx0 = fmaxf(mx0, __shfl_xor_sync(0xffffffffu, mx0, 1));
        mx0 = fmaxf(mx0, __shfl_xor_sync(0xffffffffu, mx0, 2));
        mx1 = fmaxf(mx1, __shfl_xor_sync(0xffffffffu, mx1, 1));
        mx1 = fmaxf(mx1, __shfl_xor_sync(0xffffffffu, mx1, 2));
        const float mn0 = fmaxf(m0, mx0), mn1 = fmaxf(m1, mx1);
        const float sc0 = __expf(m0 - mn0), sc1 = __expf(m1 - mn1);
        m0 = mn0; m1 = mn1;

        uint32_t pah[4][4], pal[4][4];
        float rs0 = 0.f, rs1 = 0.f;
#pragma unroll
        for (int n = 0; n < 8; n++) {
            float p0 = __expf(s_[n][0] - mn0);
            float p1 = __expf(s_[n][1] - mn0);
            float p2 = __expf(s_[n][2] - mn1);
            float p3 = __expf(s_[n][3] - mn1);
            rs0 += p0 + p1; rs1 += p2 + p3;
            __half h0, e0, h1, e1, h2, e2, h3, e3;
            split_h(p0, h0, e0); split_h(p1, h1, e1);
            split_h(p2, h2, e2); split_h(p3, h3, e3);
            const int kc = n >> 1, wh = (n & 1) * 2;
            pah[kc][wh    ] = ((uint32_t)*(uint16_t*)&h1 << 16) | *(uint16_t*)&h0;
            pah[kc][wh + 1] = ((uint32_t)*(uint16_t*)&h3 << 16) | *(uint16_t*)&h2;
            pal[kc][wh    ] = ((uint32_t)*(uint16_t*)&e1 << 16) | *(uint16_t*)&e0;
            pal[kc][wh + 1] = ((uint32_t)*(uint16_t*)&e3 << 16) | *(uint16_t*)&e2;
        }
        rs0 += __shfl_xor_sync(0xffffffffu, rs0, 1);
        rs0 += __shfl_xor_sync(0xffffffffu, rs0, 2);
        rs1 += __shfl_xor_sync(0xffffffffu, rs1, 1);
        rs1 += __shfl_xor_sync(0xffffffffu, rs1, 2);
        l0 = l0 * sc0 + rs0;
        l1 = l1 * sc1 + rs1;

#pragma unroll
        for (int n = 0; n < 8; n++) {
            acc_o[n][0] *= sc0; acc_o[n][1] *= sc0;
            acc_o[n][2] *= sc1; acc_o[n][3] *= sc1;
        }

        // ---- O += P V (split, 3 passes) ----
#pragma unroll
        for (int kc = 0; kc < 4; kc++) {
#pragma unroll
            for (int g = 0; g < 4; g++) {
                const int r = kc * 16 + (lane & 7) + ((lane >> 3) & 1) * 8;
                const int c = g * 16 + (lane >> 4) * 8;
                const uint32_t off = fa_off(r, c);
                uint32_t tvh[4], tvl[4];
                ldsm4t(tvh, bVh + off);
                ldsm4t(tvl, bVl + off);
                mma16816(acc_o[2*g],   pah[kc], tvh);
                mma16816(acc_o[2*g+1], pah[kc], tvh + 2);
                mma16816(acc_o[2*g],   pah[kc], tvl);
                mma16816(acc_o[2*g+1], pah[kc], tvl + 2);
                mma16816(acc_o[2*g],   pal[kc], tvh);
                mma16816(acc_o[2*g+1], pal[kc], tvh + 2);
            }
        }
    }

    // ---- epilogue ----
    const float i0 = 1.f / l0, i1 = 1.f / l1;
    float* ob = o + (size_t)b * SL * DM + hd * DHD;
#pragma unroll
    for (int n = 0; n < 8; n++) {
        const int c = n * 8 + (lane & 3) * 2;
        *(float2*)(ob + (size_t)gr0 * DM + c) = make_float2(acc_o[n][0] * i0, acc_o[n][1] * i0);
        *(float2*)(ob + (size_t)gr1 * DM + c) = make_float2(acc_o[n][2] * i1, acc_o[n][3] * i1);
    }
}

// ---------------- out = LayerNorm(a + r) * g + b  (+ split) ----------------
__global__ void resid_ln_kernel(const float* __restrict__ a, const float* __restrict__ r,
                                const float* __restrict__ g, const float* __restrict__ bb,
                                float* __restrict__ out)
{
    int row = blockIdx.x;
    int t = threadIdx.x;
    const float* pa = a + (size_t)row * DM;
    const float* pr = r + (size_t)row * DM;
    float v[4];
    float s = 0.f, s2 = 0.f;
#pragma unroll
    for (int i = 0; i < 4; i++) {
        float x = pa[t + i * 256] + pr[t + i * 256];
        v[i] = x; s += x; s2 += x * x;
    }
#pragma unroll
    for (int off = 16; off > 0; off >>= 1) {
        s  += __shfl_down_sync(0xffffffffu, s,  off);
        s2 += __shfl_down_sync(0xffffffffu, s2, off);
    }
    __shared__ float ws[8], ws2[8];
    __shared__ float sm_mean, sm_rstd;
    int w = t >> 5, lane = t & 31;
    if (lane == 0) { ws[w] = s; ws2[w] = s2; }
    __syncthreads();
    if (t == 0) {
        float S = 0.f, S2 = 0.f;
#pragma unroll
        for (int i = 0; i < 8; i++) { S += ws[i]; S2 += ws2[i]; }
        float mean = S * (1.f / DM);
        float var  = S2 * (1.f / DM) - mean * mean;
        sm_mean = mean;
        sm_rstd = rsqrtf(var + 1e-5f);
    }
    __syncthreads();
    float mean = sm_mean, rstd = sm_rstd;
#pragma unroll
    for (int i = 0; i < 4; i++) {
        int col = t + i * 256;
        float y = (v[i] - mean) * rstd * g[col] + bb[col];
        size_t idx = (size_t)row * DM + col;
        out[idx] = y;
        split_h(y, g_h_hi[idx], g_h_lo[idx]);
    }
}

__global__ void copy_out_kernel(float* __restrict__ out) {
    int i = blockIdx.x * 256 + threadIdx.x;
    out[i] = g_h[i];
}

// ---------------- launch ----------------
extern "C" void kernel_launch(void* const* d_in, const int* in_sizes, int n_in,
                              void* d_out, int out_size)
{
    const float* x    = (const float*)d_in[0];
    const float* pe   = (const float*)d_in[1];
    const float* wq   = (const float*)d_in[2];
    const float* wk   = (const float*)d_in[3];
    const float* wv   = (const float*)d_in[4];
    const float* ln1g = (const float*)d_in[5];
    const float* ln1b = (const float*)d_in[6];
    const float* w1   = (const float*)d_in[7];
    const float* b1   = (const float*)d_in[8];
    const float* w2   = (const float*)d_in[9];
    const float* b2   = (const float*)d_in[10];
    const float* ln2g = (const float*)d_in[11];
    const float* ln2b = (const float*)d_in[12];

    float *ph, *po;
    cudaGetSymbolAddress((void**)&ph, g_h);
    cudaGetSymbolAddress((void**)&po, g_o);
    __half *phh, *phl, *pfh, *pfl, *pqh, *pql;
    cudaGetSymbolAddress((void**)&phh, g_h_hi);
    cudaGetSymbolAddress((void**)&phl, g_h_lo);
    cudaGetSymbolAddress((void**)&pfh, g_ff_hi);
    cudaGetSymbolAddress((void**)&pfl, g_ff_lo);
    cudaGetSymbolAddress((void**)&pqh, g_qkv_hi);
    cudaGetSymbolAddress((void**)&pql, g_qkv_lo);
    __half *wqkvh, *wqkvl, *w1h, *w1l, *w2h, *w2l;
    cudaGetSymbolAddress((void**)&wqkvh, g_wqkv_hi); cudaGetSymbolAddress((void**)&wqkvl, g_wqkv_lo);
    cudaGetSymbolAddress((void**)&w1h, g_w1_hi);     cudaGetSymbolAddress((void**)&w1l, g_w1_lo);
    cudaGetSymbolAddress((void**)&w2h, g_w2_hi);     cudaGetSymbolAddress((void**)&w2l, g_w2_lo);

    cudaFuncSetAttribute(mm_kernel<1>, cudaFuncAttributeMaxDynamicSharedMemorySize, MM_SMEM);
    cudaFuncSetAttribute(mm_kernel<2>, cudaFuncAttributeMaxDynamicSharedMemorySize, MM_SMEM);
    cudaFuncSetAttribute(mm_kernel<3>, cudaFuncAttributeMaxDynamicSharedMemorySize, MM_SMEM);

    // pre-transpose + split all weights (qkv fused [3072,1024] per layer)
    dim3 tb(32, 8);
    transpose_split_kernel<<<dim3(DM/32,  DM/32,  NLAYER), tb>>>(
        wq, wqkvh,                    wqkvl,                    DM, DM,
        (size_t)DM*DM, (size_t)QS*DM);
    transpose_split_kernel<<<dim3(DM/32,  DM/32,  NLAYER), tb>>>(
        wk, wqkvh + (size_t)DM*DM,    wqkvl + (size_t)DM*DM,    DM, DM,
        (size_t)DM*DM, (size_t)QS*DM);
    transpose_split_kernel<<<dim3(DM/32,  DM/32,  NLAYER), tb>>>(
        wv, wqkvh + (size_t)2*DM*DM,  wqkvl + (size_t)2*DM*DM,  DM, DM,
        (size_t)DM*DM, (size_t)QS*DM);
    transpose_split_kernel<<<dim3(DFF/32, DM/32,  NLAYER), tb>>>(
        w1, w1h, w1l, DM, DFF, (size_t)DM*DFF, (size_t)DM*DFF);
    transpose_split_kernel<<<dim3(DM/32,  DFF/32, NLAYER), tb>>>(
        w2, w2h, w2l, DFF, DM, (size_t)DM*DFF, (size_t)DM*DFF);

    add_pe_kernel<<<NTOK * DM / 256, 256>>>(x, pe);

    for (int l = 0; l < NLAYER; l++) {
        const size_t woq = (size_t)l * QS * DM;
        const size_t wo1 = (size_t)l * DM * DFF;

        // fused QKV -> split fp16 (q scaled by 1/8)
        mm_kernel<3><<<dim3(QS / 128, NTOK / 128), 256, MM_SMEM>>>(
            phh, phl, wqkvh + woq, wqkvl + woq, nullptr,
            nullptr, pqh, pql, NTOK, QS, DM);

        flash_kernel<<<dim3(SL / 64, NB * NH), 128>>>(pqh, pql, po);

        resid_ln_kernel<<<NTOK, 256>>>(ph, po, ln1g + (size_t)l * DM, ln1b + (size_t)l * DM, ph);

        mm_kernel<1><<<dim3(DFF / 128, NTOK / 128), 256, MM_SMEM>>>(
            phh, phl, w1h + wo1, w1l + wo1, b1 + (size_t)l * DFF,
            nullptr, pfh, pfl, NTOK, DFF, DM);
        mm_kernel<2><<<dim3(DM / 128, NTOK / 128), 256, MM_SMEM>>>(
            pfh, pfl, w2h + wo1, w2l + wo1, b2 + (size_t)l * DM,
            po, nullptr, nullptr, NTOK, DM, DFF);

        resid_ln_kernel<<<NTOK, 256>>>(ph, po, ln2g + (size_t)l * DM, ln2b + (size_t)l * DM, ph);
    }

    copy_out_kernel<<<NTOK * DM / 256, 256>>>((float*)d_out);
}

// round 7
// speedup vs baseline: 2.9029x; 1.0320x over previous
#include <cuda_runtime.h>
#include <cuda_fp16.h>
#include <cstdint>
#include <math.h>

#define NB 2
#define SL 2048
#define DM 1024
#define NH 16
#define DHD 64
#define NLAYER 8
#define DFF 4096
#define NTOK (NB*SL)
#define QS (3*DM)          // fused qkv row stride

// ---------------- scratch (static device globals; no allocs) ----------------
__device__ __align__(256) float g_h  [(size_t)NTOK*DM];
__device__ __align__(256) float g_o  [(size_t)NTOK*DM];

// split-fp16 activations
__device__ __align__(256) __half g_h_hi[(size_t)NTOK*DM];
__device__ __align__(256) __half g_h_lo[(size_t)NTOK*DM];
__device__ __align__(256) __half g_ff_hi[(size_t)NTOK*DFF];
__device__ __align__(256) __half g_ff_lo[(size_t)NTOK*DFF];
__device__ __align__(256) __half g_qkv_hi[(size_t)NTOK*QS];
__device__ __align__(256) __half g_qkv_lo[(size_t)NTOK*QS];

// transposed + split weights: [N, K] fp16 hi/lo per layer (qkv fused: [3072,1024])
__device__ __align__(256) __half g_wqkv_hi[(size_t)NLAYER*QS*DM], g_wqkv_lo[(size_t)NLAYER*QS*DM];
__device__ __align__(256) __half g_w1_hi[(size_t)NLAYER*DM*DFF],  g_w1_lo[(size_t)NLAYER*DM*DFF];
__device__ __align__(256) __half g_w2_hi[(size_t)NLAYER*DM*DFF],  g_w2_lo[(size_t)NLAYER*DM*DFF];

// ---------------- helpers ----------------
__device__ __forceinline__ uint32_t smem_u32(const void* p) {
    uint32_t a;
    asm("{ .reg .u64 t; cvta.to.shared.u64 t, %1; cvt.u32.u64 %0, t; }" : "=r"(a) : "l"(p));
    return a;
}
#define CP_ASYNC16(dst, src) asm volatile("cp.async.cg.shared.global [%0], [%1], 16;" :: "r"(dst), "l"(src))
#define CP_COMMIT()          asm volatile("cp.async.commit_group;" ::: "memory")
#define CP_WAIT(n)           asm volatile("cp.async.wait_group %0;" :: "n"(n) : "memory")

__device__ __forceinline__ void ldsm4(uint32_t* r, uint32_t a) {
    asm volatile("ldmatrix.sync.aligned.m8n8.x4.shared.b16 {%0,%1,%2,%3}, [%4];"
        : "=r"(r[0]), "=r"(r[1]), "=r"(r[2]), "=r"(r[3]) : "r"(a));
}
__device__ __forceinline__ void ldsm4t(uint32_t* r, uint32_t a) {
    asm volatile("ldmatrix.sync.aligned.m8n8.x4.trans.shared.b16 {%0,%1,%2,%3}, [%4];"
        : "=r"(r[0]), "=r"(r[1]), "=r"(r[2]), "=r"(r[3]) : "r"(a));
}
__device__ __forceinline__ void mma16816(float* c, const uint32_t* a, const uint32_t* b) {
    asm volatile("mma.sync.aligned.m16n8k16.row.col.f32.f16.f16.f32 "
        "{%0,%1,%2,%3}, {%4,%5,%6,%7}, {%8,%9}, {%0,%1,%2,%3};"
        : "+f"(c[0]), "+f"(c[1]), "+f"(c[2]), "+f"(c[3])
        : "r"(a[0]), "r"(a[1]), "r"(a[2]), "r"(a[3]), "r"(b[0]), "r"(b[1]));
}
// f16-accumulate variant (corrections): D,C are 2 regs of half2
__device__ __forceinline__ void mma16816h(uint32_t* c, const uint32_t* a, const uint32_t* b) {
    asm volatile("mma.sync.aligned.m16n8k16.row.col.f16.f16.f16.f16 "
        "{%0,%1}, {%2,%3,%4,%5}, {%6,%7}, {%0,%1};"
        : "+r"(c[0]), "+r"(c[1])
        : "r"(a[0]), "r"(a[1]), "r"(a[2]), "r"(a[3]), "r"(b[0]), "r"(b[1]));
}
__device__ __forceinline__ void split_h(float v, __half& hi, __half& lo) {
    hi = __float2half_rn(v);
    lo = __float2half_rn(v - __half2float(hi));
}
__device__ __forceinline__ float selu_f(float v) {
    return 1.0507009873554805f * (v > 0.f ? v : 1.6732632423543772f * expm1f(v));
}

// GEMM smem tile: 128 rows x 32 fp16 = 64B/row, 4 x 16B chunks; chunk ^= (row>>1)&3
__device__ __forceinline__ uint32_t tile_off(int row, int colElem) {
    return (uint32_t)(row * 64 + ((((colElem >> 3) & 3) ^ ((row >> 1) & 3)) << 4));
}
// flash smem tile: 64 rows x 64 fp16 = 128B/row, 8 x 16B chunks; chunk ^= row&7
__device__ __forceinline__ uint32_t fa_off(int row, int colElem) {
    return (uint32_t)(row * 128 + ((((colElem >> 3) & 7) ^ (row & 7)) << 4));
}

// ---------------- h = x + pe (+ split) ----------------
__global__ void add_pe_kernel(const float* __restrict__ x, const float* __restrict__ pe) {
    int i = blockIdx.x * 256 + threadIdx.x;
    float v = x[i] + pe[i & (SL*DM - 1)];
    g_h[i] = v;
    split_h(v, g_h_hi[i], g_h_lo[i]);
}

// ---------------- fused weight transpose + split (ALL weights, one launch) ----------------
// Tiles of 32x32. Segment decode:
//   [0, 24576): wq/wk/wv  (each: 8 layers x 1024 tiles of a 1024x1024 matrix)
//   [24576, 57344): w1    (8 layers x 4096 tiles of 1024x4096)
//   [57344, 90112): w2    (8 layers x 4096 tiles of 4096x1024)
#define TR_GRID 90112
__global__ __launch_bounds__(256) void transpose_split_all_kernel(
    const float* __restrict__ wq, const float* __restrict__ wk, const float* __restrict__ wv,
    const float* __restrict__ w1, const float* __restrict__ w2)
{
    __shared__ float tile[32][33];
    const int bid = blockIdx.x;
    const int t = threadIdx.x;

    const float* src; __half* dh; __half* dl;
    int K, N, n0, k0;
    if (bid < 24576) {
        const int which = bid >> 13;            // /8192
        const int r = bid & 8191;
        const int l = r >> 10;
        const int tl = r & 1023;
        K = DM; N = DM;
        n0 = (tl & 31) * 32; k0 = (tl >> 5) * 32;
        src = (which == 0 ? wq : which == 1 ? wk : wv) + (size_t)l * DM * DM;
        const size_t doff = (size_t)l * QS * DM + (size_t)which * DM * DM;
        dh = g_wqkv_hi + doff; dl = g_wqkv_lo + doff;
    } else if (bid < 57344) {
        const int r = bid - 24576;
        const int l = r >> 12;
        const int tl = r & 4095;
        K = DM; N = DFF;
        n0 = (tl & 127) * 32; k0 = (tl >> 7) * 32;
        src = w1 + (size_t)l * DM * DFF;
        dh = g_w1_hi + (size_t)l * DM * DFF; dl = g_w1_lo + (size_t)l * DM * DFF;
    } else {
        const int r = bid - 57344;
        const int l = r >> 12;
        const int tl = r & 4095;
        K = DFF; N = DM;
        n0 = (tl & 31) * 32; k0 = (tl >> 5) * 32;
        src = w2 + (size_t)l * DM * DFF;
        dh = g_w2_hi + (size_t)l * DM * DFF; dl = g_w2_lo + (size_t)l * DM * DFF;
    }

    const int lx = t & 31, ly = t >> 5;
#pragma unroll
    for (int i = 0; i < 4; i++) {
        const int kr = ly + i * 8;
        tile[kr][lx] = src[(size_t)(k0 + kr) * N + n0 + lx];
    }
    __syncthreads();

    const int kp = t & 15;
#pragma unroll
    for (int p = 0; p < 2; p++) {
        const int n = (t >> 4) + p * 16;
        const float v0 = tile[2 * kp][n], v1 = tile[2 * kp + 1][n];
        __half h0, l0h, h1, l1h;
        split_h(v0, h0, l0h); split_h(v1, h1, l1h);
        const size_t o = (size_t)(n0 + n) * K + k0 + 2 * kp;
        *(__half2*)(dh + o) = __halves2half2(h0, h1);
        *(__half2*)(dl + o) = __halves2half2(l0h, l1h);
    }
}

// ---------------- split-fp16 GEMM via mma.sync (HMMA) ----------------
// C[M,N] = act( (Ah+Al)[M,K] @ (Bh+Bl)[N,K]^T + bias )
// pass1 Ah*Bh -> fp32 acc; pass2 Ah*Bl + pass3 Al*Bh -> shared f16 acc (corrections)
// EPI: 0 = fp32 out; 1 = bias+SELU -> fp16 hi/lo; 2 = bias -> fp32; 3 = qkv split fp16 (q scaled 0.125)
#define MM_STAGE 32768           // Ah 8K | Al 8K | Bh 8K | Bl 8K
#define MM_NSTG  4
#define MM_SMEM  (MM_NSTG*MM_STAGE)

template<int EPI>
__global__ __launch_bounds__(256, 1) void mm_kernel(
    const __half* __restrict__ Ah, const __half* __restrict__ Al,
    const __half* __restrict__ Bh, const __half* __restrict__ Bl,
    const float* __restrict__ bias,
    float* __restrict__ Cf, __half* __restrict__ Ch, __half* __restrict__ Cl,
    int M, int N, int K)
{
    extern __shared__ char smem[];
    const uint32_t sb = smem_u32(smem);
    const int t = threadIdx.x, lane = t & 31, wid = t >> 5;
    const int n0 = blockIdx.x * 128, m0 = blockIdx.y * 128;
    const int wm = (wid >> 1) * 32, wn = (wid & 1) * 64;

    const int row0 = t >> 2, ch0 = t & 3;
    const uint32_t so0 = tile_off(row0, ch0 * 8);

    float acc[2][8][4];
    uint32_t acc16[2][8][2];
#pragma unroll
    for (int mt = 0; mt < 2; mt++)
#pragma unroll
        for (int nt = 0; nt < 8; nt++) {
#pragma unroll
            for (int e = 0; e < 4; e++) acc[mt][nt][e] = 0.f;
            acc16[mt][nt][0] = 0u; acc16[mt][nt][1] = 0u;
        }

    const int nst = K >> 5;

    auto LOAD_STAGE = [&](int stage, int kt) {
        const uint32_t sa = sb + stage * MM_STAGE;
        const size_t kof = (size_t)kt * 32 + ch0 * 8;
#pragma unroll
        for (int i = 0; i < 2; i++) {
            const int row = row0 + i * 64;
            const uint32_t so = sa + so0 + i * 4096;
            const size_t ga = (size_t)(m0 + row) * K + kof;
            const size_t gb = (size_t)(n0 + row) * K + kof;
            CP_ASYNC16(so,         Ah + ga);
            CP_ASYNC16(so +  8192, Al + ga);
            CP_ASYNC16(so + 16384, Bh + gb);
            CP_ASYNC16(so + 24576, Bl + gb);
        }
    };

    auto COMPUTE = [&](int stage) {
        const uint32_t sa = sb + stage * MM_STAGE;
#pragma unroll
        for (int ks = 0; ks < 2; ks++) {
            const int k0 = ks * 16;
            uint32_t ahf[2][4], alf[2][4], bhf[8][2], blf[8][2];
#pragma unroll
            for (int mt = 0; mt < 2; mt++) {
                const int r = wm + mt * 16 + (lane & 7) + ((lane >> 3) & 1) * 8;
                const int c = k0 + (lane >> 4) * 8;
                const uint32_t off = tile_off(r, c);
                ldsm4(ahf[mt], sa + off);
                ldsm4(alf[mt], sa + 8192 + off);
            }
#pragma unroll
            for (int g = 0; g < 4; g++) {
                const int r = wn + g * 16 + (lane & 7) + (lane >> 4) * 8;
                const int c = k0 + ((lane >> 3) & 1) * 8;
                const uint32_t off = tile_off(r, c);
                uint32_t tmp[4];
                ldsm4(tmp, sa + 16384 + off);
                bhf[g*2][0] = tmp[0]; bhf[g*2][1] = tmp[1];
                bhf[g*2+1][0] = tmp[2]; bhf[g*2+1][1] = tmp[3];
                ldsm4(tmp, sa + 24576 + off);
                blf[g*2][0] = tmp[0]; blf[g*2][1] = tmp[1];
                blf[g*2+1][0] = tmp[2]; blf[g*2+1][1] = tmp[3];
            }
            // main product: fp32 accumulate
#pragma unroll
            for (int mt = 0; mt < 2; mt++)
#pragma unroll
                for (int nt = 0; nt < 8; nt++) mma16816(acc[mt][nt], ahf[mt], bhf[nt]);
            // corrections: f16 accumulate (values ~2^-11 of output)
#pragma unroll
            for (int mt = 0; mt < 2; mt++)
#pragma unroll
                for (int nt = 0; nt < 8; nt++) mma16816h(acc16[mt][nt], ahf[mt], blf[nt]);
#pragma unroll
            for (int mt = 0; mt < 2; mt++)
#pragma unroll
                for (int nt = 0; nt < 8; nt++) mma16816h(acc16[mt][nt], alf[mt], bhf[nt]);
        }
    };

    LOAD_STAGE(0, 0); CP_COMMIT();
    LOAD_STAGE(1, 1); CP_COMMIT();
    LOAD_STAGE(2, 2); CP_COMMIT();

#pragma unroll 1
    for (int kt = 0; kt < nst; kt++) {
        if (kt + 3 < nst) { CP_WAIT(2); } else { CP_WAIT(0); }
        __syncthreads();
        if (kt + 3 < nst) { LOAD_STAGE((kt + 3) & 3, kt + 3); CP_COMMIT(); }
        COMPUTE(kt & 3);
    }

#pragma unroll
    for (int mt = 0; mt < 2; mt++) {
        const int r0 = m0 + wm + mt * 16 + (lane >> 2);
#pragma unroll
        for (int nt = 0; nt < 8; nt++) {
            const int col = n0 + wn + nt * 8 + (lane & 3) * 2;
            const float2 c01 = __half22float2(*(__half2*)&acc16[mt][nt][0]);
            const float2 c23 = __half22float2(*(__half2*)&acc16[mt][nt][1]);
            float v0 = acc[mt][nt][0] + c01.x, v1 = acc[mt][nt][1] + c01.y;
            float v2 = acc[mt][nt][2] + c23.x, v3 = acc[mt][nt][3] + c23.y;
            if (EPI == 0) {
                *(float2*)(Cf + (size_t)r0 * N + col)       = make_float2(v0, v1);
                *(float2*)(Cf + (size_t)(r0 + 8) * N + col) = make_float2(v2, v3);
            } else if (EPI == 2) {
                const float b0 = bias[col], b1 = bias[col + 1];
                *(float2*)(Cf + (size_t)r0 * N + col)       = make_float2(v0 + b0, v1 + b1);
                *(float2*)(Cf + (size_t)(r0 + 8) * N + col) = make_float2(v2 + b0, v3 + b1);
            } else if (EPI == 1) {
                const float b0 = bias[col], b1 = bias[col + 1];
                float s0 = selu_f(v0 + b0), s1 = selu_f(v1 + b1);
                float s2 = selu_f(v2 + b0), s3 = selu_f(v3 + b1);
                __half h0, l0, h1, l1;
                split_h(s0, h0, l0); split_h(s1, h1, l1);
                *(__half2*)(Ch + (size_t)r0 * N + col) = __halves2half2(h0, h1);
                *(__half2*)(Cl + (size_t)r0 * N + col) = __halves2half2(l0, l1);
                split_h(s2, h0, l0); split_h(s3, h1, l1);
                *(__half2*)(Ch + (size_t)(r0 + 8) * N + col) = __halves2half2(h0, h1);
                *(__half2*)(Cl + (size_t)(r0 + 8) * N + col) = __halves2half2(l0, l1);
            } else {   // EPI == 3: qkv, q region scaled by 1/8, split fp16
                const float sc = (col < DM) ? 0.125f : 1.0f;
                float s0 = v0 * sc, s1 = v1 * sc, s2 = v2 * sc, s3 = v3 * sc;
                __half h0, l0, h1, l1;
                split_h(s0, h0, l0); split_h(s1, h1, l1);
                *(__half2*)(Ch + (size_t)r0 * N + col) = __halves2half2(h0, h1);
                *(__half2*)(Cl + (size_t)r0 * N + col) = __halves2half2(l0, l1);
                split_h(s2, h0, l0); split_h(s3, h1, l1);
                *(__half2*)(Ch + (size_t)(r0 + 8) * N + col) = __halves2half2(h0, h1);
                *(__half2*)(Cl + (size_t)(r0 + 8) * N + col) = __halves2half2(l0, l1);
            }
        }
    }
}

// ---------------- flash attention: split-fp16 HMMA, causal, online softmax ----------------
// 64x64 tiles, 128 threads / 4 warps; warp w owns q-rows [w*16, w*16+16).
__global__ __launch_bounds__(128, 2) void flash_kernel(
    const __half* __restrict__ qkvh, const __half* __restrict__ qkvl,
    float* __restrict__ o)
{
    __shared__ __half sQh[4096], sQl[4096], sKh[4096], sKl[4096], sVh[4096], sVl[4096];
    const uint32_t bQh = smem_u32(sQh), bQl = smem_u32(sQl);
    const uint32_t bKh = smem_u32(sKh), bKl = smem_u32(sKl);
    const uint32_t bVh = smem_u32(sVh), bVl = smem_u32(sVl);

    const int qt = gridDim.x - 1 - blockIdx.x;   // heavy tiles first
    const int bh = blockIdx.y;
    const int b  = bh >> 4, hd = bh & 15;
    const size_t qoff = (size_t)b * SL * QS + hd * DHD;

    const int t = threadIdx.x, lane = t & 31, w = t >> 5;

    int lrow[4]; uint32_t lso[4]; int lch[4];
#pragma unroll
    for (int i = 0; i < 4; i++) {
        int seg = t + i * 128;
        lrow[i] = seg >> 3;
        int ch = seg & 7;
        lso[i] = (uint32_t)(lrow[i] * 128 + ((ch ^ (lrow[i] & 7)) << 4));
        lch[i] = ch;
    }

#pragma unroll
    for (int i = 0; i < 4; i++) {
        const size_t g = qoff + (size_t)(qt * 64 + lrow[i]) * QS + lch[i] * 8;
        CP_ASYNC16(bQh + lso[i], qkvh + g);
        CP_ASYNC16(bQl + lso[i], qkvl + g);
    }
    CP_COMMIT(); CP_WAIT(0);
    __syncthreads();

    uint32_t qfh[4][4], qfl[4][4];
#pragma unroll
    for (int ks = 0; ks < 4; ks++) {
        const int r = w * 16 + (lane & 7) + ((lane >> 3) & 1) * 8;
        const int c = ks * 16 + (lane >> 4) * 8;
        const uint32_t off = fa_off(r, c);
        ldsm4(qfh[ks], bQh + off);
        ldsm4(qfl[ks], bQl + off);
    }

    float acc_o[8][4];
#pragma unroll
    for (int n = 0; n < 8; n++)
#pragma unroll
        for (int e = 0; e < 4; e++) acc_o[n][e] = 0.f;
    float m0 = -1e30f, m1 = -1e30f, l0 = 0.f, l1 = 0.f;

    const int gr0 = qt * 64 + w * 16 + (lane >> 2);
    const int gr1 = gr0 + 8;

    for (int kt = 0; kt <= qt; kt++) {
        __syncthreads();
#pragma unroll
        for (int i = 0; i < 4; i++) {
            const size_t gk = qoff + DM     + (size_t)(kt * 64 + lrow[i]) * QS + lch[i] * 8;
            const size_t gv = qoff + 2 * DM + (size_t)(kt * 64 + lrow[i]) * QS + lch[i] * 8;
            CP_ASYNC16(bKh + lso[i], qkvh + gk);
            CP_ASYNC16(bKl + lso[i], qkvl + gk);
            CP_ASYNC16(bVh + lso[i], qkvh + gv);
            CP_ASYNC16(bVl + lso[i], qkvl + gv);
        }
        CP_COMMIT(); CP_WAIT(0);
        __syncthreads();

        float s_[8][4];
#pragma unroll
        for (int n = 0; n < 8; n++)
#pragma unroll
            for (int e = 0; e < 4; e++) s_[n][e] = 0.f;

#pragma unroll
        for (int ks = 0; ks < 4; ks++) {
            const int k0 = ks * 16;
            uint32_t bhf[8][2], blf[8][2];
#pragma unroll
            for (int g = 0; g < 4; g++) {
                const int r = g * 16 + (lane & 7) + (lane >> 4) * 8;
                const int c = k0 + ((lane >> 3) & 1) * 8;
                const uint32_t off = fa_off(r, c);
                uint32_t tmp[4];
                ldsm4(tmp, bKh + off);
                bhf[g*2][0] = tmp[0]; bhf[g*2][1] = tmp[1];
                bhf[g*2+1][0] = tmp[2]; bhf[g*2+1][1] = tmp[3];
                ldsm4(tmp, bKl + off);
                blf[g*2][0] = tmp[0]; blf[g*2][1] = tmp[1];
                blf[g*2+1][0] = tmp[2]; blf[g*2+1][1] = tmp[3];
            }
#pragma unroll
            for (int n = 0; n < 8; n++) mma16816(s_[n], qfh[ks], bhf[n]);
#pragma unroll
            for (int n = 0; n < 8; n++) mma16816(s_[n], qfh[ks], blf[n]);
#pragma unroll
            for (int n = 0; n < 8; n++) mma16816(s_[n], qfl[ks], bhf[n]);
        }

        if (kt == qt) {
#pragma unroll
            for (int n = 0; n < 8; n++) {
                const int c = kt * 64 + n * 8 + (lane & 3) * 2;
                if (c     > gr0) s_[n][0] = -1e30f;
                if (c + 1 > gr0) s_[n][1] = -1e30f;
                if (c     > gr1) s_[n][2] = -1e30f;
                if (c + 1 > gr1) s_[n][3] = -1e30f;
            }
        }

        float mx0 = -1e30f, mx1 = -1e30f;
#pragma unroll
        for (int n = 0; n < 8; n++) {
            mx0 = fmaxf(mx0, fmaxf(s_[n][0], s_[n][1]));
            mx1 = fmaxf(mx1, fmaxf(s_[n][2], s_[n][3]));
        }
        mx0 = fmaxf(mx0, __shfl_xor_sync(0xffffffffu, mx0, 1));
        mx0 = fmaxf(mx0, __shfl_xor_sync(0xffffffffu, mx0, 2));
        mx1 = fmaxf(mx1, __shfl_xor_sync(0xffffffffu, mx1, 1));
        mx1 = fmaxf(mx1, __shfl_xor_sync(0xffffffffu, mx1, 2));
        const float mn0 = fmaxf(m0, mx0), mn1 = fmaxf(m1, mx1);
        const float sc0 = __expf(m0 - mn0), sc1 = __expf(m1 - mn1);
        m0 = mn0; m1 = mn1;

        uint32_t pah[4][4], pal[4][4];
        float rs0 = 0.f, rs1 = 0.f;
#pragma unroll
        for (int n = 0; n < 8; n++) {
            float p0 = __expf(s_[n][0] - mn0);
            float p1 = __expf(s_[n][1] - mn0);
            float p2 = __expf(s_[n][2] - mn1);
            float p3 = __expf(s_[n][3] - mn1);
            rs0 += p0 + p1; rs1 += p2 + p3;
            __half h0, e0, h1, e1, h2, e2, h3, e3;
            split_h(p0, h0, e0); split_h(p1, h1, e1);
            split_h(p2, h2, e2); split_h(p3, h3, e3);
            const int kc = n >> 1, wh = (n & 1) * 2;
            pah[kc][wh    ] = ((uint32_t)*(uint16_t*)&h1 << 16) | *(uint16_t*)&h0;
            pah[kc][wh + 1] = ((uint32_t)*(uint16_t*)&h3 << 16) | *(uint16_t*)&h2;
            pal[kc][wh    ] = ((uint32_t)*(uint16_t*)&e1 << 16) | *(uint16_t*)&e0;
            pal[kc][wh + 1] = ((uint32_t)*(uint16_t*)&e3 << 16) | *(uint16_t*)&e2;
        }
        rs0 += __shfl_xor_sync(0xffffffffu, rs0, 1);
        rs0 += __shfl_xor_sync(0xffffffffu, rs0, 2);
        rs1 += __shfl_xor_sync(0xffffffffu, rs1, 1);
        rs1 += __shfl_xor_sync(0xffffffffu, rs1, 2);
        l0 = l0 * sc0 + rs0;
        l1 = l1 * sc1 + rs1;

#pragma unroll
        for (int n = 0; n < 8; n++) {
            acc_o[n][0] *= sc0; acc_o[n][1] *= sc0;
            acc_o[n][2] *= sc1; acc_o[n][3] *= sc1;
        }

#pragma unroll
        for (int kc = 0; kc < 4; kc++) {
#pragma unroll
            for (int g = 0; g < 4; g++) {
                const int r = kc * 16 + (lane & 7) + ((lane >> 3) & 1) * 8;
                const int c = g * 16 + (lane >> 4) * 8;
                const uint32_t off = fa_off(r, c);
                uint32_t tvh[4], tvl[4];
                ldsm4t(tvh, bVh + off);
                ldsm4t(tvl, bVl + off);
                mma16816(acc_o[2*g],   pah[kc], tvh);
                mma16816(acc_o[2*g+1], pah[kc], tvh + 2);
                mma16816(acc_o[2*g],   pah[kc], tvl);
                mma16816(acc_o[2*g+1], pah[kc], tvl + 2);
                mma16816(acc_o[2*g],   pal[kc], tvh);
                mma16816(acc_o[2*g+1], pal[kc], tvh + 2);
            }
        }
    }

    const float i0 = 1.f / l0, i1 = 1.f / l1;
    float* ob = o + (size_t)b * SL * DM + hd * DHD;
#pragma unroll
    for (int n = 0; n < 8; n++) {
        const int c = n * 8 + (lane & 3) * 2;
        *(float2*)(ob + (size_t)gr0 * DM + c) = make_float2(acc_o[n][0] * i0, acc_o[n][1] * i0);
        *(float2*)(ob + (size_t)gr1 * DM + c) = make_float2(acc_o[n][2] * i1, acc_o[n][3] * i1);
    }
}

// ---------------- out = LayerNorm(a + r) * g + b  (+ split) ----------------
__global__ void resid_ln_kernel(const float* __restrict__ a, const float* __restrict__ r,
                                const float* __restrict__ g, const float* __restrict__ bb,
                                float* __restrict__ out)
{
    int row = blockIdx.x;
    int t = threadIdx.x;
    const float* pa = a + (size_t)row * DM;
    const float* pr = r + (size_t)row * DM;
    float v[4];
    float s = 0.f, s2 = 0.f;
#pragma unroll
    for (int i = 0; i < 4; i++) {
        float x = pa[t + i * 256] + pr[t + i * 256];
        v[i] = x; s += x; s2 += x * x;
    }
#pragma unroll
    for (int off = 16; off > 0; off >>= 1) {
        s  += __shfl_down_sync(0xffffffffu, s,  off);
        s2 += __shfl_down_sync(0xffffffffu, s2, off);
    }
    __shared__ float ws[8], ws2[8];
    __shared__ float sm_mean, sm_rstd;
    int w = t >> 5, lane = t & 31;
    if (lane == 0) { ws[w] = s; ws2[w] = s2; }
    __syncthreads();
    if (t == 0) {
        float S = 0.f, S2 = 0.f;
#pragma unroll
        for (int i = 0; i < 8; i++) { S += ws[i]; S2 += ws2[i]; }
        float mean = S * (1.f / DM);
        float var  = S2 * (1.f / DM) - mean * mean;
        sm_mean = mean;
        sm_rstd = rsqrtf(var + 1e-5f);
    }
    __syncthreads();
    float mean = sm_mean, rstd = sm_rstd;
#pragma unroll
    for (int i = 0; i < 4; i++) {
        int col = t + i * 256;
        float y = (v[i] - mean) * rstd * g[col] + bb[col];
        size_t idx = (size_t)row * DM + col;
        out[idx] = y;
        split_h(y, g_h_hi[idx], g_h_lo[idx]);
    }
}

__global__ void copy_out_kernel(float* __restrict__ out) {
    int i = blockIdx.x * 256 + threadIdx.x;
    out[i] = g_h[i];
}

// ---------------- launch ----------------
extern "C" void kernel_launch(void* const* d_in, const int* in_sizes, int n_in,
                              void* d_out, int out_size)
{
    const float* x    = (const float*)d_in[0];
    const float* pe   = (const float*)d_in[1];
    const float* wq   = (const float*)d_in[2];
    const float* wk   = (const float*)d_in[3];
    const float* wv   = (const float*)d_in[4];
    const float* ln1g = (const float*)d_in[5];
    const float* ln1b = (const float*)d_in[6];
    const float* w1   = (const float*)d_in[7];
    const float* b1   = (const float*)d_in[8];
    const float* w2   = (const float*)d_in[9];
    const float* b2   = (const float*)d_in[10];
    const float* ln2g = (const float*)d_in[11];
    const float* ln2b = (const float*)d_in[12];

    float *ph, *po;
    cudaGetSymbolAddress((void**)&ph, g_h);
    cudaGetSymbolAddress((void**)&po, g_o);
    __half *phh, *phl, *pfh, *pfl, *pqh, *pql;
    cudaGetSymbolAddress((void**)&phh, g_h_hi);
    cudaGetSymbolAddress((void**)&phl, g_h_lo);
    cudaGetSymbolAddress((void**)&pfh, g_ff_hi);
    cudaGetSymbolAddress((void**)&pfl, g_ff_lo);
    cudaGetSymbolAddress((void**)&pqh, g_qkv_hi);
    cudaGetSymbolAddress((void**)&pql, g_qkv_lo);
    __half *wqkvh, *wqkvl, *w1h, *w1l, *w2h, *w2l;
    cudaGetSymbolAddress((void**)&wqkvh, g_wqkv_hi); cudaGetSymbolAddress((void**)&wqkvl, g_wqkv_lo);
    cudaGetSymbolAddress((void**)&w1h, g_w1_hi);     cudaGetSymbolAddress((void**)&w1l, g_w1_lo);
    cudaGetSymbolAddress((void**)&w2h, g_w2_hi);     cudaGetSymbolAddress((void**)&w2l, g_w2_lo);

    cudaFuncSetAttribute(mm_kernel<1>, cudaFuncAttributeMaxDynamicSharedMemorySize, MM_SMEM);
    cudaFuncSetAttribute(mm_kernel<2>, cudaFuncAttributeMaxDynamicSharedMemorySize, MM_SMEM);
    cudaFuncSetAttribute(mm_kernel<3>, cudaFuncAttributeMaxDynamicSharedMemorySize, MM_SMEM);

    // launch #1: all weight transposes fused
    transpose_split_all_kernel<<<TR_GRID, 256>>>(wq, wk, wv, w1, w2);
    // launch #2
    add_pe_kernel<<<NTOK * DM / 256, 256>>>(x, pe);

    for (int l = 0; l < NLAYER; l++) {
        const size_t woq = (size_t)l * QS * DM;
        const size_t wo1 = (size_t)l * DM * DFF;

        // layer 0: launches #3..#8 -> ncu (-s 5 -c 1) captures launch #6 = mm_kernel<1> (MLP1)
        mm_kernel<3><<<dim3(QS / 128, NTOK / 128), 256, MM_SMEM>>>(
            phh, phl, wqkvh + woq, wqkvl + woq, nullptr,
            nullptr, pqh, pql, NTOK, QS, DM);

        flash_kernel<<<dim3(SL / 64, NB * NH), 128>>>(pqh, pql, po);

        resid_ln_kernel<<<NTOK, 256>>>(ph, po, ln1g + (size_t)l * DM, ln1b + (size_t)l * DM, ph);

        mm_kernel<1><<<dim3(DFF / 128, NTOK / 128), 256, MM_SMEM>>>(
            phh, phl, w1h + wo1, w1l + wo1, b1 + (size_t)l * DFF,
            nullptr, pfh, pfl, NTOK, DFF, DM);
        mm_kernel<2><<<dim3(DM / 128, NTOK / 128), 256, MM_SMEM>>>(
            pfh, pfl, w2h + wo1, w2l + wo1, b2 + (size_t)l * DM,
            po, nullptr, nullptr, NTOK, DM, DFF);

        resid_ln_kernel<<<NTOK, 256>>>(ph, po, ln2g + (size_t)l * DM, ln2b + (size_t)l * DM, ph);
    }

    copy_out_kernel<<<NTOK * DM / 256, 256>>>((float*)d_out);
}

// round 10
// speedup vs baseline: 2.9949x; 1.0317x over previous
#include <cuda_runtime.h>
#include <cuda_fp16.h>
#include <cstdint>
#include <math.h>

#define NB 2
#define SL 2048
#define DM 1024
#define NH 16
#define DHD 64
#define NLAYER 8
#define DFF 4096
#define NTOK (NB*SL)
#define QS (3*DM)          // fused qkv row stride

// ---------------- scratch (static device globals; no allocs) ----------------
__device__ __align__(256) float g_h  [(size_t)NTOK*DM];
__device__ __align__(256) float g_o  [(size_t)NTOK*DM];

// split-fp16 activations
__device__ __align__(256) __half g_h_hi[(size_t)NTOK*DM];
__device__ __align__(256) __half g_h_lo[(size_t)NTOK*DM];
__device__ __align__(256) __half g_ff_hi[(size_t)NTOK*DFF];
__device__ __align__(256) __half g_ff_lo[(size_t)NTOK*DFF];
__device__ __align__(256) __half g_qkv_hi[(size_t)NTOK*QS];
__device__ __align__(256) __half g_qkv_lo[(size_t)NTOK*QS];

// transposed + split weights: [N, K] fp16 hi/lo per layer (qkv fused: [3072,1024])
__device__ __align__(256) __half g_wqkv_hi[(size_t)NLAYER*QS*DM], g_wqkv_lo[(size_t)NLAYER*QS*DM];
__device__ __align__(256) __half g_w1_hi[(size_t)NLAYER*DM*DFF],  g_w1_lo[(size_t)NLAYER*DM*DFF];
__device__ __align__(256) __half g_w2_hi[(size_t)NLAYER*DM*DFF],  g_w2_lo[(size_t)NLAYER*DM*DFF];

// ---------------- helpers ----------------
__device__ __forceinline__ uint32_t smem_u32(const void* p) {
    uint32_t a;
    asm("{ .reg .u64 t; cvta.to.shared.u64 t, %1; cvt.u32.u64 %0, t; }" : "=r"(a) : "l"(p));
    return a;
}
#define CP_ASYNC16(dst, src) asm volatile("cp.async.cg.shared.global [%0], [%1], 16;" :: "r"(dst), "l"(src))
#define CP_COMMIT()          asm volatile("cp.async.commit_group;" ::: "memory")
#define CP_WAIT(n)           asm volatile("cp.async.wait_group %0;" :: "n"(n) : "memory")

__device__ __forceinline__ void ldsm4(uint32_t* r, uint32_t a) {
    asm volatile("ldmatrix.sync.aligned.m8n8.x4.shared.b16 {%0,%1,%2,%3}, [%4];"
        : "=r"(r[0]), "=r"(r[1]), "=r"(r[2]), "=r"(r[3]) : "r"(a));
}
__device__ __forceinline__ void ldsm4t(uint32_t* r, uint32_t a) {
    asm volatile("ldmatrix.sync.aligned.m8n8.x4.trans.shared.b16 {%0,%1,%2,%3}, [%4];"
        : "=r"(r[0]), "=r"(r[1]), "=r"(r[2]), "=r"(r[3]) : "r"(a));
}
__device__ __forceinline__ void mma16816(float* c, const uint32_t* a, const uint32_t* b) {
    asm volatile("mma.sync.aligned.m16n8k16.row.col.f32.f16.f16.f32 "
        "{%0,%1,%2,%3}, {%4,%5,%6,%7}, {%8,%9}, {%0,%1,%2,%3};"
        : "+f"(c[0]), "+f"(c[1]), "+f"(c[2]), "+f"(c[3])
        : "r"(a[0]), "r"(a[1]), "r"(a[2]), "r"(a[3]), "r"(b[0]), "r"(b[1]));
}
// f16-accumulate variant (corrections): D,C are 2 regs of half2
__device__ __forceinline__ void mma16816h(uint32_t* c, const uint32_t* a, const uint32_t* b) {
    asm volatile("mma.sync.aligned.m16n8k16.row.col.f16.f16.f16.f16 "
        "{%0,%1}, {%2,%3,%4,%5}, {%6,%7}, {%0,%1};"
        : "+r"(c[0]), "+r"(c[1])
        : "r"(a[0]), "r"(a[1]), "r"(a[2]), "r"(a[3]), "r"(b[0]), "r"(b[1]));
}
__device__ __forceinline__ void split_h(float v, __half& hi, __half& lo) {
    hi = __float2half_rn(v);
    lo = __float2half_rn(v - __half2float(hi));
}
__device__ __forceinline__ float selu_f(float v) {
    return 1.0507009873554805f * (v > 0.f ? v : 1.6732632423543772f * expm1f(v));
}

// GEMM smem tile: 128 rows x 32 fp16 = 64B/row, 4 x 16B chunks; chunk ^= (row>>1)&3
__device__ __forceinline__ uint32_t tile_off(int row, int colElem) {
    return (uint32_t)(row * 64 + ((((colElem >> 3) & 3) ^ ((row >> 1) & 3)) << 4));
}
// flash smem tile: 64 rows x 64 fp16 = 128B/row, 8 x 16B chunks; chunk ^= row&7
__device__ __forceinline__ uint32_t fa_off(int row, int colElem) {
    return (uint32_t)(row * 128 + ((((colElem >> 3) & 7) ^ (row & 7)) << 4));
}

// ---------------- h = x + pe (+ split) ----------------
__global__ void add_pe_kernel(const float* __restrict__ x, const float* __restrict__ pe) {
    int i = blockIdx.x * 256 + threadIdx.x;
    float v = x[i] + pe[i & (SL*DM - 1)];
    g_h[i] = v;
    split_h(v, g_h_hi[i], g_h_lo[i]);
}

// ---------------- fused weight transpose + split (ALL weights, one launch) ----------------
#define TR_GRID 90112
__global__ __launch_bounds__(256) void transpose_split_all_kernel(
    const float* __restrict__ wq, const float* __restrict__ wk, const float* __restrict__ wv,
    const float* __restrict__ w1, const float* __restrict__ w2)
{
    __shared__ float tile[32][33];
    const int bid = blockIdx.x;
    const int t = threadIdx.x;

    const float* src; __half* dh; __half* dl;
    int K, N, n0, k0;
    if (bid < 24576) {
        const int which = bid >> 13;
        const int r = bid & 8191;
        const int l = r >> 10;
        const int tl = r & 1023;
        K = DM; N = DM;
        n0 = (tl & 31) * 32; k0 = (tl >> 5) * 32;
        src = (which == 0 ? wq : which == 1 ? wk : wv) + (size_t)l * DM * DM;
        const size_t doff = (size_t)l * QS * DM + (size_t)which * DM * DM;
        dh = g_wqkv_hi + doff; dl = g_wqkv_lo + doff;
    } else if (bid < 57344) {
        const int r = bid - 24576;
        const int l = r >> 12;
        const int tl = r & 4095;
        K = DM; N = DFF;
        n0 = (tl & 127) * 32; k0 = (tl >> 7) * 32;
        src = w1 + (size_t)l * DM * DFF;
        dh = g_w1_hi + (size_t)l * DM * DFF; dl = g_w1_lo + (size_t)l * DM * DFF;
    } else {
        const int r = bid - 57344;
        const int l = r >> 12;
        const int tl = r & 4095;
        K = DFF; N = DM;
        n0 = (tl & 31) * 32; k0 = (tl >> 5) * 32;
        src = w2 + (size_t)l * DM * DFF;
        dh = g_w2_hi + (size_t)l * DM * DFF; dl = g_w2_lo + (size_t)l * DM * DFF;
    }

    const int lx = t & 31, ly = t >> 5;
#pragma unroll
    for (int i = 0; i < 4; i++) {
        const int kr = ly + i * 8;
        tile[kr][lx] = src[(size_t)(k0 + kr) * N + n0 + lx];
    }
    __syncthreads();

    const int kp = t & 15;
#pragma unroll
    for (int p = 0; p < 2; p++) {
        const int n = (t >> 4) + p * 16;
        const float v0 = tile[2 * kp][n], v1 = tile[2 * kp + 1][n];
        __half h0, l0h, h1, l1h;
        split_h(v0, h0, l0h); split_h(v1, h1, l1h);
        const size_t o = (size_t)(n0 + n) * K + k0 + 2 * kp;
        *(__half2*)(dh + o) = __halves2half2(h0, h1);
        *(__half2*)(dl + o) = __halves2half2(l0h, l1h);
    }
}

// ---------------- split-fp16 GEMM via mma.sync (HMMA) ----------------
#define MM_STAGE 32768           // Ah 8K | Al 8K | Bh 8K | Bl 8K
#define MM_NSTG  4
#define MM_SMEM  (MM_NSTG*MM_STAGE)

template<int EPI>
__global__ __launch_bounds__(256, 1) void mm_kernel(
    const __half* __restrict__ Ah, const __half* __restrict__ Al,
    const __half* __restrict__ Bh, const __half* __restrict__ Bl,
    const float* __restrict__ bias,
    float* __restrict__ Cf, __half* __restrict__ Ch, __half* __restrict__ Cl,
    int M, int N, int K)
{
    extern __shared__ char smem[];
    const uint32_t sb = smem_u32(smem);
    const int t = threadIdx.x, lane = t & 31, wid = t >> 5;
    const int n0 = blockIdx.x * 128, m0 = blockIdx.y * 128;
    const int wm = (wid >> 1) * 32, wn = (wid & 1) * 64;

    const int row0 = t >> 2, ch0 = t & 3;
    const uint32_t so0 = tile_off(row0, ch0 * 8);

    float acc[2][8][4];
    uint32_t acc16[2][8][2];
#pragma unroll
    for (int mt = 0; mt < 2; mt++)
#pragma unroll
        for (int nt = 0; nt < 8; nt++) {
#pragma unroll
            for (int e = 0; e < 4; e++) acc[mt][nt][e] = 0.f;
            acc16[mt][nt][0] = 0u; acc16[mt][nt][1] = 0u;
        }

    const int nst = K >> 5;

    auto LOAD_STAGE = [&](int stage, int kt) {
        const uint32_t sa = sb + stage * MM_STAGE;
        const size_t kof = (size_t)kt * 32 + ch0 * 8;
#pragma unroll
        for (int i = 0; i < 2; i++) {
            const int row = row0 + i * 64;
            const uint32_t so = sa + so0 + i * 4096;
            const size_t ga = (size_t)(m0 + row) * K + kof;
            const size_t gb = (size_t)(n0 + row) * K + kof;
            CP_ASYNC16(so,         Ah + ga);
            CP_ASYNC16(so +  8192, Al + ga);
            CP_ASYNC16(so + 16384, Bh + gb);
            CP_ASYNC16(so + 24576, Bl + gb);
        }
    };

    auto COMPUTE = [&](int stage) {
        const uint32_t sa = sb + stage * MM_STAGE;
#pragma unroll
        for (int ks = 0; ks < 2; ks++) {
            const int k0 = ks * 16;
            uint32_t ahf[2][4], alf[2][4], bhf[8][2], blf[8][2];
#pragma unroll
            for (int mt = 0; mt < 2; mt++) {
                const int r = wm + mt * 16 + (lane & 7) + ((lane >> 3) & 1) * 8;
                const int c = k0 + (lane >> 4) * 8;
                const uint32_t off = tile_off(r, c);
                ldsm4(ahf[mt], sa + off);
                ldsm4(alf[mt], sa + 8192 + off);
            }
#pragma unroll
            for (int g = 0; g < 4; g++) {
                const int r = wn + g * 16 + (lane & 7) + (lane >> 4) * 8;
                const int c = k0 + ((lane >> 3) & 1) * 8;
                const uint32_t off = tile_off(r, c);
                uint32_t tmp[4];
                ldsm4(tmp, sa + 16384 + off);
                bhf[g*2][0] = tmp[0]; bhf[g*2][1] = tmp[1];
                bhf[g*2+1][0] = tmp[2]; bhf[g*2+1][1] = tmp[3];
                ldsm4(tmp, sa + 24576 + off);
                blf[g*2][0] = tmp[0]; blf[g*2][1] = tmp[1];
                blf[g*2+1][0] = tmp[2]; blf[g*2+1][1] = tmp[3];
            }
#pragma unroll
            for (int mt = 0; mt < 2; mt++)
#pragma unroll
                for (int nt = 0; nt < 8; nt++) mma16816(acc[mt][nt], ahf[mt], bhf[nt]);
#pragma unroll
            for (int mt = 0; mt < 2; mt++)
#pragma unroll
                for (int nt = 0; nt < 8; nt++) mma16816h(acc16[mt][nt], ahf[mt], blf[nt]);
#pragma unroll
            for (int mt = 0; mt < 2; mt++)
#pragma unroll
                for (int nt = 0; nt < 8; nt++) mma16816h(acc16[mt][nt], alf[mt], bhf[nt]);
        }
    };

    LOAD_STAGE(0, 0); CP_COMMIT();
    LOAD_STAGE(1, 1); CP_COMMIT();
    LOAD_STAGE(2, 2); CP_COMMIT();

#pragma unroll 1
    for (int kt = 0; kt < nst; kt++) {
        if (kt + 3 < nst) { CP_WAIT(2); } else { CP_WAIT(0); }
        __syncthreads();
        if (kt + 3 < nst) { LOAD_STAGE((kt + 3) & 3, kt + 3); CP_COMMIT(); }
        COMPUTE(kt & 3);
    }

#pragma unroll
    for (int mt = 0; mt < 2; mt++) {
        const int r0 = m0 + wm + mt * 16 + (lane >> 2);
#pragma unroll
        for (int nt = 0; nt < 8; nt++) {
            const int col = n0 + wn + nt * 8 + (lane & 3) * 2;
            const float2 c01 = __half22float2(*(__half2*)&acc16[mt][nt][0]);
            const float2 c23 = __half22float2(*(__half2*)&acc16[mt][nt][1]);
            float v0 = acc[mt][nt][0] + c01.x, v1 = acc[mt][nt][1] + c01.y;
            float v2 = acc[mt][nt][2] + c23.x, v3 = acc[mt][nt][3] + c23.y;
            if (EPI == 0) {
                *(float2*)(Cf + (size_t)r0 * N + col)       = make_float2(v0, v1);
                *(float2*)(Cf + (size_t)(r0 + 8) * N + col) = make_float2(v2, v3);
            } else if (EPI == 2) {
                const float b0 = bias[col], b1 = bias[col + 1];
                *(float2*)(Cf + (size_t)r0 * N + col)       = make_float2(v0 + b0, v1 + b1);
                *(float2*)(Cf + (size_t)(r0 + 8) * N + col) = make_float2(v2 + b0, v3 + b1);
            } else if (EPI == 1) {
                const float b0 = bias[col], b1 = bias[col + 1];
                float s0 = selu_f(v0 + b0), s1 = selu_f(v1 + b1);
                float s2 = selu_f(v2 + b0), s3 = selu_f(v3 + b1);
                __half h0, l0, h1, l1;
                split_h(s0, h0, l0); split_h(s1, h1, l1);
                *(__half2*)(Ch + (size_t)r0 * N + col) = __halves2half2(h0, h1);
                *(__half2*)(Cl + (size_t)r0 * N + col) = __halves2half2(l0, l1);
                split_h(s2, h0, l0); split_h(s3, h1, l1);
                *(__half2*)(Ch + (size_t)(r0 + 8) * N + col) = __halves2half2(h0, h1);
                *(__half2*)(Cl + (size_t)(r0 + 8) * N + col) = __halves2half2(l0, l1);
            } else {   // EPI == 3: qkv, q region scaled by 1/8, split fp16
                const float sc = (col < DM) ? 0.125f : 1.0f;
                float s0 = v0 * sc, s1 = v1 * sc, s2 = v2 * sc, s3 = v3 * sc;
                __half h0, l0, h1, l1;
                split_h(s0, h0, l0); split_h(s1, h1, l1);
                *(__half2*)(Ch + (size_t)r0 * N + col) = __halves2half2(h0, h1);
                *(__half2*)(Cl + (size_t)r0 * N + col) = __halves2half2(l0, l1);
                split_h(s2, h0, l0); split_h(s3, h1, l1);
                *(__half2*)(Ch + (size_t)(r0 + 8) * N + col) = __halves2half2(h0, h1);
                *(__half2*)(Cl + (size_t)(r0 + 8) * N + col) = __halves2half2(l0, l1);
            }
        }
    }
}

// ---------------- flash attention: split-fp16 HMMA, double-buffered K/V ----------------
// 64x64 tiles, 128 threads / 4 warps; dynamic smem:
//   [0,16K)   Qh|Ql  (8K each)
//   [16K,48K) stage0: Kh|Kl|Vh|Vl (8K each)
//   [48K,80K) stage1
#define FA_SMEM (16384 + 2*32768)

__global__ __launch_bounds__(128, 2) void flash_kernel(
    const __half* __restrict__ qkvh, const __half* __restrict__ qkvl,
    float* __restrict__ o)
{
    extern __shared__ __half fsm[];
    const uint32_t bQh = smem_u32(fsm);
    const uint32_t bQl = bQh + 8192;

    const int qt = gridDim.x - 1 - blockIdx.x;   // heavy tiles first
    const int bh = blockIdx.y;
    const int b  = bh >> 4, hd = bh & 15;
    const size_t qoff = (size_t)b * SL * QS + hd * DHD;

    const int t = threadIdx.x, lane = t & 31, w = t >> 5;

    int lrow[4]; uint32_t lso[4]; int lch[4];
#pragma unroll
    for (int i = 0; i < 4; i++) {
        int seg = t + i * 128;
        lrow[i] = seg >> 3;
        int ch = seg & 7;
        lso[i] = (uint32_t)(lrow[i] * 128 + ((ch ^ (lrow[i] & 7)) << 4));
        lch[i] = ch;
    }

    auto LOAD_KV = [&](int kt, int st) {
        const uint32_t s = bQh + 16384 + st * 32768;
#pragma unroll
        for (int i = 0; i < 4; i++) {
            const size_t gk = qoff + DM     + (size_t)(kt * 64 + lrow[i]) * QS + lch[i] * 8;
            const size_t gv = qoff + 2 * DM + (size_t)(kt * 64 + lrow[i]) * QS + lch[i] * 8;
            CP_ASYNC16(s         + lso[i], qkvh + gk);
            CP_ASYNC16(s +  8192 + lso[i], qkvl + gk);
            CP_ASYNC16(s + 16384 + lso[i], qkvh + gv);
            CP_ASYNC16(s + 24576 + lso[i], qkvl + gv);
        }
    };

    // prologue: Q, then KV tile 0
#pragma unroll
    for (int i = 0; i < 4; i++) {
        const size_t g = qoff + (size_t)(qt * 64 + lrow[i]) * QS + lch[i] * 8;
        CP_ASYNC16(bQh + lso[i], qkvh + g);
        CP_ASYNC16(bQl + lso[i], qkvl + g);
    }
    CP_COMMIT();
    LOAD_KV(0, 0); CP_COMMIT();

    CP_WAIT(1);          // Q arrived
    __syncthreads();

    uint32_t qfh[4][4], qfl[4][4];
#pragma unroll
    for (int ks = 0; ks < 4; ks++) {
        const int r = w * 16 + (lane & 7) + ((lane >> 3) & 1) * 8;
        const int c = ks * 16 + (lane >> 4) * 8;
        const uint32_t off = fa_off(r, c);
        ldsm4(qfh[ks], bQh + off);
        ldsm4(qfl[ks], bQl + off);
    }

    float acc_o[8][4];
#pragma unroll
    for (int n = 0; n < 8; n++)
#pragma unroll
        for (int e = 0; e < 4; e++) acc_o[n][e] = 0.f;
    float m0 = -1e30f, m1 = -1e30f, l0 = 0.f, l1 = 0.f;

    const int gr0 = qt * 64 + w * 16 + (lane >> 2);
    const int gr1 = gr0 + 8;

    for (int kt = 0; kt <= qt; kt++) {
        const int cur = kt & 1;
        CP_WAIT(0);          // stage cur data arrived
        __syncthreads();     // all warps done with stage 1-cur (prev compute)
        if (kt < qt) { LOAD_KV(kt + 1, 1 - cur); CP_COMMIT(); }

        const uint32_t sKh = bQh + 16384 + cur * 32768;
        const uint32_t sKl = sKh + 8192;
        const uint32_t sVh = sKh + 16384;
        const uint32_t sVl = sKh + 24576;

        // ---- S = Q K^T (split, 3 passes) ----
        float s_[8][4];
#pragma unroll
        for (int n = 0; n < 8; n++)
#pragma unroll
            for (int e = 0; e < 4; e++) s_[n][e] = 0.f;

#pragma unroll
        for (int ks = 0; ks < 4; ks++) {
            const int k0 = ks * 16;
            uint32_t bhf[8][2], blf[8][2];
#pragma unroll
            for (int g = 0; g < 4; g++) {
                const int r = g * 16 + (lane & 7) + (lane >> 4) * 8;
                const int c = k0 + ((lane >> 3) & 1) * 8;
                const uint32_t off = fa_off(r, c);
                uint32_t tmp[4];
                ldsm4(tmp, sKh + off);
                bhf[g*2][0] = tmp[0]; bhf[g*2][1] = tmp[1];
                bhf[g*2+1][0] = tmp[2]; bhf[g*2+1][1] = tmp[3];
                ldsm4(tmp, sKl + off);
                blf[g*2][0] = tmp[0]; blf[g*2][1] = tmp[1];
                blf[g*2+1][0] = tmp[2]; blf[g*2+1][1] = tmp[3];
            }
#pragma unroll
            for (int n = 0; n < 8; n++) mma16816(s_[n], qfh[ks], bhf[n]);
#pragma unroll
            for (int n = 0; n < 8; n++) mma16816(s_[n], qfh[ks], blf[n]);
#pragma unroll
            for (int n = 0; n < 8; n++) mma16816(s_[n], qfl[ks], bhf[n]);
        }

        if (kt == qt) {
#pragma unroll
            for (int n = 0; n < 8; n++) {
                const int c = kt * 64 + n * 8 + (lane & 3) * 2;
                if (c     > gr0) s_[n][0] = -1e30f;
                if (c + 1 > gr0) s_[n][1] = -1e30f;
                if (c     > gr1) s_[n][2] = -1e30f;
                if (c + 1 > gr1) s_[n][3] = -1e30f;
            }
        }

        // ---- online softmax (P rounded to fp16; no P-lo term) ----
        float mx0 = -1e30f, mx1 = -1e30f;
#pragma unroll
        for (int n = 0; n < 8; n++) {
            mx0 = fmaxf(mx0, fmaxf(s_[n][0], s_[n][1]));
            mx1 = fmaxf(mx1, fmaxf(s_[n][2], s_[n][3]));
        }
        mx0 = fmaxf(mx0, __shfl_xor_sync(0xffffffffu, mx0, 1));
        mx0 = fmaxf(mx0, __shfl_xor_sync(0xffffffffu, mx0, 2));
        mx1 = fmaxf(mx1, __shfl_xor_sync(0xffffffffu, mx1, 1));
        mx1 = fmaxf(mx1, __shfl_xor_sync(0xffffffffu, mx1, 2));
        const float mn0 = fmaxf(m0, mx0), mn1 = fmaxf(m1, mx1);
        const float sc0 = __expf(m0 - mn0), sc1 = __expf(m1 - mn1);
        m0 = mn0; m1 = mn1;

        uint32_t pah[4][4];
        float rs0 = 0.f, rs1 = 0.f;
#pragma unroll
        for (int n = 0; n < 8; n++) {
            float p0 = __expf(s_[n][0] - mn0);
            float p1 = __expf(s_[n][1] - mn0);
            float p2 = __expf(s_[n][2] - mn1);
            float p3 = __expf(s_[n][3] - mn1);
            rs0 += p0 + p1; rs1 += p2 + p3;
            __half2 h01 = __floats2half2_rn(p0, p1);
            __half2 h23 = __floats2half2_rn(p2, p3);
            const int kc = n >> 1, wh = (n & 1) * 2;
            pah[kc][wh    ] = *(uint32_t*)&h01;
            pah[kc][wh + 1] = *(uint32_t*)&h23;
        }
        rs0 += __shfl_xor_sync(0xffffffffu, rs0, 1);
        rs0 += __shfl_xor_sync(0xffffffffu, rs0, 2);
        rs1 += __shfl_xor_sync(0xffffffffu, rs1, 1);
        rs1 += __shfl_xor_sync(0xffffffffu, rs1, 2);
        l0 = l0 * sc0 + rs0;
        l1 = l1 * sc1 + rs1;

#pragma unroll
        for (int n = 0; n < 8; n++) {
            acc_o[n][0] *= sc0; acc_o[n][1] *= sc0;
            acc_o[n][2] *= sc1; acc_o[n][3] *= sc1;
        }

        // ---- O += P (Vh + Vl), 2 passes ----
#pragma unroll
        for (int kc = 0; kc < 4; kc++) {
#pragma unroll
            for (int g = 0; g < 4; g++) {
                const int r = kc * 16 + (lane & 7) + ((lane >> 3) & 1) * 8;
                const int c = g * 16 + (lane >> 4) * 8;
                const uint32_t off = fa_off(r, c);
                uint32_t tvh[4], tvl[4];
                ldsm4t(tvh, sVh + off);
                ldsm4t(tvl, sVl + off);
                mma16816(acc_o[2*g],   pah[kc], tvh);
                mma16816(acc_o[2*g+1], pah[kc], tvh + 2);
                mma16816(acc_o[2*g],   pah[kc], tvl);
                mma16816(acc_o[2*g+1], pah[kc], tvl + 2);
            }
        }
    }

    const float i0 = 1.f / l0, i1 = 1.f / l1;
    float* ob = o + (size_t)b * SL * DM + hd * DHD;
#pragma unroll
    for (int n = 0; n < 8; n++) {
        const int c = n * 8 + (lane & 3) * 2;
        *(float2*)(ob + (size_t)gr0 * DM + c) = make_float2(acc_o[n][0] * i0, acc_o[n][1] * i0);
        *(float2*)(ob + (size_t)gr1 * DM + c) = make_float2(acc_o[n][2] * i1, acc_o[n][3] * i1);
    }
}

// ---------------- out = LayerNorm(a + r) * g + b  (+ split) ----------------
__global__ void resid_ln_kernel(const float* __restrict__ a, const float* __restrict__ r,
                                const float* __restrict__ g, const float* __restrict__ bb,
                                float* __restrict__ out)
{
    int row = blockIdx.x;
    int t = threadIdx.x;
    const float* pa = a + (size_t)row * DM;
    const float* pr = r + (size_t)row * DM;
    float v[4];
    float s = 0.f, s2 = 0.f;
#pragma unroll
    for (int i = 0; i < 4; i++) {
        float x = pa[t + i * 256] + pr[t + i * 256];
        v[i] = x; s += x; s2 += x * x;
    }
#pragma unroll
    for (int off = 16; off > 0; off >>= 1) {
        s  += __shfl_down_sync(0xffffffffu, s,  off);
        s2 += __shfl_down_sync(0xffffffffu, s2, off);
    }
    __shared__ float ws[8], ws2[8];
    __shared__ float sm_mean, sm_rstd;
    int w = t >> 5, lane = t & 31;
    if (lane == 0) { ws[w] = s; ws2[w] = s2; }
    __syncthreads();
    if (t == 0) {
        float S = 0.f, S2 = 0.f;
#pragma unroll
        for (int i = 0; i < 8; i++) { S += ws[i]; S2 += ws2[i]; }
        float mean = S * (1.f / DM);
        float var  = S2 * (1.f / DM) - mean * mean;
        sm_mean = mean;
        sm_rstd = rsqrtf(var + 1e-5f);
    }
    __syncthreads();
    float mean = sm_mean, rstd = sm_rstd;
#pragma unroll
    for (int i = 0; i < 4; i++) {
        int col = t + i * 256;
        float y = (v[i] - mean) * rstd * g[col] + bb[col];
        size_t idx = (size_t)row * DM + col;
        out[idx] = y;
        split_h(y, g_h_hi[idx], g_h_lo[idx]);
    }
}

__global__ void copy_out_kernel(float* __restrict__ out) {
    int i = blockIdx.x * 256 + threadIdx.x;
    out[i] = g_h[i];
}

// ---------------- launch ----------------
extern "C" void kernel_launch(void* const* d_in, const int* in_sizes, int n_in,
                              void* d_out, int out_size)
{
    const float* x    = (const float*)d_in[0];
    const float* pe   = (const float*)d_in[1];
    const float* wq   = (const float*)d_in[2];
    const float* wk   = (const float*)d_in[3];
    const float* wv   = (const float*)d_in[4];
    const float* ln1g = (const float*)d_in[5];
    const float* ln1b = (const float*)d_in[6];
    const float* w1   = (const float*)d_in[7];
    const float* b1   = (const float*)d_in[8];
    const float* w2   = (const float*)d_in[9];
    const float* b2   = (const float*)d_in[10];
    const float* ln2g = (const float*)d_in[11];
    const float* ln2b = (const float*)d_in[12];

    float *ph, *po;
    cudaGetSymbolAddress((void**)&ph, g_h);
    cudaGetSymbolAddress((void**)&po, g_o);
    __half *phh, *phl, *pfh, *pfl, *pqh, *pql;
    cudaGetSymbolAddress((void**)&phh, g_h_hi);
    cudaGetSymbolAddress((void**)&phl, g_h_lo);
    cudaGetSymbolAddress((void**)&pfh, g_ff_hi);
    cudaGetSymbolAddress((void**)&pfl, g_ff_lo);
    cudaGetSymbolAddress((void**)&pqh, g_qkv_hi);
    cudaGetSymbolAddress((void**)&pql, g_qkv_lo);
    __half *wqkvh, *wqkvl, *w1h, *w1l, *w2h, *w2l;
    cudaGetSymbolAddress((void**)&wqkvh, g_wqkv_hi); cudaGetSymbolAddress((void**)&wqkvl, g_wqkv_lo);
    cudaGetSymbolAddress((void**)&w1h, g_w1_hi);     cudaGetSymbolAddress((void**)&w1l, g_w1_lo);
    cudaGetSymbolAddress((void**)&w2h, g_w2_hi);     cudaGetSymbolAddress((void**)&w2l, g_w2_lo);

    cudaFuncSetAttribute(mm_kernel<1>, cudaFuncAttributeMaxDynamicSharedMemorySize, MM_SMEM);
    cudaFuncSetAttribute(mm_kernel<2>, cudaFuncAttributeMaxDynamicSharedMemorySize, MM_SMEM);
    cudaFuncSetAttribute(mm_kernel<3>, cudaFuncAttributeMaxDynamicSharedMemorySize, MM_SMEM);
    cudaFuncSetAttribute(flash_kernel, cudaFuncAttributeMaxDynamicSharedMemorySize, FA_SMEM);

    transpose_split_all_kernel<<<TR_GRID, 256>>>(wq, wk, wv, w1, w2);
    add_pe_kernel<<<NTOK * DM / 256, 256>>>(x, pe);

    for (int l = 0; l < NLAYER; l++) {
        const size_t woq = (size_t)l * QS * DM;
        const size_t wo1 = (size_t)l * DM * DFF;

        mm_kernel<3><<<dim3(QS / 128, NTOK / 128), 256, MM_SMEM>>>(
            phh, phl, wqkvh + woq, wqkvl + woq, nullptr,
            nullptr, pqh, pql, NTOK, QS, DM);

        flash_kernel<<<dim3(SL / 64, NB * NH), 128, FA_SMEM>>>(pqh, pql, po);

        resid_ln_kernel<<<NTOK, 256>>>(ph, po, ln1g + (size_t)l * DM, ln1b + (size_t)l * DM, ph);

        mm_kernel<1><<<dim3(DFF / 128, NTOK / 128), 256, MM_SMEM>>>(
            phh, phl, w1h + wo1, w1l + wo1, b1 + (size_t)l * DFF,
            nullptr, pfh, pfl, NTOK, DFF, DM);
        mm_kernel<2><<<dim3(DM / 128, NTOK / 128), 256, MM_SMEM>>>(
            pfh, pfl, w2h + wo1, w2l + wo1, b2 + (size_t)l * DM,
            po, nullptr, nullptr, NTOK, DM, DFF);

        resid_ln_kernel<<<NTOK, 256>>>(ph, po, ln2g + (size_t)l * DM, ln2b + (size_t)l * DM, ph);
    }

    copy_out_kernel<<<NTOK * DM / 256, 256>>>((float*)d_out);
}

// round 11
// speedup vs baseline: 3.0077x; 1.0043x over previous
#include <cuda_runtime.h>
#include <cuda_fp16.h>
#include <cstdint>
#include <math.h>

#define NB 2
#define SL 2048
#define DM 1024
#define NH 16
#define DHD 64
#define NLAYER 8
#define DFF 4096
#define NTOK (NB*SL)
#define QS (3*DM)          // fused qkv row stride

// ---------------- scratch (static device globals; no allocs) ----------------
__device__ __align__(256) float g_h  [(size_t)NTOK*DM];
__device__ __align__(256) float g_o  [(size_t)NTOK*DM];

// split-fp16 activations
__device__ __align__(256) __half g_h_hi[(size_t)NTOK*DM];
__device__ __align__(256) __half g_h_lo[(size_t)NTOK*DM];
__device__ __align__(256) __half g_ff_hi[(size_t)NTOK*DFF];
__device__ __align__(256) __half g_ff_lo[(size_t)NTOK*DFF];
__device__ __align__(256) __half g_qkv_hi[(size_t)NTOK*QS];
__device__ __align__(256) __half g_qkv_lo[(size_t)NTOK*QS];

// transposed + split weights: [N, K] fp16 hi/lo per layer (qkv fused: [3072,1024])
__device__ __align__(256) __half g_wqkv_hi[(size_t)NLAYER*QS*DM], g_wqkv_lo[(size_t)NLAYER*QS*DM];
__device__ __align__(256) __half g_w1_hi[(size_t)NLAYER*DM*DFF],  g_w1_lo[(size_t)NLAYER*DM*DFF];
__device__ __align__(256) __half g_w2_hi[(size_t)NLAYER*DM*DFF],  g_w2_lo[(size_t)NLAYER*DM*DFF];

// ---------------- helpers ----------------
__device__ __forceinline__ uint32_t smem_u32(const void* p) {
    uint32_t a;
    asm("{ .reg .u64 t; cvta.to.shared.u64 t, %1; cvt.u32.u64 %0, t; }" : "=r"(a) : "l"(p));
    return a;
}
#define CP_ASYNC16(dst, src) asm volatile("cp.async.cg.shared.global [%0], [%1], 16;" :: "r"(dst), "l"(src))
#define CP_COMMIT()          asm volatile("cp.async.commit_group;" ::: "memory")
#define CP_WAIT(n)           asm volatile("cp.async.wait_group %0;" :: "n"(n) : "memory")

__device__ __forceinline__ void ldsm4(uint32_t* r, uint32_t a) {
    asm volatile("ldmatrix.sync.aligned.m8n8.x4.shared.b16 {%0,%1,%2,%3}, [%4];"
        : "=r"(r[0]), "=r"(r[1]), "=r"(r[2]), "=r"(r[3]) : "r"(a));
}
__device__ __forceinline__ void ldsm4t(uint32_t* r, uint32_t a) {
    asm volatile("ldmatrix.sync.aligned.m8n8.x4.trans.shared.b16 {%0,%1,%2,%3}, [%4];"
        : "=r"(r[0]), "=r"(r[1]), "=r"(r[2]), "=r"(r[3]) : "r"(a));
}
__device__ __forceinline__ void mma16816(float* c, const uint32_t* a, const uint32_t* b) {
    asm volatile("mma.sync.aligned.m16n8k16.row.col.f32.f16.f16.f32 "
        "{%0,%1,%2,%3}, {%4,%5,%6,%7}, {%8,%9}, {%0,%1,%2,%3};"
        : "+f"(c[0]), "+f"(c[1]), "+f"(c[2]), "+f"(c[3])
        : "r"(a[0]), "r"(a[1]), "r"(a[2]), "r"(a[3]), "r"(b[0]), "r"(b[1]));
}
// f16-accumulate variant (corrections): D,C are 2 regs of half2
__device__ __forceinline__ void mma16816h(uint32_t* c, const uint32_t* a, const uint32_t* b) {
    asm volatile("mma.sync.aligned.m16n8k16.row.col.f16.f16.f16.f16 "
        "{%0,%1}, {%2,%3,%4,%5}, {%6,%7}, {%0,%1};"
        : "+r"(c[0]), "+r"(c[1])
        : "r"(a[0]), "r"(a[1]), "r"(a[2]), "r"(a[3]), "r"(b[0]), "r"(b[1]));
}
__device__ __forceinline__ void split_h(float v, __half& hi, __half& lo) {
    hi = __float2half_rn(v);
    lo = __float2half_rn(v - __half2float(hi));
}
__device__ __forceinline__ float selu_f(float v) {
    return 1.0507009873554805f * (v > 0.f ? v : 1.6732632423543772f * expm1f(v));
}

// GEMM smem tile: 128 rows x 32 fp16 = 64B/row, 4 x 16B chunks; chunk ^= (row>>1)&3
__device__ __forceinline__ uint32_t tile_off(int row, int colElem) {
    return (uint32_t)(row * 64 + ((((colElem >> 3) & 3) ^ ((row >> 1) & 3)) << 4));
}
// flash smem tile: rows x 64 fp16 = 128B/row, 8 x 16B chunks; chunk ^= row&7
__device__ __forceinline__ uint32_t fa_off(int row, int colElem) {
    return (uint32_t)(row * 128 + ((((colElem >> 3) & 7) ^ (row & 7)) << 4));
}

// ---------------- h = x + pe (+ split) ----------------
__global__ void add_pe_kernel(const float* __restrict__ x, const float* __restrict__ pe) {
    int i = blockIdx.x * 256 + threadIdx.x;
    float v = x[i] + pe[i & (SL*DM - 1)];
    g_h[i] = v;
    split_h(v, g_h_hi[i], g_h_lo[i]);
}

// ---------------- fused weight transpose + split (ALL weights, one launch) ----------------
#define TR_GRID 90112
__global__ __launch_bounds__(256) void transpose_split_all_kernel(
    const float* __restrict__ wq, const float* __restrict__ wk, const float* __restrict__ wv,
    const float* __restrict__ w1, const float* __restrict__ w2)
{
    __shared__ float tile[32][33];
    const int bid = blockIdx.x;
    const int t = threadIdx.x;

    const float* src; __half* dh; __half* dl;
    int K, N, n0, k0;
    if (bid < 24576) {
        const int which = bid >> 13;
        const int r = bid & 8191;
        const int l = r >> 10;
        const int tl = r & 1023;
        K = DM; N = DM;
        n0 = (tl & 31) * 32; k0 = (tl >> 5) * 32;
        src = (which == 0 ? wq : which == 1 ? wk : wv) + (size_t)l * DM * DM;
        const size_t doff = (size_t)l * QS * DM + (size_t)which * DM * DM;
        dh = g_wqkv_hi + doff; dl = g_wqkv_lo + doff;
    } else if (bid < 57344) {
        const int r = bid - 24576;
        const int l = r >> 12;
        const int tl = r & 4095;
        K = DM; N = DFF;
        n0 = (tl & 127) * 32; k0 = (tl >> 7) * 32;
        src = w1 + (size_t)l * DM * DFF;
        dh = g_w1_hi + (size_t)l * DM * DFF; dl = g_w1_lo + (size_t)l * DM * DFF;
    } else {
        const int r = bid - 57344;
        const int l = r >> 12;
        const int tl = r & 4095;
        K = DFF; N = DM;
        n0 = (tl & 31) * 32; k0 = (tl >> 5) * 32;
        src = w2 + (size_t)l * DM * DFF;
        dh = g_w2_hi + (size_t)l * DM * DFF; dl = g_w2_lo + (size_t)l * DM * DFF;
    }

    const int lx = t & 31, ly = t >> 5;
#pragma unroll
    for (int i = 0; i < 4; i++) {
        const int kr = ly + i * 8;
        tile[kr][lx] = src[(size_t)(k0 + kr) * N + n0 + lx];
    }
    __syncthreads();

    const int kp = t & 15;
#pragma unroll
    for (int p = 0; p < 2; p++) {
        const int n = (t >> 4) + p * 16;
        const float v0 = tile[2 * kp][n], v1 = tile[2 * kp + 1][n];
        __half h0, l0h, h1, l1h;
        split_h(v0, h0, l0h); split_h(v1, h1, l1h);
        const size_t o = (size_t)(n0 + n) * K + k0 + 2 * kp;
        *(__half2*)(dh + o) = __halves2half2(h0, h1);
        *(__half2*)(dl + o) = __halves2half2(l0h, l1h);
    }
}

// ---------------- split-fp16 GEMM via mma.sync (HMMA) ----------------
#define MM_STAGE 32768           // Ah 8K | Al 8K | Bh 8K | Bl 8K
#define MM_NSTG  4
#define MM_SMEM  (MM_NSTG*MM_STAGE)

template<int EPI>
__global__ __launch_bounds__(256, 1) void mm_kernel(
    const __half* __restrict__ Ah, const __half* __restrict__ Al,
    const __half* __restrict__ Bh, const __half* __restrict__ Bl,
    const float* __restrict__ bias,
    float* __restrict__ Cf, __half* __restrict__ Ch, __half* __restrict__ Cl,
    int M, int N, int K)
{
    extern __shared__ char smem[];
    const uint32_t sb = smem_u32(smem);
    const int t = threadIdx.x, lane = t & 31, wid = t >> 5;
    const int n0 = blockIdx.x * 128, m0 = blockIdx.y * 128;
    const int wm = (wid >> 1) * 32, wn = (wid & 1) * 64;

    const int row0 = t >> 2, ch0 = t & 3;
    const uint32_t so0 = tile_off(row0, ch0 * 8);

    float acc[2][8][4];
    uint32_t acc16[2][8][2];
#pragma unroll
    for (int mt = 0; mt < 2; mt++)
#pragma unroll
        for (int nt = 0; nt < 8; nt++) {
#pragma unroll
            for (int e = 0; e < 4; e++) acc[mt][nt][e] = 0.f;
            acc16[mt][nt][0] = 0u; acc16[mt][nt][1] = 0u;
        }

    const int nst = K >> 5;

    auto LOAD_STAGE = [&](int stage, int kt) {
        const uint32_t sa = sb + stage * MM_STAGE;
        const size_t kof = (size_t)kt * 32 + ch0 * 8;
#pragma unroll
        for (int i = 0; i < 2; i++) {
            const int row = row0 + i * 64;
            const uint32_t so = sa + so0 + i * 4096;
            const size_t ga = (size_t)(m0 + row) * K + kof;
            const size_t gb = (size_t)(n0 + row) * K + kof;
            CP_ASYNC16(so,         Ah + ga);
            CP_ASYNC16(so +  8192, Al + ga);
            CP_ASYNC16(so + 16384, Bh + gb);
            CP_ASYNC16(so + 24576, Bl + gb);
        }
    };

    auto COMPUTE = [&](int stage) {
        const uint32_t sa = sb + stage * MM_STAGE;
#pragma unroll
        for (int ks = 0; ks < 2; ks++) {
            const int k0 = ks * 16;
            uint32_t ahf[2][4], alf[2][4], bhf[8][2], blf[8][2];
#pragma unroll
            for (int mt = 0; mt < 2; mt++) {
                const int r = wm + mt * 16 + (lane & 7) + ((lane >> 3) & 1) * 8;
                const int c = k0 + (lane >> 4) * 8;
                const uint32_t off = tile_off(r, c);
                ldsm4(ahf[mt], sa + off);
                ldsm4(alf[mt], sa + 8192 + off);
            }
#pragma unroll
            for (int g = 0; g < 4; g++) {
                const int r = wn + g * 16 + (lane & 7) + (lane >> 4) * 8;
                const int c = k0 + ((lane >> 3) & 1) * 8;
                const uint32_t off = tile_off(r, c);
                uint32_t tmp[4];
                ldsm4(tmp, sa + 16384 + off);
                bhf[g*2][0] = tmp[0]; bhf[g*2][1] = tmp[1];
                bhf[g*2+1][0] = tmp[2]; bhf[g*2+1][1] = tmp[3];
                ldsm4(tmp, sa + 24576 + off);
                blf[g*2][0] = tmp[0]; blf[g*2][1] = tmp[1];
                blf[g*2+1][0] = tmp[2]; blf[g*2+1][1] = tmp[3];
            }
#pragma unroll
            for (int mt = 0; mt < 2; mt++)
#pragma unroll
                for (int nt = 0; nt < 8; nt++) mma16816(acc[mt][nt], ahf[mt], bhf[nt]);
#pragma unroll
            for (int mt = 0; mt < 2; mt++)
#pragma unroll
                for (int nt = 0; nt < 8; nt++) mma16816h(acc16[mt][nt], ahf[mt], blf[nt]);
#pragma unroll
            for (int mt = 0; mt < 2; mt++)
#pragma unroll
                for (int nt = 0; nt < 8; nt++) mma16816h(acc16[mt][nt], alf[mt], bhf[nt]);
        }
    };

    LOAD_STAGE(0, 0); CP_COMMIT();
    LOAD_STAGE(1, 1); CP_COMMIT();
    LOAD_STAGE(2, 2); CP_COMMIT();

#pragma unroll 1
    for (int kt = 0; kt < nst; kt++) {
        if (kt + 3 < nst) { CP_WAIT(2); } else { CP_WAIT(0); }
        __syncthreads();
        if (kt + 3 < nst) { LOAD_STAGE((kt + 3) & 3, kt + 3); CP_COMMIT(); }
        COMPUTE(kt & 3);
    }

#pragma unroll
    for (int mt = 0; mt < 2; mt++) {
        const int r0 = m0 + wm + mt * 16 + (lane >> 2);
#pragma unroll
        for (int nt = 0; nt < 8; nt++) {
            const int col = n0 + wn + nt * 8 + (lane & 3) * 2;
            const float2 c01 = __half22float2(*(__half2*)&acc16[mt][nt][0]);
            const float2 c23 = __half22float2(*(__half2*)&acc16[mt][nt][1]);
            float v0 = acc[mt][nt][0] + c01.x, v1 = acc[mt][nt][1] + c01.y;
            float v2 = acc[mt][nt][2] + c23.x, v3 = acc[mt][nt][3] + c23.y;
            if (EPI == 0) {
                *(float2*)(Cf + (size_t)r0 * N + col)       = make_float2(v0, v1);
                *(float2*)(Cf + (size_t)(r0 + 8) * N + col) = make_float2(v2, v3);
            } else if (EPI == 2) {
                const float b0 = bias[col], b1 = bias[col + 1];
                *(float2*)(Cf + (size_t)r0 * N + col)       = make_float2(v0 + b0, v1 + b1);
                *(float2*)(Cf + (size_t)(r0 + 8) * N + col) = make_float2(v2 + b0, v3 + b1);
            } else if (EPI == 1) {
                const float b0 = bias[col], b1 = bias[col + 1];
                float s0 = selu_f(v0 + b0), s1 = selu_f(v1 + b1);
                float s2 = selu_f(v2 + b0), s3 = selu_f(v3 + b1);
                __half h0, l0, h1, l1;
                split_h(s0, h0, l0); split_h(s1, h1, l1);
                *(__half2*)(Ch + (size_t)r0 * N + col) = __halves2half2(h0, h1);
                *(__half2*)(Cl + (size_t)r0 * N + col) = __halves2half2(l0, l1);
                split_h(s2, h0, l0); split_h(s3, h1, l1);
                *(__half2*)(Ch + (size_t)(r0 + 8) * N + col) = __halves2half2(h0, h1);
                *(__half2*)(Cl + (size_t)(r0 + 8) * N + col) = __halves2half2(l0, l1);
            } else {   // EPI == 3: qkv, q region scaled by 1/8, split fp16
                const float sc = (col < DM) ? 0.125f : 1.0f;
                float s0 = v0 * sc, s1 = v1 * sc, s2 = v2 * sc, s3 = v3 * sc;
                __half h0, l0, h1, l1;
                split_h(s0, h0, l0); split_h(s1, h1, l1);
                *(__half2*)(Ch + (size_t)r0 * N + col) = __halves2half2(h0, h1);
                *(__half2*)(Cl + (size_t)r0 * N + col) = __halves2half2(l0, l1);
                split_h(s2, h0, l0); split_h(s3, h1, l1);
                *(__half2*)(Ch + (size_t)(r0 + 8) * N + col) = __halves2half2(h0, h1);
                *(__half2*)(Cl + (size_t)(r0 + 8) * N + col) = __halves2half2(l0, l1);
            }
        }
    }
}

// ---------------- flash attention: split-fp16 HMMA ----------------
// 128 q-rows per 256-thread CTA (8 warps x 16 rows); kv tiles 64 rows.
// S = 3 passes (QhKh + QhKl + QlKh), PV = 1 pass (Ph*Vh).
// smem: Qh 16K | Ql 16K | 3 stages x (Kh 8K | Kl 8K | Vh 8K)
#define FA_KV_STG 24576
#define FA_SMEM   (32768 + 3*FA_KV_STG)

__global__ __launch_bounds__(256, 1) void flash_kernel(
    const __half* __restrict__ qkvh, const __half* __restrict__ qkvl,
    float* __restrict__ o)
{
    extern __shared__ __half fsm[];
    const uint32_t bQh = smem_u32(fsm);
    const uint32_t bQl = bQh + 16384;
    const uint32_t bKV = bQh + 32768;

    const int qt = gridDim.x - 1 - blockIdx.x;   // heavy tiles first, 0..15
    const int bh = blockIdx.y;
    const int b  = bh >> 4, hd = bh & 15;
    const size_t qoff = (size_t)b * SL * QS + hd * DHD;

    const int t = threadIdx.x, lane = t & 31, w = t >> 5;

    // Q load geometry: 4 chunks/thread over 128 rows
    int qrow[4]; uint32_t qso[4]; int qch[4];
#pragma unroll
    for (int i = 0; i < 4; i++) {
        int seg = t + i * 256;
        qrow[i] = seg >> 3;
        int ch = seg & 7;
        qso[i] = (uint32_t)(qrow[i] * 128 + ((ch ^ (qrow[i] & 7)) << 4));
        qch[i] = ch;
    }
    // KV load geometry: 2 chunks/thread over 64 rows
    int krow[2]; uint32_t kso[2]; int kch[2];
#pragma unroll
    for (int i = 0; i < 2; i++) {
        int seg = t + i * 256;
        krow[i] = seg >> 3;
        int ch = seg & 7;
        kso[i] = (uint32_t)(krow[i] * 128 + ((ch ^ (krow[i] & 7)) << 4));
        kch[i] = ch;
    }

    auto LOAD_KV = [&](int kt, int st) {
        const uint32_t s = bKV + st * FA_KV_STG;
#pragma unroll
        for (int i = 0; i < 2; i++) {
            const size_t gk = qoff + DM     + (size_t)(kt * 64 + krow[i]) * QS + kch[i] * 8;
            const size_t gv = qoff + 2 * DM + (size_t)(kt * 64 + krow[i]) * QS + kch[i] * 8;
            CP_ASYNC16(s         + kso[i], qkvh + gk);
            CP_ASYNC16(s +  8192 + kso[i], qkvl + gk);
            CP_ASYNC16(s + 16384 + kso[i], qkvh + gv);
        }
    };

    const int nkv = 2 * qt + 2;

    // prologue: Q, then kv tiles 0 and 1
#pragma unroll
    for (int i = 0; i < 4; i++) {
        const size_t g = qoff + (size_t)(qt * 128 + qrow[i]) * QS + qch[i] * 8;
        CP_ASYNC16(bQh + qso[i], qkvh + g);
        CP_ASYNC16(bQl + qso[i], qkvl + g);
    }
    CP_COMMIT();
    LOAD_KV(0, 0); CP_COMMIT();
    LOAD_KV(1, 1); CP_COMMIT();

    CP_WAIT(2);          // Q arrived
    __syncthreads();

    uint32_t qfh[4][4], qfl[4][4];
#pragma unroll
    for (int ks = 0; ks < 4; ks++) {
        const int r = w * 16 + (lane & 7) + ((lane >> 3) & 1) * 8;
        const int c = ks * 16 + (lane >> 4) * 8;
        const uint32_t off = fa_off(r, c);
        ldsm4(qfh[ks], bQh + off);
        ldsm4(qfl[ks], bQl + off);
    }

    float acc_o[8][4];
#pragma unroll
    for (int n = 0; n < 8; n++)
#pragma unroll
        for (int e = 0; e < 4; e++) acc_o[n][e] = 0.f;
    float m0 = -1e30f, m1 = -1e30f, l0 = 0.f, l1 = 0.f;

    const int gr0 = qt * 128 + w * 16 + (lane >> 2);
    const int gr1 = gr0 + 8;

#pragma unroll 1
    for (int kt = 0; kt < nkv; kt++) {
        const int cur = kt % 3;
        CP_WAIT(1);          // kv_kt present (kv_{kt+1} may be in flight)
        __syncthreads();     // all warps done with stage being overwritten next
        if (kt + 2 < nkv) { LOAD_KV(kt + 2, (kt + 2) % 3); CP_COMMIT(); }

        const uint32_t sKh = bKV + cur * FA_KV_STG;
        const uint32_t sKl = sKh + 8192;
        const uint32_t sVh = sKh + 16384;

        // ---- S = Q K^T (split, 3 passes) ----
        float s_[8][4];
#pragma unroll
        for (int n = 0; n < 8; n++)
#pragma unroll
            for (int e = 0; e < 4; e++) s_[n][e] = 0.f;

#pragma unroll
        for (int ks = 0; ks < 4; ks++) {
            const int k0 = ks * 16;
            uint32_t bhf[8][2], blf[8][2];
#pragma unroll
            for (int g = 0; g < 4; g++) {
                const int r = g * 16 + (lane & 7) + (lane >> 4) * 8;
                const int c = k0 + ((lane >> 3) & 1) * 8;
                const uint32_t off = fa_off(r, c);
                uint32_t tmp[4];
                ldsm4(tmp, sKh + off);
                bhf[g*2][0] = tmp[0]; bhf[g*2][1] = tmp[1];
                bhf[g*2+1][0] = tmp[2]; bhf[g*2+1][1] = tmp[3];
                ldsm4(tmp, sKl + off);
                blf[g*2][0] = tmp[0]; blf[g*2][1] = tmp[1];
                blf[g*2+1][0] = tmp[2]; blf[g*2+1][1] = tmp[3];
            }
#pragma unroll
            for (int n = 0; n < 8; n++) mma16816(s_[n], qfh[ks], bhf[n]);
#pragma unroll
            for (int n = 0; n < 8; n++) mma16816(s_[n], qfh[ks], blf[n]);
#pragma unroll
            for (int n = 0; n < 8; n++) mma16816(s_[n], qfl[ks], bhf[n]);
        }

        // ---- causal mask (only tiles overlapping the diagonal) ----
        if (kt >= 2 * qt) {
#pragma unroll
            for (int n = 0; n < 8; n++) {
                const int c = kt * 64 + n * 8 + (lane & 3) * 2;
                if (c     > gr0) s_[n][0] = -1e30f;
                if (c + 1 > gr0) s_[n][1] = -1e30f;
                if (c     > gr1) s_[n][2] = -1e30f;
                if (c + 1 > gr1) s_[n][3] = -1e30f;
            }
        }

        // ---- online softmax (P rounded to fp16) ----
        float mx0 = -1e30f, mx1 = -1e30f;
#pragma unroll
        for (int n = 0; n < 8; n++) {
            mx0 = fmaxf(mx0, fmaxf(s_[n][0], s_[n][1]));
            mx1 = fmaxf(mx1, fmaxf(s_[n][2], s_[n][3]));
        }
        mx0 = fmaxf(mx0, __shfl_xor_sync(0xffffffffu, mx0, 1));
        mx0 = fmaxf(mx0, __shfl_xor_sync(0xffffffffu, mx0, 2));
        mx1 = fmaxf(mx1, __shfl_xor_sync(0xffffffffu, mx1, 1));
        mx1 = fmaxf(mx1, __shfl_xor_sync(0xffffffffu, mx1, 2));
        const float mn0 = fmaxf(m0, mx0), mn1 = fmaxf(m1, mx1);
        const float sc0 = __expf(m0 - mn0), sc1 = __expf(m1 - mn1);
        m0 = mn0; m1 = mn1;

        uint32_t pah[4][4];
        float rs0 = 0.f, rs1 = 0.f;
#pragma unroll
        for (int n = 0; n < 8; n++) {
            float p0 = __expf(s_[n][0] - mn0);
            float p1 = __expf(s_[n][1] - mn0);
            float p2 = __expf(s_[n][2] - mn1);
            float p3 = __expf(s_[n][3] - mn1);
            rs0 += p0 + p1; rs1 += p2 + p3;
            __half2 h01 = __floats2half2_rn(p0, p1);
            __half2 h23 = __floats2half2_rn(p2, p3);
            const int kc = n >> 1, wh = (n & 1) * 2;
            pah[kc][wh    ] = *(uint32_t*)&h01;
            pah[kc][wh + 1] = *(uint32_t*)&h23;
        }
        rs0 += __shfl_xor_sync(0xffffffffu, rs0, 1);
        rs0 += __shfl_xor_sync(0xffffffffu, rs0, 2);
        rs1 += __shfl_xor_sync(0xffffffffu, rs1, 1);
        rs1 += __shfl_xor_sync(0xffffffffu, rs1, 2);
        l0 = l0 * sc0 + rs0;
        l1 = l1 * sc1 + rs1;

#pragma unroll
        for (int n = 0; n < 8; n++) {
            acc_o[n][0] *= sc0; acc_o[n][1] *= sc0;
            acc_o[n][2] *= sc1; acc_o[n][3] *= sc1;
        }

        // ---- O += P * Vh (1 pass) ----
#pragma unroll
        for (int kc = 0; kc < 4; kc++) {
#pragma unroll
            for (int g = 0; g < 4; g++) {
                const int r = kc * 16 + (lane & 7) + ((lane >> 3) & 1) * 8;
                const int c = g * 16 + (lane >> 4) * 8;
                const uint32_t off = fa_off(r, c);
                uint32_t tvh[4];
                ldsm4t(tvh, sVh + off);
                mma16816(acc_o[2*g],   pah[kc], tvh);
                mma16816(acc_o[2*g+1], pah[kc], tvh + 2);
            }
        }
    }

    const float i0 = 1.f / l0, i1 = 1.f / l1;
    float* ob = o + (size_t)b * SL * DM + hd * DHD;
#pragma unroll
    for (int n = 0; n < 8; n++) {
        const int c = n * 8 + (lane & 3) * 2;
        *(float2*)(ob + (size_t)gr0 * DM + c) = make_float2(acc_o[n][0] * i0, acc_o[n][1] * i0);
        *(float2*)(ob + (size_t)gr1 * DM + c) = make_float2(acc_o[n][2] * i1, acc_o[n][3] * i1);
    }
}

// ---------------- out = LayerNorm(a + r) * g + b  (+ split) ----------------
__global__ void resid_ln_kernel(const float* __restrict__ a, const float* __restrict__ r,
                                const float* __restrict__ g, const float* __restrict__ bb,
                                float* __restrict__ out)
{
    int row = blockIdx.x;
    int t = threadIdx.x;
    const float* pa = a + (size_t)row * DM;
    const float* pr = r + (size_t)row * DM;
    float v[4];
    float s = 0.f, s2 = 0.f;
#pragma unroll
    for (int i = 0; i < 4; i++) {
        float x = pa[t + i * 256] + pr[t + i * 256];
        v[i] = x; s += x; s2 += x * x;
    }
#pragma unroll
    for (int off = 16; off > 0; off >>= 1) {
        s  += __shfl_down_sync(0xffffffffu, s,  off);
        s2 += __shfl_down_sync(0xffffffffu, s2, off);
    }
    __shared__ float ws[8], ws2[8];
    __shared__ float sm_mean, sm_rstd;
    int w = t >> 5, lane = t & 31;
    if (lane == 0) { ws[w] = s; ws2[w] = s2; }
    __syncthreads();
    if (t == 0) {
        float S = 0.f, S2 = 0.f;
#pragma unroll
        for (int i = 0; i < 8; i++) { S += ws[i]; S2 += ws2[i]; }
        float mean = S * (1.f / DM);
        float var  = S2 * (1.f / DM) - mean * mean;
        sm_mean = mean;
        sm_rstd = rsqrtf(var + 1e-5f);
    }
    __syncthreads();
    float mean = sm_mean, rstd = sm_rstd;
#pragma unroll
    for (int i = 0; i < 4; i++) {
        int col = t + i * 256;
        float y = (v[i] - mean) * rstd * g[col] + bb[col];
        size_t idx = (size_t)row * DM + col;
        out[idx] = y;
        split_h(y, g_h_hi[idx], g_h_lo[idx]);
    }
}

__global__ void copy_out_kernel(float* __restrict__ out) {
    int i = blockIdx.x * 256 + threadIdx.x;
    out[i] = g_h[i];
}

// ---------------- launch ----------------
extern "C" void kernel_launch(void* const* d_in, const int* in_sizes, int n_in,
                              void* d_out, int out_size)
{
    const float* x    = (const float*)d_in[0];
    const float* pe   = (const float*)d_in[1];
    const float* wq   = (const float*)d_in[2];
    const float* wk   = (const float*)d_in[3];
    const float* wv   = (const float*)d_in[4];
    const float* ln1g = (const float*)d_in[5];
    const float* ln1b = (const float*)d_in[6];
    const float* w1   = (const float*)d_in[7];
    const float* b1   = (const float*)d_in[8];
    const float* w2   = (const float*)d_in[9];
    const float* b2   = (const float*)d_in[10];
    const float* ln2g = (const float*)d_in[11];
    const float* ln2b = (const float*)d_in[12];

    float *ph, *po;
    cudaGetSymbolAddress((void**)&ph, g_h);
    cudaGetSymbolAddress((void**)&po, g_o);
    __half *phh, *phl, *pfh, *pfl, *pqh, *pql;
    cudaGetSymbolAddress((void**)&phh, g_h_hi);
    cudaGetSymbolAddress((void**)&phl, g_h_lo);
    cudaGetSymbolAddress((void**)&pfh, g_ff_hi);
    cudaGetSymbolAddress((void**)&pfl, g_ff_lo);
    cudaGetSymbolAddress((void**)&pqh, g_qkv_hi);
    cudaGetSymbolAddress((void**)&pql, g_qkv_lo);
    __half *wqkvh, *wqkvl, *w1h, *w1l, *w2h, *w2l;
    cudaGetSymbolAddress((void**)&wqkvh, g_wqkv_hi); cudaGetSymbolAddress((void**)&wqkvl, g_wqkv_lo);
    cudaGetSymbolAddress((void**)&w1h, g_w1_hi);     cudaGetSymbolAddress((void**)&w1l, g_w1_lo);
    cudaGetSymbolAddress((void**)&w2h, g_w2_hi);     cudaGetSymbolAddress((void**)&w2l, g_w2_lo);

    cudaFuncSetAttribute(mm_kernel<1>, cudaFuncAttributeMaxDynamicSharedMemorySize, MM_SMEM);
    cudaFuncSetAttribute(mm_kernel<2>, cudaFuncAttributeMaxDynamicSharedMemorySize, MM_SMEM);
    cudaFuncSetAttribute(mm_kernel<3>, cudaFuncAttributeMaxDynamicSharedMemorySize, MM_SMEM);
    cudaFuncSetAttribute(flash_kernel, cudaFuncAttributeMaxDynamicSharedMemorySize, FA_SMEM);

    transpose_split_all_kernel<<<TR_GRID, 256>>>(wq, wk, wv, w1, w2);
    add_pe_kernel<<<NTOK * DM / 256, 256>>>(x, pe);

    for (int l = 0; l < NLAYER; l++) {
        const size_t woq = (size_t)l * QS * DM;
        const size_t wo1 = (size_t)l * DM * DFF;

        mm_kernel<3><<<dim3(QS / 128, NTOK / 128), 256, MM_SMEM>>>(
            phh, phl, wqkvh + woq, wqkvl + woq, nullptr,
            nullptr, pqh, pql, NTOK, QS, DM);

        flash_kernel<<<dim3(SL / 128, NB * NH), 256, FA_SMEM>>>(pqh, pql, po);

        resid_ln_kernel<<<NTOK, 256>>>(ph, po, ln1g + (size_t)l * DM, ln1b + (size_t)l * DM, ph);

        mm_kernel<1><<<dim3(DFF / 128, NTOK / 128), 256, MM_SMEM>>>(
            phh, phl, w1h + wo1, w1l + wo1, b1 + (size_t)l * DFF,
            nullptr, pfh, pfl, NTOK, DFF, DM);
        mm_kernel<2><<<dim3(DM / 128, NTOK / 128), 256, MM_SMEM>>>(
            pfh, pfl, w2h + wo1, w2l + wo1, b2 + (size_t)l * DM,
            po, nullptr, nullptr, NTOK, DM, DFF);

        resid_ln_kernel<<<NTOK, 256>>>(ph, po, ln2g + (size_t)l * DM, ln2b + (size_t)l * DM, ph);
    }

    copy_out_kernel<<<NTOK * DM / 256, 256>>>((float*)d_out);
}

// round 13
// speedup vs baseline: 3.1206x; 1.0376x over previous
#include <cuda_runtime.h>
#include <cuda_fp16.h>
#include <cstdint>
#include <math.h>

#define NB 2
#define SL 2048
#define DM 1024
#define NH 16
#define DHD 64
#define NLAYER 8
#define DFF 4096
#define NTOK (NB*SL)
#define QS (3*DM)          // fused qkv row stride

// ---------------- scratch (static device globals; no allocs) ----------------
__device__ __align__(256) float g_h  [(size_t)NTOK*DM];
__device__ __align__(256) float g_o  [(size_t)NTOK*DM];

// split-fp16 activations
__device__ __align__(256) __half g_h_hi[(size_t)NTOK*DM];
__device__ __align__(256) __half g_h_lo[(size_t)NTOK*DM];
__device__ __align__(256) __half g_ff_hi[(size_t)NTOK*DFF];
__device__ __align__(256) __half g_ff_lo[(size_t)NTOK*DFF];
__device__ __align__(256) __half g_qkv_hi[(size_t)NTOK*QS];
__device__ __align__(256) __half g_qkv_lo[(size_t)NTOK*QS];

// transposed + split weights: [N, K] fp16 hi/lo per layer (qkv fused: [3072,1024])
__device__ __align__(256) __half g_wqkv_hi[(size_t)NLAYER*QS*DM], g_wqkv_lo[(size_t)NLAYER*QS*DM];
__device__ __align__(256) __half g_w1_hi[(size_t)NLAYER*DM*DFF],  g_w1_lo[(size_t)NLAYER*DM*DFF];
__device__ __align__(256) __half g_w2_hi[(size_t)NLAYER*DM*DFF],  g_w2_lo[(size_t)NLAYER*DM*DFF];

// ---------------- helpers ----------------
__device__ __forceinline__ uint32_t smem_u32(const void* p) {
    uint32_t a;
    asm("{ .reg .u64 t; cvta.to.shared.u64 t, %1; cvt.u32.u64 %0, t; }" : "=r"(a) : "l"(p));
    return a;
}
#define CP_ASYNC16(dst, src) asm volatile("cp.async.cg.shared.global [%0], [%1], 16;" :: "r"(dst), "l"(src))
#define CP_COMMIT()          asm volatile("cp.async.commit_group;" ::: "memory")
#define CP_WAIT(n)           asm volatile("cp.async.wait_group %0;" :: "n"(n) : "memory")

__device__ __forceinline__ void ldsm4(uint32_t* r, uint32_t a) {
    asm volatile("ldmatrix.sync.aligned.m8n8.x4.shared.b16 {%0,%1,%2,%3}, [%4];"
        : "=r"(r[0]), "=r"(r[1]), "=r"(r[2]), "=r"(r[3]) : "r"(a));
}
__device__ __forceinline__ void ldsm4t(uint32_t* r, uint32_t a) {
    asm volatile("ldmatrix.sync.aligned.m8n8.x4.trans.shared.b16 {%0,%1,%2,%3}, [%4];"
        : "=r"(r[0]), "=r"(r[1]), "=r"(r[2]), "=r"(r[3]) : "r"(a));
}
__device__ __forceinline__ void mma16816(float* c, const uint32_t* a, const uint32_t* b) {
    asm volatile("mma.sync.aligned.m16n8k16.row.col.f32.f16.f16.f32 "
        "{%0,%1,%2,%3}, {%4,%5,%6,%7}, {%8,%9}, {%0,%1,%2,%3};"
        : "+f"(c[0]), "+f"(c[1]), "+f"(c[2]), "+f"(c[3])
        : "r"(a[0]), "r"(a[1]), "r"(a[2]), "r"(a[3]), "r"(b[0]), "r"(b[1]));
}
// f16-accumulate variant (corrections): D,C are 2 regs of half2
__device__ __forceinline__ void mma16816h(uint32_t* c, const uint32_t* a, const uint32_t* b) {
    asm volatile("mma.sync.aligned.m16n8k16.row.col.f16.f16.f16.f16 "
        "{%0,%1}, {%2,%3,%4,%5}, {%6,%7}, {%0,%1};"
        : "+r"(c[0]), "+r"(c[1])
        : "r"(a[0]), "r"(a[1]), "r"(a[2]), "r"(a[3]), "r"(b[0]), "r"(b[1]));
}
__device__ __forceinline__ void split_h(float v, __half& hi, __half& lo) {
    hi = __float2half_rn(v);
    lo = __float2half_rn(v - __half2float(hi));
}
__device__ __forceinline__ float selu_f(float v) {
    return 1.0507009873554805f * (v > 0.f ? v : 1.6732632423543772f * expm1f(v));
}

// GEMM smem tile: 128 rows x 32 fp16 = 64B/row, 4 x 16B chunks; chunk ^= (row>>1)&3
__device__ __forceinline__ uint32_t tile_off(int row, int colElem) {
    return (uint32_t)(row * 64 + ((((colElem >> 3) & 3) ^ ((row >> 1) & 3)) << 4));
}
// flash smem tile: rows x 64 fp16 = 128B/row, 8 x 16B chunks; chunk ^= row&7
__device__ __forceinline__ uint32_t fa_off(int row, int colElem) {
    return (uint32_t)(row * 128 + ((((colElem >> 3) & 7) ^ (row & 7)) << 4));
}

// ---------------- h = x + pe (+ split) ----------------
__global__ void add_pe_kernel(const float* __restrict__ x, const float* __restrict__ pe) {
    int i = blockIdx.x * 256 + threadIdx.x;
    float v = x[i] + pe[i & (SL*DM - 1)];
    g_h[i] = v;
    split_h(v, g_h_hi[i], g_h_lo[i]);
}

// ---------------- fused weight transpose + split (ALL weights, one launch) ----------------
#define TR_GRID 90112
__global__ __launch_bounds__(256) void transpose_split_all_kernel(
    const float* __restrict__ wq, const float* __restrict__ wk, const float* __restrict__ wv,
    const float* __restrict__ w1, const float* __restrict__ w2)
{
    __shared__ float tile[32][33];
    const int bid = blockIdx.x;
    const int t = threadIdx.x;

    const float* src; __half* dh; __half* dl;
    int K, N, n0, k0;
    if (bid < 24576) {
        const int which = bid >> 13;
        const int r = bid & 8191;
        const int l = r >> 10;
        const int tl = r & 1023;
        K = DM; N = DM;
        n0 = (tl & 31) * 32; k0 = (tl >> 5) * 32;
        src = (which == 0 ? wq : which == 1 ? wk : wv) + (size_t)l * DM * DM;
        const size_t doff = (size_t)l * QS * DM + (size_t)which * DM * DM;
        dh = g_wqkv_hi + doff; dl = g_wqkv_lo + doff;
    } else if (bid < 57344) {
        const int r = bid - 24576;
        const int l = r >> 12;
        const int tl = r & 4095;
        K = DM; N = DFF;
        n0 = (tl & 127) * 32; k0 = (tl >> 7) * 32;
        src = w1 + (size_t)l * DM * DFF;
        dh = g_w1_hi + (size_t)l * DM * DFF; dl = g_w1_lo + (size_t)l * DM * DFF;
    } else {
        const int r = bid - 57344;
        const int l = r >> 12;
        const int tl = r & 4095;
        K = DFF; N = DM;
        n0 = (tl & 31) * 32; k0 = (tl >> 5) * 32;
        src = w2 + (size_t)l * DM * DFF;
        dh = g_w2_hi + (size_t)l * DM * DFF; dl = g_w2_lo + (size_t)l * DM * DFF;
    }

    const int lx = t & 31, ly = t >> 5;
#pragma unroll
    for (int i = 0; i < 4; i++) {
        const int kr = ly + i * 8;
        tile[kr][lx] = src[(size_t)(k0 + kr) * N + n0 + lx];
    }
    __syncthreads();

    const int kp = t & 15;
#pragma unroll
    for (int p = 0; p < 2; p++) {
        const int n = (t >> 4) + p * 16;
        const float v0 = tile[2 * kp][n], v1 = tile[2 * kp + 1][n];
        __half h0, l0h, h1, l1h;
        split_h(v0, h0, l0h); split_h(v1, h1, l1h);
        const size_t o = (size_t)(n0 + n) * K + k0 + 2 * kp;
        *(__half2*)(dh + o) = __halves2half2(h0, h1);
        *(__half2*)(dl + o) = __halves2half2(l0h, l1h);
    }
}

// ---------------- split-fp16 GEMM via mma.sync (HMMA) ----------------
#define MM_STAGE 32768           // Ah 8K | Al 8K | Bh 8K | Bl 8K
#define MM_NSTG  4
#define MM_SMEM  (MM_NSTG*MM_STAGE)

template<int EPI>
__global__ __launch_bounds__(256, 1) void mm_kernel(
    const __half* __restrict__ Ah, const __half* __restrict__ Al,
    const __half* __restrict__ Bh, const __half* __restrict__ Bl,
    const float* __restrict__ bias,
    float* __restrict__ Cf, __half* __restrict__ Ch, __half* __restrict__ Cl,
    int M, int N, int K)
{
    extern __shared__ char smem[];
    const uint32_t sb = smem_u32(smem);
    const int t = threadIdx.x, lane = t & 31, wid = t >> 5;
    const int n0 = blockIdx.x * 128, m0 = blockIdx.y * 128;
    const int wm = (wid >> 1) * 32, wn = (wid & 1) * 64;

    const int row0 = t >> 2, ch0 = t & 3;
    const uint32_t so0 = tile_off(row0, ch0 * 8);

    float acc[2][8][4];
    uint32_t acc16[2][8][2];
#pragma unroll
    for (int mt = 0; mt < 2; mt++)
#pragma unroll
        for (int nt = 0; nt < 8; nt++) {
#pragma unroll
            for (int e = 0; e < 4; e++) acc[mt][nt][e] = 0.f;
            acc16[mt][nt][0] = 0u; acc16[mt][nt][1] = 0u;
        }

    const int nst = K >> 5;

    auto LOAD_STAGE = [&](int stage, int kt) {
        const uint32_t sa = sb + stage * MM_STAGE;
        const size_t kof = (size_t)kt * 32 + ch0 * 8;
#pragma unroll
        for (int i = 0; i < 2; i++) {
            const int row = row0 + i * 64;
            const uint32_t so = sa + so0 + i * 4096;
            const size_t ga = (size_t)(m0 + row) * K + kof;
            const size_t gb = (size_t)(n0 + row) * K + kof;
            CP_ASYNC16(so,         Ah + ga);
            CP_ASYNC16(so +  8192, Al + ga);
            CP_ASYNC16(so + 16384, Bh + gb);
            CP_ASYNC16(so + 24576, Bl + gb);
        }
    };

    auto COMPUTE = [&](int stage) {
        const uint32_t sa = sb + stage * MM_STAGE;
#pragma unroll
        for (int ks = 0; ks < 2; ks++) {
            const int k0 = ks * 16;
            uint32_t ahf[2][4], alf[2][4], bhf[8][2], blf[8][2];
#pragma unroll
            for (int mt = 0; mt < 2; mt++) {
                const int r = wm + mt * 16 + (lane & 7) + ((lane >> 3) & 1) * 8;
                const int c = k0 + (lane >> 4) * 8;
                const uint32_t off = tile_off(r, c);
                ldsm4(ahf[mt], sa + off);
                ldsm4(alf[mt], sa + 8192 + off);
            }
#pragma unroll
            for (int g = 0; g < 4; g++) {
                const int r = wn + g * 16 + (lane & 7) + (lane >> 4) * 8;
                const int c = k0 + ((lane >> 3) & 1) * 8;
                const uint32_t off = tile_off(r, c);
                uint32_t tmp[4];
                ldsm4(tmp, sa + 16384 + off);
                bhf[g*2][0] = tmp[0]; bhf[g*2][1] = tmp[1];
                bhf[g*2+1][0] = tmp[2]; bhf[g*2+1][1] = tmp[3];
                ldsm4(tmp, sa + 24576 + off);
                blf[g*2][0] = tmp[0]; blf[g*2][1] = tmp[1];
                blf[g*2+1][0] = tmp[2]; blf[g*2+1][1] = tmp[3];
            }
#pragma unroll
            for (int mt = 0; mt < 2; mt++)
#pragma unroll
                for (int nt = 0; nt < 8; nt++) mma16816(acc[mt][nt], ahf[mt], bhf[nt]);
#pragma unroll
            for (int mt = 0; mt < 2; mt++)
#pragma unroll
                for (int nt = 0; nt < 8; nt++) mma16816h(acc16[mt][nt], ahf[mt], blf[nt]);
#pragma unroll
            for (int mt = 0; mt < 2; mt++)
#pragma unroll
                for (int nt = 0; nt < 8; nt++) mma16816h(acc16[mt][nt], alf[mt], bhf[nt]);
        }
    };

    LOAD_STAGE(0, 0); CP_COMMIT();
    LOAD_STAGE(1, 1); CP_COMMIT();
    LOAD_STAGE(2, 2); CP_COMMIT();

#pragma unroll 1
    for (int kt = 0; kt < nst; kt++) {
        if (kt + 3 < nst) { CP_WAIT(2); } else { CP_WAIT(0); }
        __syncthreads();
        if (kt + 3 < nst) { LOAD_STAGE((kt + 3) & 3, kt + 3); CP_COMMIT(); }
        COMPUTE(kt & 3);
    }

#pragma unroll
    for (int mt = 0; mt < 2; mt++) {
        const int r0 = m0 + wm + mt * 16 + (lane >> 2);
#pragma unroll
        for (int nt = 0; nt < 8; nt++) {
            const int col = n0 + wn + nt * 8 + (lane & 3) * 2;
            const float2 c01 = __half22float2(*(__half2*)&acc16[mt][nt][0]);
            const float2 c23 = __half22float2(*(__half2*)&acc16[mt][nt][1]);
            float v0 = acc[mt][nt][0] + c01.x, v1 = acc[mt][nt][1] + c01.y;
            float v2 = acc[mt][nt][2] + c23.x, v3 = acc[mt][nt][3] + c23.y;
            if (EPI == 0) {
                *(float2*)(Cf + (size_t)r0 * N + col)       = make_float2(v0, v1);
                *(float2*)(Cf + (size_t)(r0 + 8) * N + col) = make_float2(v2, v3);
            } else if (EPI == 2) {
                const float b0 = bias[col], b1 = bias[col + 1];
                *(float2*)(Cf + (size_t)r0 * N + col)       = make_float2(v0 + b0, v1 + b1);
                *(float2*)(Cf + (size_t)(r0 + 8) * N + col) = make_float2(v2 + b0, v3 + b1);
            } else if (EPI == 1) {
                const float b0 = bias[col], b1 = bias[col + 1];
                float s0 = selu_f(v0 + b0), s1 = selu_f(v1 + b1);
                float s2 = selu_f(v2 + b0), s3 = selu_f(v3 + b1);
                __half h0, l0, h1, l1;
                split_h(s0, h0, l0); split_h(s1, h1, l1);
                *(__half2*)(Ch + (size_t)r0 * N + col) = __halves2half2(h0, h1);
                *(__half2*)(Cl + (size_t)r0 * N + col) = __halves2half2(l0, l1);
                split_h(s2, h0, l0); split_h(s3, h1, l1);
                *(__half2*)(Ch + (size_t)(r0 + 8) * N + col) = __halves2half2(h0, h1);
                *(__half2*)(Cl + (size_t)(r0 + 8) * N + col) = __halves2half2(l0, l1);
            } else {   // EPI == 3: qkv, q region scaled by 1/8, split fp16
                const float sc = (col < DM) ? 0.125f : 1.0f;
                float s0 = v0 * sc, s1 = v1 * sc, s2 = v2 * sc, s3 = v3 * sc;
                __half h0, l0, h1, l1;
                split_h(s0, h0, l0); split_h(s1, h1, l1);
                *(__half2*)(Ch + (size_t)r0 * N + col) = __halves2half2(h0, h1);
                *(__half2*)(Cl + (size_t)r0 * N + col) = __halves2half2(l0, l1);
                split_h(s2, h0, l0); split_h(s3, h1, l1);
                *(__half2*)(Ch + (size_t)(r0 + 8) * N + col) = __halves2half2(h0, h1);
                *(__half2*)(Cl + (size_t)(r0 + 8) * N + col) = __halves2half2(l0, l1);
            }
        }
    }
}

// ---------------- flash attention: split-fp16 HMMA, high-occupancy ----------------
// 64 q-rows per 128-thread CTA (4 warps x 16 rows); kv tiles 64 rows.
// S = 2 passes (QhKh + QlKh; K fp16-rounded), PV = 1 pass (Ph*Vh).
// smem 64KB: Qh 8K | Ql 8K | 3 stages x (Kh 8K | Vh 8K); 3 CTAs/SM.
#define FA_KV_STG 16384
#define FA_SMEM   (16384 + 3*FA_KV_STG)

__global__ __launch_bounds__(128, 3) void flash_kernel(
    const __half* __restrict__ qkvh, const __half* __restrict__ qkvl,
    float* __restrict__ o)
{
    extern __shared__ __half fsm[];
    const uint32_t bQh = smem_u32(fsm);
    const uint32_t bQl = bQh + 8192;
    const uint32_t bKV = bQh + 16384;

    const int qt = gridDim.x - 1 - blockIdx.x;   // heavy tiles first, 0..31
    const int bh = blockIdx.y;
    const int b  = bh >> 4, hd = bh & 15;
    const size_t qoff = (size_t)b * SL * QS + hd * DHD;

    const int t = threadIdx.x, lane = t & 31, w = t >> 5;

    // load geometry: 4 chunks/thread over a 64-row tile (8KB buffer)
    int lrow[4]; uint32_t lso[4]; int lch[4];
#pragma unroll
    for (int i = 0; i < 4; i++) {
        int seg = t + i * 128;
        lrow[i] = seg >> 3;
        int ch = seg & 7;
        lso[i] = (uint32_t)(lrow[i] * 128 + ((ch ^ (lrow[i] & 7)) << 4));
        lch[i] = ch;
    }

    auto LOAD_KV = [&](int kt, int st) {
        const uint32_t s = bKV + st * FA_KV_STG;
#pragma unroll
        for (int i = 0; i < 4; i++) {
            const size_t gk = qoff + DM     + (size_t)(kt * 64 + lrow[i]) * QS + lch[i] * 8;
            const size_t gv = qoff + 2 * DM + (size_t)(kt * 64 + lrow[i]) * QS + lch[i] * 8;
            CP_ASYNC16(s        + lso[i], qkvh + gk);
            CP_ASYNC16(s + 8192 + lso[i], qkvh + gv);
        }
    };

    // prologue: Q (hi+lo), then kv tiles 0 and 1
#pragma unroll
    for (int i = 0; i < 4; i++) {
        const size_t g = qoff + (size_t)(qt * 64 + lrow[i]) * QS + lch[i] * 8;
        CP_ASYNC16(bQh + lso[i], qkvh + g);
        CP_ASYNC16(bQl + lso[i], qkvl + g);
    }
    CP_COMMIT();
    LOAD_KV(0, 0); CP_COMMIT();
    if (qt >= 1) LOAD_KV(1, 1);
    CP_COMMIT();

    CP_WAIT(2);          // Q arrived
    __syncthreads();

    uint32_t qfh[4][4], qfl[4][4];
#pragma unroll
    for (int ks = 0; ks < 4; ks++) {
        const int r = w * 16 + (lane & 7) + ((lane >> 3) & 1) * 8;
        const int c = ks * 16 + (lane >> 4) * 8;
        const uint32_t off = fa_off(r, c);
        ldsm4(qfh[ks], bQh + off);
        ldsm4(qfl[ks], bQl + off);
    }

    float acc_o[8][4];
#pragma unroll
    for (int n = 0; n < 8; n++)
#pragma unroll
        for (int e = 0; e < 4; e++) acc_o[n][e] = 0.f;
    float m0 = -1e30f, m1 = -1e30f, l0 = 0.f, l1 = 0.f;

    const int gr0 = qt * 64 + w * 16 + (lane >> 2);
    const int gr1 = gr0 + 8;

#pragma unroll 1
    for (int kt = 0; kt <= qt; kt++) {
        const int cur = kt % 3;
        if (kt < qt) { CP_WAIT(1); } else { CP_WAIT(0); }
        __syncthreads();     // all warps done reading the stage being overwritten
        if (kt + 2 <= qt) { LOAD_KV(kt + 2, (kt + 2) % 3); CP_COMMIT(); }

        const uint32_t sKh = bKV + cur * FA_KV_STG;
        const uint32_t sVh = sKh + 8192;

        // ---- S = Q K^T (2 passes: Qh*Kh + Ql*Kh) ----
        float s_[8][4];
#pragma unroll
        for (int n = 0; n < 8; n++)
#pragma unroll
            for (int e = 0; e < 4; e++) s_[n][e] = 0.f;

#pragma unroll
        for (int ks = 0; ks < 4; ks++) {
            const int k0 = ks * 16;
            uint32_t bhf[8][2];
#pragma unroll
            for (int g = 0; g < 4; g++) {
                const int r = g * 16 + (lane & 7) + (lane >> 4) * 8;
                const int c = k0 + ((lane >> 3) & 1) * 8;
                const uint32_t off = fa_off(r, c);
                uint32_t tmp[4];
                ldsm4(tmp, sKh + off);
                bhf[g*2][0] = tmp[0]; bhf[g*2][1] = tmp[1];
                bhf[g*2+1][0] = tmp[2]; bhf[g*2+1][1] = tmp[3];
            }
#pragma unroll
            for (int n = 0; n < 8; n++) mma16816(s_[n], qfh[ks], bhf[n]);
#pragma unroll
            for (int n = 0; n < 8; n++) mma16816(s_[n], qfl[ks], bhf[n]);
        }

        // ---- causal mask on diagonal tile ----
        if (kt == qt) {
#pragma unroll
            for (int n = 0; n < 8; n++) {
                const int c = kt * 64 + n * 8 + (lane & 3) * 2;
                if (c     > gr0) s_[n][0] = -1e30f;
                if (c + 1 > gr0) s_[n][1] = -1e30f;
                if (c     > gr1) s_[n][2] = -1e30f;
                if (c + 1 > gr1) s_[n][3] = -1e30f;
            }
        }

        // ---- online softmax (P rounded to fp16) ----
        float mx0 = -1e30f, mx1 = -1e30f;
#pragma unroll
        for (int n = 0; n < 8; n++) {
            mx0 = fmaxf(mx0, fmaxf(s_[n][0], s_[n][1]));
            mx1 = fmaxf(mx1, fmaxf(s_[n][2], s_[n][3]));
        }
        mx0 = fmaxf(mx0, __shfl_xor_sync(0xffffffffu, mx0, 1));
        mx0 = fmaxf(mx0, __shfl_xor_sync(0xffffffffu, mx0, 2));
        mx1 = fmaxf(mx1, __shfl_xor_sync(0xffffffffu, mx1, 1));
        mx1 = fmaxf(mx1, __shfl_xor_sync(0xffffffffu, mx1, 2));
        const float mn0 = fmaxf(m0, mx0), mn1 = fmaxf(m1, mx1);
        const float sc0 = __expf(m0 - mn0), sc1 = __expf(m1 - mn1);
        m0 = mn0; m1 = mn1;

        uint32_t pah[4][4];
        float rs0 = 0.f, rs1 = 0.f;
#pragma unroll
        for (int n = 0; n < 8; n++) {
            float p0 = __expf(s_[n][0] - mn0);
            float p1 = __expf(s_[n][1] - mn0);
            float p2 = __expf(s_[n][2] - mn1);
            float p3 = __expf(s_[n][3] - mn1);
            rs0 += p0 + p1; rs1 += p2 + p3;
            __half2 h01 = __floats2half2_rn(p0, p1);
            __half2 h23 = __floats2half2_rn(p2, p3);
            const int kc = n >> 1, wh = (n & 1) * 2;
            pah[kc][wh    ] = *(uint32_t*)&h01;
            pah[kc][wh + 1] = *(uint32_t*)&h23;
        }
        rs0 += __shfl_xor_sync(0xffffffffu, rs0, 1);
        rs0 += __shfl_xor_sync(0xffffffffu, rs0, 2);
        rs1 += __shfl_xor_sync(0xffffffffu, rs1, 1);
        rs1 += __shfl_xor_sync(0xffffffffu, rs1, 2);
        l0 = l0 * sc0 + rs0;
        l1 = l1 * sc1 + rs1;

#pragma unroll
        for (int n = 0; n < 8; n++) {
            acc_o[n][0] *= sc0; acc_o[n][1] *= sc0;
            acc_o[n][2] *= sc1; acc_o[n][3] *= sc1;
        }

        // ---- O += P * Vh (1 pass) ----
#pragma unroll
        for (int kc = 0; kc < 4; kc++) {
#pragma unroll
            for (int g = 0; g < 4; g++) {
                const int r = kc * 16 + (lane & 7) + ((lane >> 3) & 1) * 8;
                const int c = g * 16 + (lane >> 4) * 8;
                const uint32_t off = fa_off(r, c);
                uint32_t tvh[4];
                ldsm4t(tvh, sVh + off);
                mma16816(acc_o[2*g],   pah[kc], tvh);
                mma16816(acc_o[2*g+1], pah[kc], tvh + 2);
            }
        }
    }

    const float i0 = 1.f / l0, i1 = 1.f / l1;
    float* ob = o + (size_t)b * SL * DM + hd * DHD;
#pragma unroll
    for (int n = 0; n < 8; n++) {
        const int c = n * 8 + (lane & 3) * 2;
        *(float2*)(ob + (size_t)gr0 * DM + c) = make_float2(acc_o[n][0] * i0, acc_o[n][1] * i0);
        *(float2*)(ob + (size_t)gr1 * DM + c) = make_float2(acc_o[n][2] * i1, acc_o[n][3] * i1);
    }
}

// ---------------- out = LayerNorm(a + r) * g + b  (+ split) ----------------
__global__ void resid_ln_kernel(const float* __restrict__ a, const float* __restrict__ r,
                                const float* __restrict__ g, const float* __restrict__ bb,
                                float* __restrict__ out)
{
    int row = blockIdx.x;
    int t = threadIdx.x;
    const float* pa = a + (size_t)row * DM;
    const float* pr = r + (size_t)row * DM;
    float v[4];
    float s = 0.f, s2 = 0.f;
#pragma unroll
    for (int i = 0; i < 4; i++) {
        float x = pa[t + i * 256] + pr[t + i * 256];
        v[i] = x; s += x; s2 += x * x;
    }
#pragma unroll
    for (int off = 16; off > 0; off >>= 1) {
        s  += __shfl_down_sync(0xffffffffu, s,  off);
        s2 += __shfl_down_sync(0xffffffffu, s2, off);
    }
    __shared__ float ws[8], ws2[8];
    __shared__ float sm_mean, sm_rstd;
    int w = t >> 5, lane = t & 31;
    if (lane == 0) { ws[w] = s; ws2[w] = s2; }
    __syncthreads();
    if (t == 0) {
        float S = 0.f, S2 = 0.f;
#pragma unroll
        for (int i = 0; i < 8; i++) { S += ws[i]; S2 += ws2[i]; }
        float mean = S * (1.f / DM);
        float var  = S2 * (1.f / DM) - mean * mean;
        sm_mean = mean;
        sm_rstd = rsqrtf(var + 1e-5f);
    }
    __syncthreads();
    float mean = sm_mean, rstd = sm_rstd;
#pragma unroll
    for (int i = 0; i < 4; i++) {
        int col = t + i * 256;
        float y = (v[i] - mean) * rstd * g[col] + bb[col];
        size_t idx = (size_t)row * DM + col;
        out[idx] = y;
        split_h(y, g_h_hi[idx], g_h_lo[idx]);
    }
}

__global__ void copy_out_kernel(float* __restrict__ out) {
    int i = blockIdx.x * 256 + threadIdx.x;
    out[i] = g_h[i];
}

// ---------------- launch ----------------
extern "C" void kernel_launch(void* const* d_in, const int* in_sizes, int n_in,
                              void* d_out, int out_size)
{
    const float* x    = (const float*)d_in[0];
    const float* pe   = (const float*)d_in[1];
    const float* wq   = (const float*)d_in[2];
    const float* wk   = (const float*)d_in[3];
    const float* wv   = (const float*)d_in[4];
    const float* ln1g = (const float*)d_in[5];
    const float* ln1b = (const float*)d_in[6];
    const float* w1   = (const float*)d_in[7];
    const float* b1   = (const float*)d_in[8];
    const float* w2   = (const float*)d_in[9];
    const float* b2   = (const float*)d_in[10];
    const float* ln2g = (const float*)d_in[11];
    const float* ln2b = (const float*)d_in[12];

    float *ph, *po;
    cudaGetSymbolAddress((void**)&ph, g_h);
    cudaGetSymbolAddress((void**)&po, g_o);
    __half *phh, *phl, *pfh, *pfl, *pqh, *pql;
    cudaGetSymbolAddress((void**)&phh, g_h_hi);
    cudaGetSymbolAddress((void**)&phl, g_h_lo);
    cudaGetSymbolAddress((void**)&pfh, g_ff_hi);
    cudaGetSymbolAddress((void**)&pfl, g_ff_lo);
    cudaGetSymbolAddress((void**)&pqh, g_qkv_hi);
    cudaGetSymbolAddress((void**)&pql, g_qkv_lo);
    __half *wqkvh, *wqkvl, *w1h, *w1l, *w2h, *w2l;
    cudaGetSymbolAddress((void**)&wqkvh, g_wqkv_hi); cudaGetSymbolAddress((void**)&wqkvl, g_wqkv_lo);
    cudaGetSymbolAddress((void**)&w1h, g_w1_hi);     cudaGetSymbolAddress((void**)&w1l, g_w1_lo);
    cudaGetSymbolAddress((void**)&w2h, g_w2_hi);     cudaGetSymbolAddress((void**)&w2l, g_w2_lo);

    cudaFuncSetAttribute(mm_kernel<1>, cudaFuncAttributeMaxDynamicSharedMemorySize, MM_SMEM);
    cudaFuncSetAttribute(mm_kernel<2>, cudaFuncAttributeMaxDynamicSharedMemorySize, MM_SMEM);
    cudaFuncSetAttribute(mm_kernel<3>, cudaFuncAttributeMaxDynamicSharedMemorySize, MM_SMEM);
    cudaFuncSetAttribute(flash_kernel, cudaFuncAttributeMaxDynamicSharedMemorySize, FA_SMEM);

    transpose_split_all_kernel<<<TR_GRID, 256>>>(wq, wk, wv, w1, w2);
    add_pe_kernel<<<NTOK * DM / 256, 256>>>(x, pe);

    for (int l = 0; l < NLAYER; l++) {
        const size_t woq = (size_t)l * QS * DM;
        const size_t wo1 = (size_t)l * DM * DFF;

        mm_kernel<3><<<dim3(QS / 128, NTOK / 128), 256, MM_SMEM>>>(
            phh, phl, wqkvh + woq, wqkvl + woq, nullptr,
            nullptr, pqh, pql, NTOK, QS, DM);

        flash_kernel<<<dim3(SL / 64, NB * NH), 128, FA_SMEM>>>(pqh, pql, po);

        resid_ln_kernel<<<NTOK, 256>>>(ph, po, ln1g + (size_t)l * DM, ln1b + (size_t)l * DM, ph);

        mm_kernel<1><<<dim3(DFF / 128, NTOK / 128), 256, MM_SMEM>>>(
            phh, phl, w1h + wo1, w1l + wo1, b1 + (size_t)l * DFF,
            nullptr, pfh, pfl, NTOK, DFF, DM);
        mm_kernel<2><<<dim3(DM / 128, NTOK / 128), 256, MM_SMEM>>>(
            pfh, pfl, w2h + wo1, w2l + wo1, b2 + (size_t)l * DM,
            po, nullptr, nullptr, NTOK, DM, DFF);

        resid_ln_kernel<<<NTOK, 256>>>(ph, po, ln2g + (size_t)l * DM, ln2b + (size_t)l * DM, ph);
    }

    copy_out_kernel<<<NTOK * DM / 256, 256>>>((float*)d_out);
}

// round 17
// speedup vs baseline: 3.4559x; 1.1074x over previous
#include <cuda_runtime.h>
#include <cuda_fp16.h>
#include <cstdint>
#include <math.h>

#define NB 2
#define SL 2048
#define DM 1024
#define NH 16
#define DHD 64
#define NLAYER 8
#define DFF 4096
#define NTOK (NB*SL)
#define QS (3*DM)          // fused qkv row stride

// ---------------- scratch (static device globals; no allocs) ----------------
__device__ __align__(256) float g_h  [(size_t)NTOK*DM];
__device__ __align__(256) float g_o  [(size_t)NTOK*DM];

// split-fp16 activations
__device__ __align__(256) __half g_h_hi[(size_t)NTOK*DM];
__device__ __align__(256) __half g_h_lo[(size_t)NTOK*DM];
__device__ __align__(256) __half g_ff_hi[(size_t)NTOK*DFF];
__device__ __align__(256) __half g_qkv_hi[(size_t)NTOK*QS];
__device__ __align__(256) __half g_qkv_lo[(size_t)NTOK*QS];

// transposed + split weights: [N, K] fp16 hi/lo per layer (qkv fused: [3072,1024])
__device__ __align__(256) __half g_wqkv_hi[(size_t)NLAYER*QS*DM], g_wqkv_lo[(size_t)NLAYER*QS*DM];
__device__ __align__(256) __half g_w1_hi[(size_t)NLAYER*DM*DFF],  g_w1_lo[(size_t)NLAYER*DM*DFF];
__device__ __align__(256) __half g_w2_hi[(size_t)NLAYER*DM*DFF],  g_w2_lo[(size_t)NLAYER*DM*DFF];

// ---------------- helpers ----------------
__device__ __forceinline__ uint32_t smem_u32(const void* p) {
    uint32_t a;
    asm("{ .reg .u64 t; cvta.to.shared.u64 t, %1; cvt.u32.u64 %0, t; }" : "=r"(a) : "l"(p));
    return a;
}
#define CP_ASYNC16(dst, src) asm volatile("cp.async.cg.shared.global [%0], [%1], 16;" :: "r"(dst), "l"(src))
#define CP_COMMIT()          asm volatile("cp.async.commit_group;" ::: "memory")
#define CP_WAIT(n)           asm volatile("cp.async.wait_group %0;" :: "n"(n) : "memory")

__device__ __forceinline__ void ldsm4(uint32_t* r, uint32_t a) {
    asm volatile("ldmatrix.sync.aligned.m8n8.x4.shared.b16 {%0,%1,%2,%3}, [%4];"
        : "=r"(r[0]), "=r"(r[1]), "=r"(r[2]), "=r"(r[3]) : "r"(a));
}
__device__ __forceinline__ void ldsm4t(uint32_t* r, uint32_t a) {
    asm volatile("ldmatrix.sync.aligned.m8n8.x4.trans.shared.b16 {%0,%1,%2,%3}, [%4];"
        : "=r"(r[0]), "=r"(r[1]), "=r"(r[2]), "=r"(r[3]) : "r"(a));
}
__device__ __forceinline__ void mma16816(float* c, const uint32_t* a, const uint32_t* b) {
    asm volatile("mma.sync.aligned.m16n8k16.row.col.f32.f16.f16.f32 "
        "{%0,%1,%2,%3}, {%4,%5,%6,%7}, {%8,%9}, {%0,%1,%2,%3};"
        : "+f"(c[0]), "+f"(c[1]), "+f"(c[2]), "+f"(c[3])
        : "r"(a[0]), "r"(a[1]), "r"(a[2]), "r"(a[3]), "r"(b[0]), "r"(b[1]));
}
// f16-accumulate variant (corrections): D,C are 2 regs of half2
__device__ __forceinline__ void mma16816h(uint32_t* c, const uint32_t* a, const uint32_t* b) {
    asm volatile("mma.sync.aligned.m16n8k16.row.col.f16.f16.f16.f16 "
        "{%0,%1}, {%2,%3,%4,%5}, {%6,%7}, {%0,%1};"
        : "+r"(c[0]), "+r"(c[1])
        : "r"(a[0]), "r"(a[1]), "r"(a[2]), "r"(a[3]), "r"(b[0]), "r"(b[1]));
}
__device__ __forceinline__ void split_h(float v, __half& hi, __half& lo) {
    hi = __float2half_rn(v);
    lo = __float2half_rn(v - __half2float(hi));
}
__device__ __forceinline__ float selu_f(float v) {
    return 1.0507009873554805f * (v > 0.f ? v : 1.6732632423543772f * expm1f(v));
}

// GEMM smem tile: 128 rows x 32 fp16 = 64B/row, 4 x 16B chunks; chunk ^= (row>>1)&3
__device__ __forceinline__ uint32_t tile_off(int row, int colElem) {
    return (uint32_t)(row * 64 + ((((colElem >> 3) & 3) ^ ((row >> 1) & 3)) << 4));
}
// flash smem tile: rows x 64 fp16 = 128B/row, 8 x 16B chunks; chunk ^= row&7
__device__ __forceinline__ uint32_t fa_off(int row, int colElem) {
    return (uint32_t)(row * 128 + ((((colElem >> 3) & 7) ^ (row & 7)) << 4));
}

// ---------------- h = x + pe (+ split) ----------------
__global__ void add_pe_kernel(const float* __restrict__ x, const float* __restrict__ pe) {
    int i = blockIdx.x * 256 + threadIdx.x;
    float v = x[i] + pe[i & (SL*DM - 1)];
    g_h[i] = v;
    split_h(v, g_h_hi[i], g_h_lo[i]);
}

// ---------------- fused weight transpose + split (ALL weights, one launch) ----------------
#define TR_GRID 90112
__global__ __launch_bounds__(256) void transpose_split_all_kernel(
    const float* __restrict__ wq, const float* __restrict__ wk, const float* __restrict__ wv,
    const float* __restrict__ w1, const float* __restrict__ w2)
{
    __shared__ float tile[32][33];
    const int bid = blockIdx.x;
    const int t = threadIdx.x;

    const float* src; __half* dh; __half* dl;
    int K, N, n0, k0;
    if (bid < 24576) {
        const int which = bid >> 13;
        const int r = bid & 8191;
        const int l = r >> 10;
        const int tl = r & 1023;
        K = DM; N = DM;
        n0 = (tl & 31) * 32; k0 = (tl >> 5) * 32;
        src = (which == 0 ? wq : which == 1 ? wk : wv) + (size_t)l * DM * DM;
        const size_t doff = (size_t)l * QS * DM + (size_t)which * DM * DM;
        dh = g_wqkv_hi + doff; dl = g_wqkv_lo + doff;
    } else if (bid < 57344) {
        const int r = bid - 24576;
        const int l = r >> 12;
        const int tl = r & 4095;
        K = DM; N = DFF;
        n0 = (tl & 127) * 32; k0 = (tl >> 7) * 32;
        src = w1 + (size_t)l * DM * DFF;
        dh = g_w1_hi + (size_t)l * DM * DFF; dl = g_w1_lo + (size_t)l * DM * DFF;
    } else {
        const int r = bid - 57344;
        const int l = r >> 12;
        const int tl = r & 4095;
        K = DFF; N = DM;
        n0 = (tl & 31) * 32; k0 = (tl >> 5) * 32;
        src = w2 + (size_t)l * DM * DFF;
        dh = g_w2_hi + (size_t)l * DM * DFF; dl = g_w2_lo + (size_t)l * DM * DFF;
    }

    const int lx = t & 31, ly = t >> 5;
#pragma unroll
    for (int i = 0; i < 4; i++) {
        const int kr = ly + i * 8;
        tile[kr][lx] = src[(size_t)(k0 + kr) * N + n0 + lx];
    }
    __syncthreads();

    const int kp = t & 15;
#pragma unroll
    for (int p = 0; p < 2; p++) {
        const int n = (t >> 4) + p * 16;
        const float v0 = tile[2 * kp][n], v1 = tile[2 * kp + 1][n];
        __half h0, l0h, h1, l1h;
        split_h(v0, h0, l0h); split_h(v1, h1, l1h);
        const size_t o = (size_t)(n0 + n) * K + k0 + 2 * kp;
        *(__half2*)(dh + o) = __halves2half2(h0, h1);
        *(__half2*)(dl + o) = __halves2half2(l0h, l1h);
    }
}

// ---------------- split-fp16 GEMM via mma.sync (HMMA) ----------------
// C[M,N] = act( A @ (Bh+Bl)^T + bias ),  A = Ah (+ Al if AL)
// Passes: Ah*Bh (fp32 acc) + Ah*Bl (f16 acc) [+ Al*Bh (f16 acc) if AL]
// EPI: 1 = bias+SELU -> fp16 hi only; 2 = bias -> fp32; 3 = qkv split fp16 (q scaled 0.125)
template<int EPI, bool AL>
__global__ __launch_bounds__(256, 1) void mm_kernel(
    const __half* __restrict__ Ah, const __half* __restrict__ Al,
    const __half* __restrict__ Bh, const __half* __restrict__ Bl,
    const float* __restrict__ bias,
    float* __restrict__ Cf, __half* __restrict__ Ch, __half* __restrict__ Cl,
    int M, int N, int K)
{
    constexpr uint32_t STG   = AL ? 32768 : 24576;      // Ah | (Al) | Bh | Bl, 8K each
    constexpr uint32_t O_AL  = 8192;
    constexpr uint32_t O_BH  = AL ? 16384 : 8192;
    constexpr uint32_t O_BL  = AL ? 24576 : 16384;

    extern __shared__ char smem[];
    const uint32_t sb = smem_u32(smem);
    const int t = threadIdx.x, lane = t & 31, wid = t >> 5;
    const int n0 = blockIdx.x * 128, m0 = blockIdx.y * 128;
    const int wm = (wid >> 1) * 32, wn = (wid & 1) * 64;

    const int row0 = t >> 2, ch0 = t & 3;
    const uint32_t so0 = tile_off(row0, ch0 * 8);

    float acc[2][8][4];
    uint32_t acc16[2][8][2];
#pragma unroll
    for (int mt = 0; mt < 2; mt++)
#pragma unroll
        for (int nt = 0; nt < 8; nt++) {
#pragma unroll
            for (int e = 0; e < 4; e++) acc[mt][nt][e] = 0.f;
            acc16[mt][nt][0] = 0u; acc16[mt][nt][1] = 0u;
        }

    const int nst = K >> 5;

    auto LOAD_STAGE = [&](int stage, int kt) {
        const uint32_t sa = sb + stage * STG;
        const size_t kof = (size_t)kt * 32 + ch0 * 8;
#pragma unroll
        for (int i = 0; i < 2; i++) {
            const int row = row0 + i * 64;
            const uint32_t so = sa + so0 + i * 4096;
            const size_t ga = (size_t)(m0 + row) * K + kof;
            const size_t gb = (size_t)(n0 + row) * K + kof;
            CP_ASYNC16(so,        Ah + ga);
            if (AL) CP_ASYNC16(so + O_AL, Al + ga);
            CP_ASYNC16(so + O_BH, Bh + gb);
            CP_ASYNC16(so + O_BL, Bl + gb);
        }
    };

    auto COMPUTE = [&](int stage) {
        const uint32_t sa = sb + stage * STG;
#pragma unroll
        for (int ks = 0; ks < 2; ks++) {
            const int k0 = ks * 16;
            uint32_t ahf[2][4], alf[2][4], bhf[8][2], blf[8][2];
#pragma unroll
            for (int mt = 0; mt < 2; mt++) {
                const int r = wm + mt * 16 + (lane & 7) + ((lane >> 3) & 1) * 8;
                const int c = k0 + (lane >> 4) * 8;
                const uint32_t off = tile_off(r, c);
                ldsm4(ahf[mt], sa + off);
                if (AL) ldsm4(alf[mt], sa + O_AL + off);
            }
#pragma unroll
            for (int g = 0; g < 4; g++) {
                const int r = wn + g * 16 + (lane & 7) + (lane >> 4) * 8;
                const int c = k0 + ((lane >> 3) & 1) * 8;
                const uint32_t off = tile_off(r, c);
                uint32_t tmp[4];
                ldsm4(tmp, sa + O_BH + off);
                bhf[g*2][0] = tmp[0]; bhf[g*2][1] = tmp[1];
                bhf[g*2+1][0] = tmp[2]; bhf[g*2+1][1] = tmp[3];
                ldsm4(tmp, sa + O_BL + off);
                blf[g*2][0] = tmp[0]; blf[g*2][1] = tmp[1];
                blf[g*2+1][0] = tmp[2]; blf[g*2+1][1] = tmp[3];
            }
#pragma unroll
            for (int mt = 0; mt < 2; mt++)
#pragma unroll
                for (int nt = 0; nt < 8; nt++) mma16816(acc[mt][nt], ahf[mt], bhf[nt]);
#pragma unroll
            for (int mt = 0; mt < 2; mt++)
#pragma unroll
                for (int nt = 0; nt < 8; nt++) mma16816h(acc16[mt][nt], ahf[mt], blf[nt]);
            if (AL) {
#pragma unroll
                for (int mt = 0; mt < 2; mt++)
#pragma unroll
                    for (int nt = 0; nt < 8; nt++) mma16816h(acc16[mt][nt], alf[mt], bhf[nt]);
            }
        }
    };

    LOAD_STAGE(0, 0); CP_COMMIT();
    LOAD_STAGE(1, 1); CP_COMMIT();
    LOAD_STAGE(2, 2); CP_COMMIT();

#pragma unroll 1
    for (int kt = 0; kt < nst; kt++) {
        if (kt + 3 < nst) { CP_WAIT(2); } else { CP_WAIT(0); }
        __syncthreads();
        if (kt + 3 < nst) { LOAD_STAGE((kt + 3) & 3, kt + 3); CP_COMMIT(); }
        COMPUTE(kt & 3);
    }

#pragma unroll
    for (int mt = 0; mt < 2; mt++) {
        const int r0 = m0 + wm + mt * 16 + (lane >> 2);
#pragma unroll
        for (int nt = 0; nt < 8; nt++) {
            const int col = n0 + wn + nt * 8 + (lane & 3) * 2;
            const float2 c01 = __half22float2(*(__half2*)&acc16[mt][nt][0]);
            const float2 c23 = __half22float2(*(__half2*)&acc16[mt][nt][1]);
            float v0 = acc[mt][nt][0] + c01.x, v1 = acc[mt][nt][1] + c01.y;
            float v2 = acc[mt][nt][2] + c23.x, v3 = acc[mt][nt][3] + c23.y;
            if (EPI == 2) {
                const float b0 = bias[col], b1 = bias[col + 1];
                *(float2*)(Cf + (size_t)r0 * N + col)       = make_float2(v0 + b0, v1 + b1);
                *(float2*)(Cf + (size_t)(r0 + 8) * N + col) = make_float2(v2 + b0, v3 + b1);
            } else if (EPI == 1) {
                // bias + SELU -> fp16 hi only (ff_lo dropped)
                const float b0 = bias[col], b1 = bias[col + 1];
                float s0 = selu_f(v0 + b0), s1 = selu_f(v1 + b1);
                float s2 = selu_f(v2 + b0), s3 = selu_f(v3 + b1);
                *(__half2*)(Ch + (size_t)r0 * N + col)       = __floats2half2_rn(s0, s1);
                *(__half2*)(Ch + (size_t)(r0 + 8) * N + col) = __floats2half2_rn(s2, s3);
            } else {   // EPI == 3: qkv, q region scaled by 1/8, split fp16
                const float sc = (col < DM) ? 0.125f : 1.0f;
                float s0 = v0 * sc, s1 = v1 * sc, s2 = v2 * sc, s3 = v3 * sc;
                __half h0, l0, h1, l1;
                split_h(s0, h0, l0); split_h(s1, h1, l1);
                *(__half2*)(Ch + (size_t)r0 * N + col) = __halves2half2(h0, h1);
                *(__half2*)(Cl + (size_t)r0 * N + col) = __halves2half2(l0, l1);
                split_h(s2, h0, l0); split_h(s3, h1, l1);
                *(__half2*)(Ch + (size_t)(r0 + 8) * N + col) = __halves2half2(h0, h1);
                *(__half2*)(Cl + (size_t)(r0 + 8) * N + col) = __halves2half2(l0, l1);
            }
        }
    }
}

#define MM_SMEM_AL   (4*32768)
#define MM_SMEM_NOAL (4*24576)

// ---------------- flash attention: split-fp16 HMMA, high-occupancy ----------------
// 64 q-rows per 128-thread CTA (4 warps x 16 rows); kv tiles 64 rows.
// S = 2 passes (QhKh + QlKh; K fp16-rounded), PV = 1 pass (Ph*Vh).
// smem 64KB: Qh 8K | Ql 8K | 3 stages x (Kh 8K | Vh 8K); 3 CTAs/SM.
#define FA_KV_STG 16384
#define FA_SMEM   (16384 + 3*FA_KV_STG)

__global__ __launch_bounds__(128, 3) void flash_kernel(
    const __half* __restrict__ qkvh, const __half* __restrict__ qkvl,
    float* __restrict__ o)
{
    extern __shared__ __half fsm[];
    const uint32_t bQh = smem_u32(fsm);
    const uint32_t bQl = bQh + 8192;
    const uint32_t bKV = bQh + 16384;

    const int qt = gridDim.x - 1 - blockIdx.x;   // heavy tiles first, 0..31
    const int bh = blockIdx.y;
    const int b  = bh >> 4, hd = bh & 15;
    const size_t qoff = (size_t)b * SL * QS + hd * DHD;

    const int t = threadIdx.x, lane = t & 31, w = t >> 5;

    int lrow[4]; uint32_t lso[4]; int lch[4];
#pragma unroll
    for (int i = 0; i < 4; i++) {
        int seg = t + i * 128;
        lrow[i] = seg >> 3;
        int ch = seg & 7;
        lso[i] = (uint32_t)(lrow[i] * 128 + ((ch ^ (lrow[i] & 7)) << 4));
        lch[i] = ch;
    }

    auto LOAD_KV = [&](int kt, int st) {
        const uint32_t s = bKV + st * FA_KV_STG;
#pragma unroll
        for (int i = 0; i < 4; i++) {
            const size_t gk = qoff + DM     + (size_t)(kt * 64 + lrow[i]) * QS + lch[i] * 8;
            const size_t gv = qoff + 2 * DM + (size_t)(kt * 64 + lrow[i]) * QS + lch[i] * 8;
            CP_ASYNC16(s        + lso[i], qkvh + gk);
            CP_ASYNC16(s + 8192 + lso[i], qkvh + gv);
        }
    };

#pragma unroll
    for (int i = 0; i < 4; i++) {
        const size_t g = qoff + (size_t)(qt * 64 + lrow[i]) * QS + lch[i] * 8;
        CP_ASYNC16(bQh + lso[i], qkvh + g);
        CP_ASYNC16(bQl + lso[i], qkvl + g);
    }
    CP_COMMIT();
    LOAD_KV(0, 0); CP_COMMIT();
    if (qt >= 1) LOAD_KV(1, 1);
    CP_COMMIT();

    CP_WAIT(2);
    __syncthreads();

    uint32_t qfh[4][4], qfl[4][4];
#pragma unroll
    for (int ks = 0; ks < 4; ks++) {
        const int r = w * 16 + (lane & 7) + ((lane >> 3) & 1) * 8;
        const int c = ks * 16 + (lane >> 4) * 8;
        const uint32_t off = fa_off(r, c);
        ldsm4(qfh[ks], bQh + off);
        ldsm4(qfl[ks], bQl + off);
    }

    float acc_o[8][4];
#pragma unroll
    for (int n = 0; n < 8; n++)
#pragma unroll
        for (int e = 0; e < 4; e++) acc_o[n][e] = 0.f;
    float m0 = -1e30f, m1 = -1e30f, l0 = 0.f, l1 = 0.f;

    const int gr0 = qt * 64 + w * 16 + (lane >> 2);
    const int gr1 = gr0 + 8;

#pragma unroll 1
    for (int kt = 0; kt <= qt; kt++) {
        const int cur = kt % 3;
        if (kt < qt) { CP_WAIT(1); } else { CP_WAIT(0); }
        __syncthreads();
        if (kt + 2 <= qt) { LOAD_KV(kt + 2, (kt + 2) % 3); CP_COMMIT(); }

        const uint32_t sKh = bKV + cur * FA_KV_STG;
        const uint32_t sVh = sKh + 8192;

        float s_[8][4];
#pragma unroll
        for (int n = 0; n < 8; n++)
#pragma unroll
            for (int e = 0; e < 4; e++) s_[n][e] = 0.f;

#pragma unroll
        for (int ks = 0; ks < 4; ks++) {
            const int k0 = ks * 16;
            uint32_t bhf[8][2];
#pragma unroll
            for (int g = 0; g < 4; g++) {
                const int r = g * 16 + (lane & 7) + (lane >> 4) * 8;
                const int c = k0 + ((lane >> 3) & 1) * 8;
                const uint32_t off = fa_off(r, c);
                uint32_t tmp[4];
                ldsm4(tmp, sKh + off);
                bhf[g*2][0] = tmp[0]; bhf[g*2][1] = tmp[1];
                bhf[g*2+1][0] = tmp[2]; bhf[g*2+1][1] = tmp[3];
            }
#pragma unroll
            for (int n = 0; n < 8; n++) mma16816(s_[n], qfh[ks], bhf[n]);
#pragma unroll
            for (int n = 0; n < 8; n++) mma16816(s_[n], qfl[ks], bhf[n]);
        }

        if (kt == qt) {
#pragma unroll
            for (int n = 0; n < 8; n++) {
                const int c = kt * 64 + n * 8 + (lane & 3) * 2;
                if (c     > gr0) s_[n][0] = -1e30f;
                if (c + 1 > gr0) s_[n][1] = -1e30f;
                if (c     > gr1) s_[n][2] = -1e30f;
                if (c + 1 > gr1) s_[n][3] = -1e30f;
            }
        }

        float mx0 = -1e30f, mx1 = -1e30f;
#pragma unroll
        for (int n = 0; n < 8; n++) {
            mx0 = fmaxf(mx0, fmaxf(s_[n][0], s_[n][1]));
            mx1 = fmaxf(mx1, fmaxf(s_[n][2], s_[n][3]));
        }
        mx0 = fmaxf(mx0, __shfl_xor_sync(0xffffffffu, mx0, 1));
        mx0 = fmaxf(mx0, __shfl_xor_sync(0xffffffffu, mx0, 2));
        mx1 = fmaxf(mx1, __shfl_xor_sync(0xffffffffu, mx1, 1));
        mx1 = fmaxf(mx1, __shfl_xor_sync(0xffffffffu, mx1, 2));
        const float mn0 = fmaxf(m0, mx0), mn1 = fmaxf(m1, mx1);
        const float sc0 = __expf(m0 - mn0), sc1 = __expf(m1 - mn1);
        m0 = mn0; m1 = mn1;

        uint32_t pah[4][4];
        float rs0 = 0.f, rs1 = 0.f;
#pragma unroll
        for (int n = 0; n < 8; n++) {
            float p0 = __expf(s_[n][0] - mn0);
            float p1 = __expf(s_[n][1] - mn0);
            float p2 = __expf(s_[n][2] - mn1);
            float p3 = __expf(s_[n][3] - mn1);
            rs0 += p0 + p1; rs1 += p2 + p3;
            __half2 h01 = __floats2half2_rn(p0, p1);
            __half2 h23 = __floats2half2_rn(p2, p3);
            const int kc = n >> 1, wh = (n & 1) * 2;
            pah[kc][wh    ] = *(uint32_t*)&h01;
            pah[kc][wh + 1] = *(uint32_t*)&h23;
        }
        rs0 += __shfl_xor_sync(0xffffffffu, rs0, 1);
        rs0 += __shfl_xor_sync(0xffffffffu, rs0, 2);
        rs1 += __shfl_xor_sync(0xffffffffu, rs1, 1);
        rs1 += __shfl_xor_sync(0xffffffffu, rs1, 2);
        l0 = l0 * sc0 + rs0;
        l1 = l1 * sc1 + rs1;

#pragma unroll
        for (int n = 0; n < 8; n++) {
            acc_o[n][0] *= sc0; acc_o[n][1] *= sc0;
            acc_o[n][2] *= sc1; acc_o[n][3] *= sc1;
        }

#pragma unroll
        for (int kc = 0; kc < 4; kc++) {
#pragma unroll
            for (int g = 0; g < 4; g++) {
                const int r = kc * 16 + (lane & 7) + ((lane >> 3) & 1) * 8;
                const int c = g * 16 + (lane >> 4) * 8;
                const uint32_t off = fa_off(r, c);
                uint32_t tvh[4];
                ldsm4t(tvh, sVh + off);
                mma16816(acc_o[2*g],   pah[kc], tvh);
                mma16816(acc_o[2*g+1], pah[kc], tvh + 2);
            }
        }
    }

    const float i0 = 1.f / l0, i1 = 1.f / l1;
    float* ob = o + (size_t)b * SL * DM + hd * DHD;
#pragma unroll
    for (int n = 0; n < 8; n++) {
        const int c = n * 8 + (lane & 3) * 2;
        *(float2*)(ob + (size_t)gr0 * DM + c) = make_float2(acc_o[n][0] * i0, acc_o[n][1] * i0);
        *(float2*)(ob + (size_t)gr1 * DM + c) = make_float2(acc_o[n][2] * i1, acc_o[n][3] * i1);
    }
}

// ---------------- out = LayerNorm(a + r) * g + b  (+ split) ----------------
__global__ void resid_ln_kernel(const float* __restrict__ a, const float* __restrict__ r,
                                const float* __restrict__ g, const float* __restrict__ bb,
                                float* __restrict__ out)
{
    int row = blockIdx.x;
    int t = threadIdx.x;
    const float* pa = a + (size_t)row * DM;
    const float* pr = r + (size_t)row * DM;
    float v[4];
    float s = 0.f, s2 = 0.f;
#pragma unroll
    for (int i = 0; i < 4; i++) {
        float x = pa[t + i * 256] + pr[t + i * 256];
        v[i] = x; s += x; s2 += x * x;
    }
#pragma unroll
    for (int off = 16; off > 0; off >>= 1) {
        s  += __shfl_down_sync(0xffffffffu, s,  off);
        s2 += __shfl_down_sync(0xffffffffu, s2, off);
    }
    __shared__ float ws[8], ws2[8];
    __shared__ float sm_mean, sm_rstd;
    int w = t >> 5, lane = t & 31;
    if (lane == 0) { ws[w] = s; ws2[w] = s2; }
    __syncthreads();
    if (t == 0) {
        float S = 0.f, S2 = 0.f;
#pragma unroll
        for (int i = 0; i < 8; i++) { S += ws[i]; S2 += ws2[i]; }
        float mean = S * (1.f / DM);
        float var  = S2 * (1.f / DM) - mean * mean;
        sm_mean = mean;
        sm_rstd = rsqrtf(var + 1e-5f);
    }
    __syncthreads();
    float mean = sm_mean, rstd = sm_rstd;
#pragma unroll
    for (int i = 0; i < 4; i++) {
        int col = t + i * 256;
        float y = (v[i] - mean) * rstd * g[col] + bb[col];
        size_t idx = (size_t)row * DM + col;
        out[idx] = y;
        split_h(y, g_h_hi[idx], g_h_lo[idx]);
    }
}

__global__ void copy_out_kernel(float* __restrict__ out) {
    int i = blockIdx.x * 256 + threadIdx.x;
    out[i] = g_h[i];
}

// ---------------- launch ----------------
extern "C" void kernel_launch(void* const* d_in, const int* in_sizes, int n_in,
                              void* d_out, int out_size)
{
    const float* x    = (const float*)d_in[0];
    const float* pe   = (const float*)d_in[1];
    const float* wq   = (const float*)d_in[2];
    const float* wk   = (const float*)d_in[3];
    const float* wv   = (const float*)d_in[4];
    const float* ln1g = (const float*)d_in[5];
    const float* ln1b = (const float*)d_in[6];
    const float* w1   = (const float*)d_in[7];
    const float* b1   = (const float*)d_in[8];
    const float* w2   = (const float*)d_in[9];
    const float* b2   = (const float*)d_in[10];
    const float* ln2g = (const float*)d_in[11];
    const float* ln2b = (const float*)d_in[12];

    float *ph, *po;
    cudaGetSymbolAddress((void**)&ph, g_h);
    cudaGetSymbolAddress((void**)&po, g_o);
    __half *phh, *phl, *pfh, *pqh, *pql;
    cudaGetSymbolAddress((void**)&phh, g_h_hi);
    cudaGetSymbolAddress((void**)&phl, g_h_lo);
    cudaGetSymbolAddress((void**)&pfh, g_ff_hi);
    cudaGetSymbolAddress((void**)&pqh, g_qkv_hi);
    cudaGetSymbolAddress((void**)&pql, g_qkv_lo);
    __half *wqkvh, *wqkvl, *w1h, *w1l, *w2h, *w2l;
    cudaGetSymbolAddress((void**)&wqkvh, g_wqkv_hi); cudaGetSymbolAddress((void**)&wqkvl, g_wqkv_lo);
    cudaGetSymbolAddress((void**)&w1h, g_w1_hi);     cudaGetSymbolAddress((void**)&w1l, g_w1_lo);
    cudaGetSymbolAddress((void**)&w2h, g_w2_hi);     cudaGetSymbolAddress((void**)&w2l, g_w2_lo);

    cudaFuncSetAttribute((void*)mm_kernel<1, true>,  cudaFuncAttributeMaxDynamicSharedMemorySize, MM_SMEM_AL);
    cudaFuncSetAttribute((void*)mm_kernel<2, false>, cudaFuncAttributeMaxDynamicSharedMemorySize, MM_SMEM_NOAL);
    cudaFuncSetAttribute((void*)mm_kernel<3, false>, cudaFuncAttributeMaxDynamicSharedMemorySize, MM_SMEM_NOAL);
    cudaFuncSetAttribute(flash_kernel, cudaFuncAttributeMaxDynamicSharedMemorySize, FA_SMEM);

    transpose_split_all_kernel<<<TR_GRID, 256>>>(wq, wk, wv, w1, w2);
    add_pe_kernel<<<NTOK * DM / 256, 256>>>(x, pe);

    for (int l = 0; l < NLAYER; l++) {
        const size_t woq = (size_t)l * QS * DM;
        const size_t wo1 = (size_t)l * DM * DFF;

        // QKV: activation-lo dropped (2 passes)
        mm_kernel<3, false><<<dim3(QS / 128, NTOK / 128), 256, MM_SMEM_NOAL>>>(
            phh, nullptr, wqkvh + woq, wqkvl + woq, nullptr,
            nullptr, pqh, pql, NTOK, QS, DM);

        flash_kernel<<<dim3(SL / 64, NB * NH), 128, FA_SMEM>>>(pqh, pql, po);

        resid_ln_kernel<<<NTOK, 256>>>(ph, po, ln1g + (size_t)l * DM, ln1b + (size_t)l * DM, ph);

        // MLP1: fully corrected (3 passes), output fp16 hi only
        mm_kernel<1, true><<<dim3(DFF / 128, NTOK / 128), 256, MM_SMEM_AL>>>(
            phh, phl, w1h + wo1, w1l + wo1, b1 + (size_t)l * DFF,
            nullptr, pfh, nullptr, NTOK, DFF, DM);
        // MLP2: activation-lo dropped (2 passes)
        mm_kernel<2, false><<<dim3(DM / 128, NTOK / 128), 256, MM_SMEM_NOAL>>>(
            pfh, nullptr, w2h + wo1, w2l + wo1, b2 + (size_t)l * DM,
            po, nullptr, nullptr, NTOK, DM, DFF);

        resid_ln_kernel<<<NTOK, 256>>>(ph, po, ln2g + (size_t)l * DM, ln2b + (size_t)l * DM, ph);
    }

    copy_out_kernel<<<NTOK * DM / 256, 256>>>((float*)d_out);
}